// round 11
// baseline (speedup 1.0000x reference)
#include <cuda_runtime.h>
#include <cuda_fp16.h>
#include <cstdint>

#define NB    2
#define SXX   1024
#define SYY   1024
#define DIM   1024
#define NH    16
#define HDIM  64
#define FULLN 1536

// ---------------- scratch (device globals) ----------------
__device__ int   g_lens[4];
__device__ float g_bias4k[4096];

__device__ unsigned short g_xh [2048 * 1024], g_xl [2048 * 1024];
__device__ unsigned short g_yh [2048 * 1024], g_yl [2048 * 1024];
// fused QKV|Q2: cols 0-1023 Q, 1024-2047 K, 2048-3071 V, 3072-4095 Q2
__device__ unsigned short g_qkvh[2048 * 4096], g_qkvl[2048 * 4096];
__device__ unsigned short g_kv2h[2048 * 2048];
__device__ unsigned short g_cath[2048 * 2048];
__device__ unsigned short g_wc_h [4096 * 1024];     // W_attn|W_2a [N,K]
__device__ unsigned short g_w2b_h[2048 * 1024];
__device__ unsigned short g_wpj_h[1024 * 2048], g_wpj_l[1024 * 2048];

// ---------------- helpers ----------------
__device__ __forceinline__ uint32_t smem_u32(const void* p) {
    uint32_t a;
    asm("{ .reg .u64 t; cvta.to.shared.u64 t, %1; cvt.u32.u64 %0, t; }" : "=r"(a) : "l"(p));
    return a;
}
#define CP_ASYNC16(dst, src) \
    asm volatile("cp.async.ca.shared.global [%0], [%1], 16;" :: "r"(dst), "l"(src) : "memory")
#define CP_COMMIT() asm volatile("cp.async.commit_group;" ::: "memory")
#define CP_WAIT1()  asm volatile("cp.async.wait_group 1;" ::: "memory")
#define CP_WAIT0()  asm volatile("cp.async.wait_group 0;" ::: "memory")

#define MMA_F16(c, a0, a1, a2, a3, b0, b1) \
    asm volatile("mma.sync.aligned.m16n8k16.row.col.f32.f16.f16.f32 " \
        "{%0,%1,%2,%3}, {%4,%5,%6,%7}, {%8,%9}, {%0,%1,%2,%3};" \
        : "+f"((c)[0]), "+f"((c)[1]), "+f"((c)[2]), "+f"((c)[3]) \
        : "r"(a0), "r"(a1), "r"(a2), "r"(a3), "r"(b0), "r"(b1))

#define LDSM4(r0, r1, r2, r3, a) \
    asm volatile("ldmatrix.sync.aligned.m8n8.x4.shared.b16 {%0,%1,%2,%3}, [%4];" \
        : "=r"(r0), "=r"(r1), "=r"(r2), "=r"(r3) : "r"(a))
#define LDSM4T(r0, r1, r2, r3, a) \
    asm volatile("ldmatrix.sync.aligned.m8n8.x4.trans.shared.b16 {%0,%1,%2,%3}, [%4];" \
        : "=r"(r0), "=r"(r1), "=r"(r2), "=r"(r3) : "r"(a))

__device__ __forceinline__ void split_pack_h(float a, float b, uint32_t& h, uint32_t& l) {
    __half ha = __float2half_rn(a), hb = __float2half_rn(b);
    __half la = __float2half_rn(a - __half2float(ha));
    __half lb = __float2half_rn(b - __half2float(hb));
    h = (uint32_t)*(unsigned short*)&ha | ((uint32_t)*(unsigned short*)&hb << 16);
    l = (uint32_t)*(unsigned short*)&la | ((uint32_t)*(unsigned short*)&lb << 16);
}
__device__ __forceinline__ uint32_t pack_h2(float a, float b) {
    __half2 v = __floats2half2_rn(a, b);
    return *(uint32_t*)&v;
}

// ---------------- lens + bias concat ----------------
__global__ void prep_small(const int* __restrict__ xb, int nx,
                           const int* __restrict__ yb, int ny,
                           const float* __restrict__ ba, const float* __restrict__ b2a,
                           float* __restrict__ bias4k)
{
    if (blockIdx.x == 16) {
        __shared__ int cnt[4];
        int t = threadIdx.x;
        if (t < 4) cnt[t] = 0;
        __syncthreads();
        for (int i = t; i < nx; i += blockDim.x) atomicAdd(&cnt[xb[i]], 1);
        for (int i = t; i < ny; i += blockDim.x) atomicAdd(&cnt[2 + yb[i]], 1);
        __syncthreads();
        if (t < 4) g_lens[t] = cnt[t];
    } else {
        int i = blockIdx.x * 256 + threadIdx.x;
        bias4k[i] = (i < 3072) ? ba[i] : b2a[i - 3072];
    }
}

// ---------------- fp32 -> fp16 hi/lo split (x and y) ----------------
__global__ __launch_bounds__(256)
void split_xy(const float* __restrict__ x, const float* __restrict__ y,
              unsigned short* __restrict__ xh, unsigned short* __restrict__ xl,
              unsigned short* __restrict__ yh, unsigned short* __restrict__ yl)
{
    const int N4 = 2048 * 1024 / 4;
    int i = blockIdx.x * 256 + threadIdx.x;
    const float* in; unsigned short *oh, *ol;
    int j;
    if (i < N4) { in = x; oh = xh; ol = xl; j = i; }
    else        { in = y; oh = yh; ol = yl; j = i - N4; }
    float4 v = ((const float4*)in)[j];
    uint32_t h0, l0, h1, l1;
    split_pack_h(v.x, v.y, h0, l0);
    split_pack_h(v.z, v.w, h1, l1);
    ((uint2*)oh)[j] = make_uint2(h0, h1);
    ((uint2*)ol)[j] = make_uint2(l0, l1);
}

// ---------------- all weight transposes ----------------
__global__ __launch_bounds__(256)
void transpose_all(const float* __restrict__ Wa, const float* __restrict__ W2a,
                   const float* __restrict__ W2b, const float* __restrict__ Wp,
                   unsigned short* __restrict__ wc, unsigned short* __restrict__ wb,
                   unsigned short* __restrict__ wph, unsigned short* __restrict__ wpl)
{
    int f = blockIdx.x;
    const float* in; unsigned short *oh, *ol = nullptr;
    int K, N, bx, by;
    if (f < 3072)      { in = Wa;  oh = wc;  K = 1024; N = 3072; f -= 0;    bx = f % 96; by = f / 96; }
    else if (f < 4096) { in = W2a; oh = wc + (size_t)3072 * 1024; K = 1024; N = 1024; f -= 3072; bx = f % 32; by = f / 32; }
    else if (f < 6144) { in = W2b; oh = wb;  K = 1024; N = 2048; f -= 4096; bx = f % 64; by = f / 64; }
    else               { in = Wp;  oh = wph; ol = wpl; K = 2048; N = 1024; f -= 6144; bx = f % 32; by = f / 32; }

    __shared__ float tile[32][33];
    int n0 = bx << 5, k0 = by << 5;
    int tx = threadIdx.x & 31, ty = threadIdx.x >> 5;
    for (int i = ty; i < 32; i += 8)
        tile[i][tx] = in[(size_t)(k0 + i) * N + n0 + tx];
    __syncthreads();
    for (int i = ty; i < 32; i += 8) {
        float v = tile[tx][i];
        __half h = __float2half_rn(v);
        size_t o = (size_t)(n0 + i) * K + k0 + tx;
        oh[o] = *(unsigned short*)&h;
        if (ol) {
            __half l = __float2half_rn(v - __half2float(h));
            ol[o] = *(unsigned short*)&l;
        }
    }
}

// ---------------- front GEMMs fused, K-chunk 64, per-block product count ----------------
// Score-side outputs (Q, K, Q2, K2): single product (Ah·Bh) — softmax washes the noise.
// Value-side outputs (V, V2): 2 products ((Ah+Al)·Bh).
#define TSF (128 * 72)
#define TSB (64 * 72)
__global__ __launch_bounds__(256)
void gemm_front(const unsigned short* __restrict__ xh, const unsigned short* __restrict__ xl,
                const unsigned short* __restrict__ yh, const unsigned short* __restrict__ yl,
                const unsigned short* __restrict__ wc, const unsigned short* __restrict__ wb,
                const float* __restrict__ bias4k, const float* __restrict__ b2b,
                unsigned short* __restrict__ qkvh, unsigned short* __restrict__ qkvl,
                unsigned short* __restrict__ kv2h)
{
    extern __shared__ unsigned short sm16[];
    unsigned short* sAh = sm16;             // [2][TSF]
    unsigned short* sAl = sm16 + 2 * TSF;
    unsigned short* sBh = sm16 + 4 * TSF;
    const uint32_t uAh = smem_u32(sAh), uAl = smem_u32(sAl), uBh = smem_u32(sBh);

    const int bid = blockIdx.x;
    const unsigned short *Ah, *Al, *Bh;
    const float* bias;
    unsigned short *Ch, *Cl;
    int bm, bn, N;
    bool need_lo, useAl;
    if (bid < 512) {
        bm = (bid >> 5) << 7; bn = (bid & 31) << 7; N = 4096;
        Ah = xh; Al = xl; Bh = wc; bias = bias4k; Ch = qkvh; Cl = qkvl;
        need_lo = (bn < 1024) || (bn >= 3072);    // Q, Q2 outputs hi/lo
        useAl   = (bn >= 2048) && (bn < 3072);    // only V needs the Al product
    } else {
        int i = bid - 512;
        bm = (i >> 4) << 7; bn = (i & 15) << 7; N = 2048;
        Ah = yh; Al = yl; Bh = wb; bias = b2b; Ch = kv2h; Cl = nullptr;
        need_lo = false;
        useAl   = (bn >= 1024);                   // only V2 needs the Al product
    }
    const int K = 1024;

    const int tid  = threadIdx.x;
    const int lane = tid & 31, wid = tid >> 5;
    const int wm = (wid >> 2) << 6;
    const int wn = (wid & 3) << 5;

    float acc[4][4][4];
#pragma unroll
    for (int i = 0; i < 4; i++)
#pragma unroll
        for (int j = 0; j < 4; j++)
#pragma unroll
            for (int k = 0; k < 4; k++) acc[i][j][k] = 0.f;

    const int nchunk = K >> 6;   // 16

#define PREFETCH_F(t) do { \
        uint32_t st_ = (uint32_t)((t) & 1) * (TSF * 2); \
        int k0_  = (t) << 6; \
        _Pragma("unroll") \
        for (int it_ = 0; it_ < 4; it_++) { \
            int i_ = tid + it_ * 256; \
            int row_ = i_ >> 3, sg_ = i_ & 7; \
            uint32_t so_ = st_ + (uint32_t)(row_ * 72 + sg_ * 8) * 2; \
            size_t ao_ = (size_t)(bm + row_) * K + k0_ + sg_ * 8; \
            size_t bo_ = (size_t)(bn + row_) * K + k0_ + sg_ * 8; \
            CP_ASYNC16(uAh + so_, Ah + ao_); \
            if (useAl) CP_ASYNC16(uAl + so_, Al + ao_); \
            CP_ASYNC16(uBh + so_, Bh + bo_); \
        } \
    } while (0)

    PREFETCH_F(0);
    CP_COMMIT();

    const int l8 = lane & 7, g = lane >> 3;
    uint32_t aoff[4], boff[2];
#pragma unroll
    for (int mi = 0; mi < 4; mi++)
        aoff[mi] = (uint32_t)((wm + (mi << 4) + ((g & 1) << 3) + l8) * 72 + ((g >> 1) << 3)) * 2;
#pragma unroll
    for (int p = 0; p < 2; p++)
        boff[p] = (uint32_t)((wn + (p << 4) + ((g >> 1) << 3) + l8) * 72 + ((g & 1) << 3)) * 2;

    const int fr = lane >> 2;
    const int fc = (lane & 3) << 1;

    for (int t = 0; t < nchunk; t++) {
        if (t + 1 < nchunk) { PREFETCH_F(t + 1); CP_COMMIT(); CP_WAIT1(); }
        else                { CP_WAIT0(); }
        __syncthreads();
        const uint32_t stg = (uint32_t)(t & 1) * (TSF * 2);
#pragma unroll
        for (int kt = 0; kt < 4; kt++) {
            const uint32_t kof = stg + (uint32_t)(kt << 5);
            uint32_t bh[2][4];
#pragma unroll
            for (int p = 0; p < 2; p++)
                LDSM4(bh[p][0], bh[p][1], bh[p][2], bh[p][3], uBh + kof + boff[p]);
#pragma unroll
            for (int mi = 0; mi < 4; mi++) {
                uint32_t ah0, ah1, ah2, ah3;
                LDSM4(ah0, ah1, ah2, ah3, uAh + kof + aoff[mi]);
#pragma unroll
                for (int p = 0; p < 2; p++) {
                    MMA_F16(acc[mi][2*p],   ah0, ah1, ah2, ah3, bh[p][0], bh[p][1]);
                    MMA_F16(acc[mi][2*p+1], ah0, ah1, ah2, ah3, bh[p][2], bh[p][3]);
                }
                if (useAl) {
                    uint32_t al0, al1, al2, al3;
                    LDSM4(al0, al1, al2, al3, uAl + kof + aoff[mi]);
#pragma unroll
                    for (int p = 0; p < 2; p++) {
                        MMA_F16(acc[mi][2*p],   al0, al1, al2, al3, bh[p][0], bh[p][1]);
                        MMA_F16(acc[mi][2*p+1], al0, al1, al2, al3, bh[p][2], bh[p][3]);
                    }
                }
            }
        }
        __syncthreads();
    }

    if (need_lo) {
#pragma unroll
        for (int mi = 0; mi < 4; mi++) {
            int row = bm + wm + (mi << 4) + fr;
#pragma unroll
            for (int ni = 0; ni < 4; ni++) {
                int col = bn + wn + (ni << 3) + fc;
                float bx = bias[col], by = bias[col + 1];
                uint32_t hh, ll;
                split_pack_h(acc[mi][ni][0] + bx, acc[mi][ni][1] + by, hh, ll);
                *(uint32_t*)&Ch[(size_t)row * N + col] = hh;
                *(uint32_t*)&Cl[(size_t)row * N + col] = ll;
                split_pack_h(acc[mi][ni][2] + bx, acc[mi][ni][3] + by, hh, ll);
                *(uint32_t*)&Ch[(size_t)(row + 8) * N + col] = hh;
                *(uint32_t*)&Cl[(size_t)(row + 8) * N + col] = ll;
            }
        }
    } else {
#pragma unroll
        for (int mi = 0; mi < 4; mi++) {
            int row = bm + wm + (mi << 4) + fr;
#pragma unroll
            for (int ni = 0; ni < 4; ni++) {
                int col = bn + wn + (ni << 3) + fc;
                float bx = bias[col], by = bias[col + 1];
                *(uint32_t*)&Ch[(size_t)row * N + col] =
                    pack_h2(acc[mi][ni][0] + bx, acc[mi][ni][1] + by);
                *(uint32_t*)&Ch[(size_t)(row + 8) * N + col] =
                    pack_h2(acc[mi][ni][2] + bx, acc[mi][ni][3] + by);
            }
        }
    }
}

// ---------------- proj GEMM: 128x64 tile, K-chunk 64, 3 CTAs/SM ----------------
__global__ __launch_bounds__(256, 3)
void gemm_proj(const unsigned short* __restrict__ Ah,
               const unsigned short* __restrict__ Bh, const unsigned short* __restrict__ Bl,
               const float* __restrict__ bias, float* __restrict__ Cf,
               int M, int N, int K)
{
    extern __shared__ unsigned short sm16[];
    unsigned short* sAh = sm16;                 // [2][TSF]
    unsigned short* sBh = sm16 + 2 * TSF;       // [2][TSB]
    unsigned short* sBl = sm16 + 2 * TSF + 2 * TSB;
    const uint32_t uAh = smem_u32(sAh), uBh = smem_u32(sBh), uBl = smem_u32(sBl);

    const int tid  = threadIdx.x;
    const int lane = tid & 31, wid = tid >> 5;
    const int wm = (wid >> 2) << 6;
    const int wn = (wid & 3) << 4;
    const int bm = blockIdx.y << 7, bn = blockIdx.x << 6;

    float acc[4][2][4];
#pragma unroll
    for (int i = 0; i < 4; i++)
#pragma unroll
        for (int j = 0; j < 2; j++)
#pragma unroll
            for (int k = 0; k < 4; k++) acc[i][j][k] = 0.f;

    const int nchunk = K >> 6;   // 32

#define PREFETCH_P(t) do { \
        int k0_ = (t) << 6; \
        uint32_t sa_ = (uint32_t)((t) & 1) * (TSF * 2); \
        uint32_t sb_ = (uint32_t)((t) & 1) * (TSB * 2); \
        _Pragma("unroll") \
        for (int it_ = 0; it_ < 4; it_++) { \
            int i_ = tid + it_ * 256; \
            int row_ = i_ >> 3, sg_ = i_ & 7; \
            uint32_t so_ = sa_ + (uint32_t)(row_ * 72 + sg_ * 8) * 2; \
            CP_ASYNC16(uAh + so_, Ah + (size_t)(bm + row_) * K + k0_ + sg_ * 8); \
        } \
        _Pragma("unroll") \
        for (int it_ = 0; it_ < 2; it_++) { \
            int i_ = tid + it_ * 256; \
            int row_ = i_ >> 3, sg_ = i_ & 7; \
            uint32_t so_ = sb_ + (uint32_t)(row_ * 72 + sg_ * 8) * 2; \
            size_t bo_ = (size_t)(bn + row_) * K + k0_ + sg_ * 8; \
            CP_ASYNC16(uBh + so_, Bh + bo_); \
            CP_ASYNC16(uBl + so_, Bl + bo_); \
        } \
    } while (0)

    PREFETCH_P(0);
    CP_COMMIT();

    const int l8 = lane & 7, g = lane >> 3;
    uint32_t aoff[4], boff;
#pragma unroll
    for (int mi = 0; mi < 4; mi++)
        aoff[mi] = (uint32_t)((wm + (mi << 4) + ((g & 1) << 3) + l8) * 72 + ((g >> 1) << 3)) * 2;
    boff = (uint32_t)((wn + ((g >> 1) << 3) + l8) * 72 + ((g & 1) << 3)) * 2;

    const int fr = lane >> 2;
    const int fc = (lane & 3) << 1;

    for (int t = 0; t < nchunk; t++) {
        if (t + 1 < nchunk) { PREFETCH_P(t + 1); CP_COMMIT(); CP_WAIT1(); }
        else                { CP_WAIT0(); }
        __syncthreads();
        const uint32_t sa = (uint32_t)(t & 1) * (TSF * 2);
        const uint32_t sb = (uint32_t)(t & 1) * (TSB * 2);
#pragma unroll
        for (int kt = 0; kt < 4; kt++) {
            const uint32_t ko = (uint32_t)(kt << 5);
            uint32_t bh0, bh1, bh2, bh3, bl0, bl1, bl2, bl3;
            LDSM4(bh0, bh1, bh2, bh3, uBh + sb + ko + boff);
            LDSM4(bl0, bl1, bl2, bl3, uBl + sb + ko + boff);
#pragma unroll
            for (int mi = 0; mi < 4; mi++) {
                uint32_t a0, a1, a2, a3;
                LDSM4(a0, a1, a2, a3, uAh + sa + ko + aoff[mi]);
                MMA_F16(acc[mi][0], a0, a1, a2, a3, bh0, bh1);
                MMA_F16(acc[mi][0], a0, a1, a2, a3, bl0, bl1);
                MMA_F16(acc[mi][1], a0, a1, a2, a3, bh2, bh3);
                MMA_F16(acc[mi][1], a0, a1, a2, a3, bl2, bl3);
            }
        }
        __syncthreads();
    }

#pragma unroll
    for (int mi = 0; mi < 4; mi++) {
        int row = bm + wm + (mi << 4) + fr;
#pragma unroll
        for (int ni = 0; ni < 2; ni++) {
            int col = bn + wn + (ni << 3) + fc;
            float bx = bias[col], by = bias[col + 1];
            float2 v0 = { acc[mi][ni][0] + bx, acc[mi][ni][1] + by };
            float2 v1 = { acc[mi][ni][2] + bx, acc[mi][ni][3] + by };
            *(float2*)(Cf + (size_t)row * N + col)       = v0;
            *(float2*)(Cf + (size_t)(row + 8) * N + col) = v1;
        }
    }
}

// ================= fused MMA flash attention (self + cross) =================
#define AST 72
#define QB  (64 * AST)
#define KVB (QB * 2)
#define QSTRIDE 4096

__global__ __launch_bounds__(128)
void attn_fused(const unsigned short* __restrict__ qkvh,
                const unsigned short* __restrict__ qkvl,
                const unsigned short* __restrict__ kvh,
                const float* __restrict__ mask,
                unsigned short* __restrict__ cath)
{
    extern __shared__ char smraw[];
    unsigned short* sQh = (unsigned short*)smraw;
    unsigned short* sQl = sQh + QB;
    unsigned short* sK  = sQl + QB;
    unsigned short* sV  = sK  + 2 * QB;
    float* sMsf = (float*)(sV + 2 * QB);
    const uint32_t uQh = smem_u32(sQh), uQl = smem_u32(sQl);
    const uint32_t uK = smem_u32(sK), uV = smem_u32(sV);
    const uint32_t uMs = smem_u32(sMsf);

    const int bx = blockIdx.x;
    const bool is_self = bx < 16;
    const int qt = is_self ? (15 - bx) : (31 - bx);
    const int h = blockIdx.y, b = blockIdx.z;
    const int tid = threadIdx.x, lane = tid & 31, wid = tid >> 5;
    const int q0 = wid << 4;
    const int r = lane >> 2, cq = (lane & 3) << 1;
    const int l8 = lane & 7, g = lane >> 3;

    const int lenx = g_lens[b], leny = g_lens[2 + b];

    uint32_t qfo = (uint32_t)((q0 + ((g & 1) << 3) + l8) * AST + ((g >> 1) << 3)) * 2;
    uint32_t kfo[4], vfo[4];
#pragma unroll
    for (int p = 0; p < 4; p++) {
        kfo[p] = (uint32_t)(((p << 4) + ((g >> 1) << 3) + l8) * AST + ((g & 1) << 3)) * 2;
        vfo[p] = (uint32_t)((((g & 1) << 3) + l8) * AST + (((p << 1) + (g >> 1)) << 3)) * 2;
    }

    float o[8][4];
#pragma unroll
    for (int i = 0; i < 8; i++)
#pragma unroll
        for (int j = 0; j < 4; j++) o[i][j] = 0.f;
    float mrow0 = -1e30f, mrow1 = -1e30f, lrow0 = 0.f, lrow1 = 0.f;

    if (is_self) {
        const size_t gb = (size_t)b * SXX * QSTRIDE;
        for (int i = tid; i < 512; i += 128) {
            int rr = i >> 3, seg = i & 7;
            size_t src = gb + (size_t)(qt * 64 + rr) * QSTRIDE + h * 64 + seg * 8;
            *(uint4*)&sQh[rr * AST + seg * 8] = *(const uint4*)&qkvh[src];
            *(uint4*)&sQl[rr * AST + seg * 8] = *(const uint4*)&qkvl[src];
        }

        const float* maskb = mask + b * SXX;
        int nt1 = qt + 1, nt2 = (lenx + 63) >> 6;
        const int ntile = nt1 < nt2 ? nt1 : nt2;

#define APREF_SELF(t) do { \
        uint32_t kd_ = uK + (uint32_t)((t) & 1) * KVB; \
        uint32_t vd_ = uV + (uint32_t)((t) & 1) * KVB; \
        _Pragma("unroll") \
        for (int it_ = 0; it_ < 4; it_++) { \
            int i_ = tid + it_ * 128; \
            int rr_ = i_ >> 3, sg_ = i_ & 7; \
            size_t kr_ = gb + (size_t)((t) * 64 + rr_) * QSTRIDE + 1024 + h * 64 + sg_ * 8; \
            uint32_t so_ = (uint32_t)(rr_ * AST + sg_ * 8) * 2; \
            CP_ASYNC16(kd_ + so_, qkvh + kr_); \
            CP_ASYNC16(vd_ + so_, qkvh + kr_ + 1024); \
        } \
        if (tid < 16) CP_ASYNC16(uMs + ((t) & 1) * 256 + tid * 16, maskb + (t) * 64 + tid * 4); \
    } while (0)

        APREF_SELF(0);
        CP_COMMIT();

        for (int t = 0; t < ntile; t++) {
            if (t + 1 < ntile) { APREF_SELF(t + 1); CP_COMMIT(); CP_WAIT1(); }
            else               { CP_WAIT0(); }
            __syncthreads();
            const uint32_t kb = (uint32_t)(t & 1) * KVB;
            const int mb = (t & 1) * 64;

            float sc[8][4];
#pragma unroll
            for (int i = 0; i < 8; i++)
#pragma unroll
                for (int j = 0; j < 4; j++) sc[i][j] = 0.f;

#pragma unroll
            for (int kt = 0; kt < 4; kt++) {
                const uint32_t ko = (uint32_t)(kt << 5);
                uint32_t ah0, ah1, ah2, ah3, al0, al1, al2, al3;
                LDSM4(ah0, ah1, ah2, ah3, uQh + qfo + ko);
                LDSM4(al0, al1, al2, al3, uQl + qfo + ko);
#pragma unroll
                for (int p = 0; p < 4; p++) {
                    uint32_t k0r, k1r, k2r, k3r;
                    LDSM4(k0r, k1r, k2r, k3r, uK + kb + kfo[p] + ko);
                    MMA_F16(sc[2*p],   ah0, ah1, ah2, ah3, k0r, k1r);
                    MMA_F16(sc[2*p],   al0, al1, al2, al3, k0r, k1r);
                    MMA_F16(sc[2*p+1], ah0, ah1, ah2, ah3, k2r, k3r);
                    MMA_F16(sc[2*p+1], al0, al1, al2, al3, k2r, k3r);
                }
            }

            const int grow = qt * 64 + q0 + r;
#pragma unroll
            for (int nt = 0; nt < 8; nt++) {
                int c0 = t * 64 + nt * 8 + cq;
                float m0 = sMsf[mb + nt * 8 + cq], m1 = sMsf[mb + nt * 8 + cq + 1];
                float v;
                v = sc[nt][0] * 0.125f; sc[nt][0] = ((c0     <= grow    ) ? v : -10000.f) + m0;
                v = sc[nt][1] * 0.125f; sc[nt][1] = ((c0 + 1 <= grow    ) ? v : -10000.f) + m1;
                v = sc[nt][2] * 0.125f; sc[nt][2] = ((c0     <= grow + 8) ? v : -10000.f) + m0;
                v = sc[nt][3] * 0.125f; sc[nt][3] = ((c0 + 1 <= grow + 8) ? v : -10000.f) + m1;
            }

            float mx0 = -1e30f, mx1 = -1e30f;
#pragma unroll
            for (int nt = 0; nt < 8; nt++) {
                mx0 = fmaxf(mx0, fmaxf(sc[nt][0], sc[nt][1]));
                mx1 = fmaxf(mx1, fmaxf(sc[nt][2], sc[nt][3]));
            }
            mx0 = fmaxf(mx0, __shfl_xor_sync(0xffffffffu, mx0, 1));
            mx0 = fmaxf(mx0, __shfl_xor_sync(0xffffffffu, mx0, 2));
            mx1 = fmaxf(mx1, __shfl_xor_sync(0xffffffffu, mx1, 1));
            mx1 = fmaxf(mx1, __shfl_xor_sync(0xffffffffu, mx1, 2));
            float mn0 = fmaxf(mrow0, mx0), mn1 = fmaxf(mrow1, mx1);
            float al0f = __expf(mrow0 - mn0), al1f = __expf(mrow1 - mn1);
            float s0 = 0.f, s1 = 0.f;
#pragma unroll
            for (int nt = 0; nt < 8; nt++) {
                sc[nt][0] = __expf(sc[nt][0] - mn0); s0 += sc[nt][0];
                sc[nt][1] = __expf(sc[nt][1] - mn0); s0 += sc[nt][1];
                sc[nt][2] = __expf(sc[nt][2] - mn1); s1 += sc[nt][2];
                sc[nt][3] = __expf(sc[nt][3] - mn1); s1 += sc[nt][3];
            }
            s0 += __shfl_xor_sync(0xffffffffu, s0, 1);
            s0 += __shfl_xor_sync(0xffffffffu, s0, 2);
            s1 += __shfl_xor_sync(0xffffffffu, s1, 1);
            s1 += __shfl_xor_sync(0xffffffffu, s1, 2);
            lrow0 = lrow0 * al0f + s0; mrow0 = mn0;
            lrow1 = lrow1 * al1f + s1; mrow1 = mn1;
#pragma unroll
            for (int nt = 0; nt < 8; nt++) {
                o[nt][0] *= al0f; o[nt][1] *= al0f;
                o[nt][2] *= al1f; o[nt][3] *= al1f;
            }

#pragma unroll
            for (int kc = 0; kc < 4; kc++) {
                uint32_t ph[4], pl[4];
                split_pack_h(sc[2*kc][0],   sc[2*kc][1],   ph[0], pl[0]);
                split_pack_h(sc[2*kc][2],   sc[2*kc][3],   ph[1], pl[1]);
                split_pack_h(sc[2*kc+1][0], sc[2*kc+1][1], ph[2], pl[2]);
                split_pack_h(sc[2*kc+1][2], sc[2*kc+1][3], ph[3], pl[3]);
                const uint32_t vrow = kb + (uint32_t)(kc * 16 * AST) * 2;
#pragma unroll
                for (int p = 0; p < 4; p++) {
                    uint32_t v0r, v1r, v2r, v3r;
                    LDSM4T(v0r, v1r, v2r, v3r, uV + vrow + vfo[p]);
                    MMA_F16(o[2*p],   ph[0], ph[1], ph[2], ph[3], v0r, v1r);
                    MMA_F16(o[2*p],   pl[0], pl[1], pl[2], pl[3], v0r, v1r);
                    MMA_F16(o[2*p+1], ph[0], ph[1], ph[2], ph[3], v2r, v3r);
                    MMA_F16(o[2*p+1], pl[0], pl[1], pl[2], pl[3], v2r, v3r);
                }
            }
            __syncthreads();
        }

        float i0 = 1.f / lrow0, i1 = 1.f / lrow1;
        size_t ob = (size_t)b * SXX * 2048 + (size_t)(qt * 64 + q0 + r) * 2048 + h * 64;
#pragma unroll
        for (int dn = 0; dn < 8; dn++) {
            *(uint32_t*)&cath[ob + dn * 8 + cq] = pack_h2(o[dn][0] * i0, o[dn][1] * i0);
            *(uint32_t*)&cath[ob + (size_t)8 * 2048 + dn * 8 + cq] = pack_h2(o[dn][2] * i1, o[dn][3] * i1);
        }
    } else {
        const int off = FULLN - lenx;
        size_t obase = (size_t)b * SXX * 2048 + (size_t)(qt * 64) * 2048 + 1024 + h * 64;
        if (qt * 64 >= lenx) {
            const uint4 z = {0, 0, 0, 0};
            for (int i = tid; i < 512; i += 128) {
                int rr = i >> 3, seg = i & 7;
                *(uint4*)&cath[obase + (size_t)rr * 2048 + seg * 8] = z;
            }
            return;
        }

        const size_t qgb = (size_t)b * SXX * QSTRIDE;
        for (int i = tid; i < 512; i += 128) {
            int rr = i >> 3, seg = i & 7;
            size_t src = qgb + (size_t)(qt * 64 + rr) * QSTRIDE + 3072 + h * 64 + seg * 8;
            *(uint4*)&sQh[rr * AST + seg * 8] = *(const uint4*)&qkvh[src];
            *(uint4*)&sQl[rr * AST + seg * 8] = *(const uint4*)&qkvl[src];
        }

        int qlast = qt * 64 + 63;
        if (qlast >= lenx) qlast = lenx - 1;
        int jmax = off + qlast + 1;
        if (jmax > leny) jmax = leny;
        const int ntile = (jmax + 63) >> 6;
        const size_t kgb = (size_t)b * SYY * 2048;

#define APREF_CROSS(t) do { \
        uint32_t kd_ = uK + (uint32_t)((t) & 1) * KVB; \
        uint32_t vd_ = uV + (uint32_t)((t) & 1) * KVB; \
        _Pragma("unroll") \
        for (int it_ = 0; it_ < 4; it_++) { \
            int i_ = tid + it_ * 128; \
            int rr_ = i_ >> 3, sg_ = i_ & 7; \
            size_t kr_ = kgb + (size_t)((t) * 64 + rr_) * 2048 + h * 64 + sg_ * 8; \
            uint32_t so_ = (uint32_t)(rr_ * AST + sg_ * 8) * 2; \
            CP_ASYNC16(kd_ + so_, kvh + kr_); \
            CP_ASYNC16(vd_ + so_, kvh + kr_ + 1024); \
        } \
    } while (0)

        APREF_CROSS(0);
        CP_COMMIT();

        for (int t = 0; t < ntile; t++) {
            if (t + 1 < ntile) { APREF_CROSS(t + 1); CP_COMMIT(); CP_WAIT1(); }
            else               { CP_WAIT0(); }
            __syncthreads();
            const uint32_t kb = (uint32_t)(t & 1) * KVB;

            float sc[8][4];
#pragma unroll
            for (int i = 0; i < 8; i++)
#pragma unroll
                for (int j = 0; j < 4; j++) sc[i][j] = 0.f;

#pragma unroll
            for (int kt = 0; kt < 4; kt++) {
                const uint32_t ko = (uint32_t)(kt << 5);
                uint32_t ah0, ah1, ah2, ah3, al0, al1, al2, al3;
                LDSM4(ah0, ah1, ah2, ah3, uQh + qfo + ko);
                LDSM4(al0, al1, al2, al3, uQl + qfo + ko);
#pragma unroll
                for (int p = 0; p < 4; p++) {
                    uint32_t k0r, k1r, k2r, k3r;
                    LDSM4(k0r, k1r, k2r, k3r, uK + kb + kfo[p] + ko);
                    MMA_F16(sc[2*p],   ah0, ah1, ah2, ah3, k0r, k1r);
                    MMA_F16(sc[2*p],   al0, al1, al2, al3, k0r, k1r);
                    MMA_F16(sc[2*p+1], ah0, ah1, ah2, ah3, k2r, k3r);
                    MMA_F16(sc[2*p+1], al0, al1, al2, al3, k2r, k3r);
                }
            }

            const int grow = off + qt * 64 + q0 + r;
#pragma unroll
            for (int nt = 0; nt < 8; nt++) {
                int c0 = t * 64 + nt * 8 + cq;
                sc[nt][0] = (c0     <= grow     && c0     < leny) ? sc[nt][0] * 0.125f : -1e30f;
                sc[nt][1] = (c0 + 1 <= grow     && c0 + 1 < leny) ? sc[nt][1] * 0.125f : -1e30f;
                sc[nt][2] = (c0     <= grow + 8 && c0     < leny) ? sc[nt][2] * 0.125f : -1e30f;
                sc[nt][3] = (c0 + 1 <= grow + 8 && c0 + 1 < leny) ? sc[nt][3] * 0.125f : -1e30f;
            }

            float mx0 = -1e30f, mx1 = -1e30f;
#pragma unroll
            for (int nt = 0; nt < 8; nt++) {
                mx0 = fmaxf(mx0, fmaxf(sc[nt][0], sc[nt][1]));
                mx1 = fmaxf(mx1, fmaxf(sc[nt][2], sc[nt][3]));
            }
            mx0 = fmaxf(mx0, __shfl_xor_sync(0xffffffffu, mx0, 1));
            mx0 = fmaxf(mx0, __shfl_xor_sync(0xffffffffu, mx0, 2));
            mx1 = fmaxf(mx1, __shfl_xor_sync(0xffffffffu, mx1, 1));
            mx1 = fmaxf(mx1, __shfl_xor_sync(0xffffffffu, mx1, 2));
            float mn0 = fmaxf(mrow0, mx0), mn1 = fmaxf(mrow1, mx1);
            float al0f = __expf(mrow0 - mn0), al1f = __expf(mrow1 - mn1);
            float s0 = 0.f, s1 = 0.f;
#pragma unroll
            for (int nt = 0; nt < 8; nt++) {
                sc[nt][0] = __expf(sc[nt][0] - mn0); s0 += sc[nt][0];
                sc[nt][1] = __expf(sc[nt][1] - mn0); s0 += sc[nt][1];
                sc[nt][2] = __expf(sc[nt][2] - mn1); s1 += sc[nt][2];
                sc[nt][3] = __expf(sc[nt][3] - mn1); s1 += sc[nt][3];
            }
            s0 += __shfl_xor_sync(0xffffffffu, s0, 1);
            s0 += __shfl_xor_sync(0xffffffffu, s0, 2);
            s1 += __shfl_xor_sync(0xffffffffu, s1, 1);
            s1 += __shfl_xor_sync(0xffffffffu, s1, 2);
            lrow0 = lrow0 * al0f + s0; mrow0 = mn0;
            lrow1 = lrow1 * al1f + s1; mrow1 = mn1;
#pragma unroll
            for (int nt = 0; nt < 8; nt++) {
                o[nt][0] *= al0f; o[nt][1] *= al0f;
                o[nt][2] *= al1f; o[nt][3] *= al1f;
            }

#pragma unroll
            for (int kc = 0; kc < 4; kc++) {
                uint32_t ph[4], pl[4];
                split_pack_h(sc[2*kc][0],   sc[2*kc][1],   ph[0], pl[0]);
                split_pack_h(sc[2*kc][2],   sc[2*kc][3],   ph[1], pl[1]);
                split_pack_h(sc[2*kc+1][0], sc[2*kc+1][1], ph[2], pl[2]);
                split_pack_h(sc[2*kc+1][2], sc[2*kc+1][3], ph[3], pl[3]);
                const uint32_t vrow = kb + (uint32_t)(kc * 16 * AST) * 2;
#pragma unroll
                for (int p = 0; p < 4; p++) {
                    uint32_t v0r, v1r, v2r, v3r;
                    LDSM4T(v0r, v1r, v2r, v3r, uV + vrow + vfo[p]);
                    MMA_F16(o[2*p],   ph[0], ph[1], ph[2], ph[3], v0r, v1r);
                    MMA_F16(o[2*p],   pl[0], pl[1], pl[2], pl[3], v0r, v1r);
                    MMA_F16(o[2*p+1], ph[0], ph[1], ph[2], ph[3], v2r, v3r);
                    MMA_F16(o[2*p+1], pl[0], pl[1], pl[2], pl[3], v2r, v3r);
                }
            }
            __syncthreads();
        }

        float i0 = 1.f / lrow0, i1 = 1.f / lrow1;
        int row0 = qt * 64 + q0 + r, row1 = row0 + 8;
        bool v0 = row0 < lenx, v1 = row1 < lenx;
        size_t ob = (size_t)b * SXX * 2048 + (size_t)row0 * 2048 + 1024 + h * 64;
#pragma unroll
        for (int dn = 0; dn < 8; dn++) {
            *(uint32_t*)&cath[ob + dn * 8 + cq] =
                v0 ? pack_h2(o[dn][0] * i0, o[dn][1] * i0) : 0u;
            *(uint32_t*)&cath[ob + (size_t)8 * 2048 + dn * 8 + cq] =
                v1 ? pack_h2(o[dn][2] * i1, o[dn][3] * i1) : 0u;
        }
    }
}

// ---------------- launch ----------------
extern "C" void kernel_launch(void* const* d_in, const int* in_sizes, int n_in,
                              void* d_out, int out_size)
{
    const float* x      = (const float*)d_in[0];
    const float* y      = (const float*)d_in[1];
    const float* maskx  = (const float*)d_in[2];
    const float* W_attn = (const float*)d_in[3];
    const float* b_attn = (const float*)d_in[4];
    const float* W_2a   = (const float*)d_in[5];
    const float* b_2a   = (const float*)d_in[6];
    const float* W_2b   = (const float*)d_in[7];
    const float* b_2b   = (const float*)d_in[8];
    const float* W_proj = (const float*)d_in[9];
    const float* b_proj = (const float*)d_in[10];
    const int*   xtb    = (const int*)d_in[11];
    const int*   ytb    = (const int*)d_in[15];

    unsigned short *xh, *xl, *yh, *yl;
    unsigned short *qkvh, *qkvl, *kv2h, *cath;
    unsigned short *wc, *wb, *wph, *wpl;
    float* bias4k;
    cudaGetSymbolAddress((void**)&xh, g_xh);     cudaGetSymbolAddress((void**)&xl, g_xl);
    cudaGetSymbolAddress((void**)&yh, g_yh);     cudaGetSymbolAddress((void**)&yl, g_yl);
    cudaGetSymbolAddress((void**)&qkvh, g_qkvh); cudaGetSymbolAddress((void**)&qkvl, g_qkvl);
    cudaGetSymbolAddress((void**)&kv2h, g_kv2h);
    cudaGetSymbolAddress((void**)&cath, g_cath);
    cudaGetSymbolAddress((void**)&wc, g_wc_h);
    cudaGetSymbolAddress((void**)&wb, g_w2b_h);
    cudaGetSymbolAddress((void**)&wph, g_wpj_h); cudaGetSymbolAddress((void**)&wpl, g_wpj_l);
    cudaGetSymbolAddress((void**)&bias4k, g_bias4k);

    const int SMEM_GF = 6 * TSF * 2;                    // 110592 B
    const int SMEM_GP = (2 * TSF + 4 * TSB) * 2;        // 73728 B
    const int SMEM_ATTN = 6 * QB * 2 + 2 * 64 * 4;      // 55808 B
    cudaFuncSetAttribute((const void*)gemm_front, cudaFuncAttributeMaxDynamicSharedMemorySize, SMEM_GF);
    cudaFuncSetAttribute((const void*)gemm_proj,  cudaFuncAttributeMaxDynamicSharedMemorySize, SMEM_GP);
    cudaFuncSetAttribute((const void*)attn_fused, cudaFuncAttributeMaxDynamicSharedMemorySize, SMEM_ATTN);

    prep_small<<<17, 256>>>(xtb, in_sizes[11], ytb, in_sizes[15], b_attn, b_2a, bias4k);
    split_xy<<<4096, 256>>>(x, y, xh, xl, yh, yl);
    transpose_all<<<8192, 256>>>(W_attn, W_2a, W_2b, W_proj, wc, wb, wph, wpl);

    gemm_front<<<768, 256, SMEM_GF>>>(xh, xl, yh, yl, wc, wb, bias4k, b_2b, qkvh, qkvl, kv2h);

    attn_fused<<<dim3(32, 16, 2), 128, SMEM_ATTN>>>(qkvh, qkvl, kv2h, maskx, cath);

    gemm_proj<<<dim3(16, 16), 256, SMEM_GP>>>(cath, wph, wpl, b_proj, (float*)d_out, 2048, 1024, 2048);
}

// round 12
// speedup vs baseline: 1.6211x; 1.6211x over previous
#include <cuda_runtime.h>
#include <cuda_fp16.h>
#include <cstdint>

#define NB    2
#define SXX   1024
#define SYY   1024
#define DIM   1024
#define NH    16
#define HDIM  64
#define FULLN 1536

// ---------------- scratch (device globals) ----------------
__device__ int   g_lens[4];
__device__ float g_bias4k[4096];

__device__ unsigned short g_xh [2048 * 1024], g_xl [2048 * 1024];
__device__ unsigned short g_yh [2048 * 1024], g_yl [2048 * 1024];
// fused QKV|Q2: cols 0-1023 Q, 1024-2047 K, 2048-3071 V, 3072-4095 Q2
__device__ unsigned short g_qkvh[2048 * 4096], g_qkvl[2048 * 4096];
__device__ unsigned short g_kv2h[2048 * 2048];
__device__ unsigned short g_cath[2048 * 2048];
__device__ unsigned short g_wc_h [4096 * 1024];     // W_attn|W_2a [N,K]
__device__ unsigned short g_w2b_h[2048 * 1024];
__device__ unsigned short g_wpj_h[1024 * 2048], g_wpj_l[1024 * 2048];

// ---------------- helpers ----------------
__device__ __forceinline__ uint32_t smem_u32(const void* p) {
    uint32_t a;
    asm("{ .reg .u64 t; cvta.to.shared.u64 t, %1; cvt.u32.u64 %0, t; }" : "=r"(a) : "l"(p));
    return a;
}
#define CP_ASYNC16(dst, src) \
    asm volatile("cp.async.ca.shared.global [%0], [%1], 16;" :: "r"(dst), "l"(src) : "memory")
#define CP_COMMIT() asm volatile("cp.async.commit_group;" ::: "memory")
#define CP_WAIT1()  asm volatile("cp.async.wait_group 1;" ::: "memory")
#define CP_WAIT0()  asm volatile("cp.async.wait_group 0;" ::: "memory")

#define MMA_F16(c, a0, a1, a2, a3, b0, b1) \
    asm volatile("mma.sync.aligned.m16n8k16.row.col.f32.f16.f16.f32 " \
        "{%0,%1,%2,%3}, {%4,%5,%6,%7}, {%8,%9}, {%0,%1,%2,%3};" \
        : "+f"((c)[0]), "+f"((c)[1]), "+f"((c)[2]), "+f"((c)[3]) \
        : "r"(a0), "r"(a1), "r"(a2), "r"(a3), "r"(b0), "r"(b1))

#define LDSM4(r0, r1, r2, r3, a) \
    asm volatile("ldmatrix.sync.aligned.m8n8.x4.shared.b16 {%0,%1,%2,%3}, [%4];" \
        : "=r"(r0), "=r"(r1), "=r"(r2), "=r"(r3) : "r"(a))
#define LDSM4T(r0, r1, r2, r3, a) \
    asm volatile("ldmatrix.sync.aligned.m8n8.x4.trans.shared.b16 {%0,%1,%2,%3}, [%4];" \
        : "=r"(r0), "=r"(r1), "=r"(r2), "=r"(r3) : "r"(a))

__device__ __forceinline__ void split_pack_h(float a, float b, uint32_t& h, uint32_t& l) {
    __half ha = __float2half_rn(a), hb = __float2half_rn(b);
    __half la = __float2half_rn(a - __half2float(ha));
    __half lb = __float2half_rn(b - __half2float(hb));
    h = (uint32_t)*(unsigned short*)&ha | ((uint32_t)*(unsigned short*)&hb << 16);
    l = (uint32_t)*(unsigned short*)&la | ((uint32_t)*(unsigned short*)&lb << 16);
}
__device__ __forceinline__ uint32_t pack_h2(float a, float b) {
    __half2 v = __floats2half2_rn(a, b);
    return *(uint32_t*)&v;
}

// ---------------- lens + bias concat ----------------
__global__ void prep_small(const int* __restrict__ xb, int nx,
                           const int* __restrict__ yb, int ny,
                           const float* __restrict__ ba, const float* __restrict__ b2a,
                           float* __restrict__ bias4k)
{
    if (blockIdx.x == 16) {
        __shared__ int cnt[4];
        int t = threadIdx.x;
        if (t < 4) cnt[t] = 0;
        __syncthreads();
        for (int i = t; i < nx; i += blockDim.x) atomicAdd(&cnt[xb[i]], 1);
        for (int i = t; i < ny; i += blockDim.x) atomicAdd(&cnt[2 + yb[i]], 1);
        __syncthreads();
        if (t < 4) g_lens[t] = cnt[t];
    } else {
        int i = blockIdx.x * 256 + threadIdx.x;
        bias4k[i] = (i < 3072) ? ba[i] : b2a[i - 3072];
    }
}

// ---------------- fp32 -> fp16 hi/lo split (x and y) ----------------
__global__ __launch_bounds__(256)
void split_xy(const float* __restrict__ x, const float* __restrict__ y,
              unsigned short* __restrict__ xh, unsigned short* __restrict__ xl,
              unsigned short* __restrict__ yh, unsigned short* __restrict__ yl)
{
    const int N4 = 2048 * 1024 / 4;
    int i = blockIdx.x * 256 + threadIdx.x;
    const float* in; unsigned short *oh, *ol;
    int j;
    if (i < N4) { in = x; oh = xh; ol = xl; j = i; }
    else        { in = y; oh = yh; ol = yl; j = i - N4; }
    float4 v = ((const float4*)in)[j];
    uint32_t h0, l0, h1, l1;
    split_pack_h(v.x, v.y, h0, l0);
    split_pack_h(v.z, v.w, h1, l1);
    ((uint2*)oh)[j] = make_uint2(h0, h1);
    ((uint2*)ol)[j] = make_uint2(l0, l1);
}

// ---------------- all weight transposes ----------------
__global__ __launch_bounds__(256)
void transpose_all(const float* __restrict__ Wa, const float* __restrict__ W2a,
                   const float* __restrict__ W2b, const float* __restrict__ Wp,
                   unsigned short* __restrict__ wc, unsigned short* __restrict__ wb,
                   unsigned short* __restrict__ wph, unsigned short* __restrict__ wpl)
{
    int f = blockIdx.x;
    const float* in; unsigned short *oh, *ol = nullptr;
    int K, N, bx, by;
    if (f < 3072)      { in = Wa;  oh = wc;  K = 1024; N = 3072; f -= 0;    bx = f % 96; by = f / 96; }
    else if (f < 4096) { in = W2a; oh = wc + (size_t)3072 * 1024; K = 1024; N = 1024; f -= 3072; bx = f % 32; by = f / 32; }
    else if (f < 6144) { in = W2b; oh = wb;  K = 1024; N = 2048; f -= 4096; bx = f % 64; by = f / 64; }
    else               { in = Wp;  oh = wph; ol = wpl; K = 2048; N = 1024; f -= 6144; bx = f % 32; by = f / 32; }

    __shared__ float tile[32][33];
    int n0 = bx << 5, k0 = by << 5;
    int tx = threadIdx.x & 31, ty = threadIdx.x >> 5;
    for (int i = ty; i < 32; i += 8)
        tile[i][tx] = in[(size_t)(k0 + i) * N + n0 + tx];
    __syncthreads();
    for (int i = ty; i < 32; i += 8) {
        float v = tile[tx][i];
        __half h = __float2half_rn(v);
        size_t o = (size_t)(n0 + i) * K + k0 + tx;
        oh[o] = *(unsigned short*)&h;
        if (ol) {
            __half l = __float2half_rn(v - __half2float(h));
            ol[o] = *(unsigned short*)&l;
        }
    }
}

// ---------------- front GEMM mainloop, compile-time product count ----------------
#define TSF (128 * 72)
#define TSB (64 * 72)

template<bool USEAL>
__device__ __forceinline__ void front_loop(
    const unsigned short* __restrict__ Ah, const unsigned short* __restrict__ Al,
    const unsigned short* __restrict__ Bh,
    int bm, int bn, int tid,
    uint32_t uAh, uint32_t uAl, uint32_t uBh,
    const uint32_t* aoff, const uint32_t* boff,
    float acc[4][4][4])
{
    const int K = 1024;
    const int nchunk = K >> 6;   // 16

#define PREFETCH_FL(t) do { \
        uint32_t st_ = (uint32_t)((t) & 1) * (TSF * 2); \
        int k0_  = (t) << 6; \
        _Pragma("unroll") \
        for (int it_ = 0; it_ < 4; it_++) { \
            int i_ = tid + it_ * 256; \
            int row_ = i_ >> 3, sg_ = i_ & 7; \
            uint32_t so_ = st_ + (uint32_t)(row_ * 72 + sg_ * 8) * 2; \
            size_t ao_ = (size_t)(bm + row_) * K + k0_ + sg_ * 8; \
            size_t bo_ = (size_t)(bn + row_) * K + k0_ + sg_ * 8; \
            CP_ASYNC16(uAh + so_, Ah + ao_); \
            if (USEAL) CP_ASYNC16(uAl + so_, Al + ao_); \
            CP_ASYNC16(uBh + so_, Bh + bo_); \
        } \
    } while (0)

    PREFETCH_FL(0);
    CP_COMMIT();

    for (int t = 0; t < nchunk; t++) {
        if (t + 1 < nchunk) { PREFETCH_FL(t + 1); CP_COMMIT(); CP_WAIT1(); }
        else                { CP_WAIT0(); }
        __syncthreads();
        const uint32_t stg = (uint32_t)(t & 1) * (TSF * 2);
#pragma unroll
        for (int kt = 0; kt < 4; kt++) {
            const uint32_t kof = stg + (uint32_t)(kt << 5);
            uint32_t bh[2][4];
#pragma unroll
            for (int p = 0; p < 2; p++)
                LDSM4(bh[p][0], bh[p][1], bh[p][2], bh[p][3], uBh + kof + boff[p]);
#pragma unroll
            for (int mi = 0; mi < 4; mi++) {
                uint32_t a0, a1, a2, a3;
                LDSM4(a0, a1, a2, a3, uAh + kof + aoff[mi]);
#pragma unroll
                for (int p = 0; p < 2; p++) {
                    MMA_F16(acc[mi][2*p],   a0, a1, a2, a3, bh[p][0], bh[p][1]);
                    MMA_F16(acc[mi][2*p+1], a0, a1, a2, a3, bh[p][2], bh[p][3]);
                }
                if (USEAL) {
                    uint32_t l0, l1, l2, l3;
                    LDSM4(l0, l1, l2, l3, uAl + kof + aoff[mi]);
#pragma unroll
                    for (int p = 0; p < 2; p++) {
                        MMA_F16(acc[mi][2*p],   l0, l1, l2, l3, bh[p][0], bh[p][1]);
                        MMA_F16(acc[mi][2*p+1], l0, l1, l2, l3, bh[p][2], bh[p][3]);
                    }
                }
            }
        }
        __syncthreads();
    }
#undef PREFETCH_FL
}

__global__ __launch_bounds__(256)
void gemm_front(const unsigned short* __restrict__ xh, const unsigned short* __restrict__ xl,
                const unsigned short* __restrict__ yh, const unsigned short* __restrict__ yl,
                const unsigned short* __restrict__ wc, const unsigned short* __restrict__ wb,
                const float* __restrict__ bias4k, const float* __restrict__ b2b,
                unsigned short* __restrict__ qkvh, unsigned short* __restrict__ qkvl,
                unsigned short* __restrict__ kv2h)
{
    extern __shared__ unsigned short sm16[];
    unsigned short* sAh = sm16;             // [2][TSF]
    unsigned short* sAl = sm16 + 2 * TSF;
    unsigned short* sBh = sm16 + 4 * TSF;
    const uint32_t uAh = smem_u32(sAh), uAl = smem_u32(sAl), uBh = smem_u32(sBh);

    const int bid = blockIdx.x;
    const unsigned short *Ah, *Al, *Bh;
    const float* bias;
    unsigned short *Ch, *Cl;
    int bm, bn, N;
    bool need_lo, useAl;
    if (bid < 512) {
        bm = (bid >> 5) << 7; bn = (bid & 31) << 7; N = 4096;
        Ah = xh; Al = xl; Bh = wc; bias = bias4k; Ch = qkvh; Cl = qkvl;
        need_lo = (bn < 1024) || (bn >= 3072);    // Q, Q2 outputs hi/lo
        useAl   = (bn >= 2048) && (bn < 3072);    // only V needs the Al product
    } else {
        int i = bid - 512;
        bm = (i >> 4) << 7; bn = (i & 15) << 7; N = 2048;
        Ah = yh; Al = yl; Bh = wb; bias = b2b; Ch = kv2h; Cl = nullptr;
        need_lo = false;
        useAl   = (bn >= 1024);                   // only V2 needs the Al product
    }

    const int tid  = threadIdx.x;
    const int lane = tid & 31, wid = tid >> 5;
    const int wm = (wid >> 2) << 6;
    const int wn = (wid & 3) << 5;

    float acc[4][4][4];
#pragma unroll
    for (int i = 0; i < 4; i++)
#pragma unroll
        for (int j = 0; j < 4; j++)
#pragma unroll
            for (int k = 0; k < 4; k++) acc[i][j][k] = 0.f;

    const int l8 = lane & 7, g = lane >> 3;
    uint32_t aoff[4], boff[2];
#pragma unroll
    for (int mi = 0; mi < 4; mi++)
        aoff[mi] = (uint32_t)((wm + (mi << 4) + ((g & 1) << 3) + l8) * 72 + ((g >> 1) << 3)) * 2;
#pragma unroll
    for (int p = 0; p < 2; p++)
        boff[p] = (uint32_t)((wn + (p << 4) + ((g >> 1) << 3) + l8) * 72 + ((g & 1) << 3)) * 2;

    // CTA-uniform branch -> two clean compile-time specializations
    if (useAl) front_loop<true >(Ah, Al, Bh, bm, bn, tid, uAh, uAl, uBh, aoff, boff, acc);
    else       front_loop<false>(Ah, Al, Bh, bm, bn, tid, uAh, uAl, uBh, aoff, boff, acc);

    const int fr = lane >> 2;
    const int fc = (lane & 3) << 1;

    if (need_lo) {
#pragma unroll
        for (int mi = 0; mi < 4; mi++) {
            int row = bm + wm + (mi << 4) + fr;
#pragma unroll
            for (int ni = 0; ni < 4; ni++) {
                int col = bn + wn + (ni << 3) + fc;
                float bx = bias[col], by = bias[col + 1];
                uint32_t hh, ll;
                split_pack_h(acc[mi][ni][0] + bx, acc[mi][ni][1] + by, hh, ll);
                *(uint32_t*)&Ch[(size_t)row * N + col] = hh;
                *(uint32_t*)&Cl[(size_t)row * N + col] = ll;
                split_pack_h(acc[mi][ni][2] + bx, acc[mi][ni][3] + by, hh, ll);
                *(uint32_t*)&Ch[(size_t)(row + 8) * N + col] = hh;
                *(uint32_t*)&Cl[(size_t)(row + 8) * N + col] = ll;
            }
        }
    } else {
#pragma unroll
        for (int mi = 0; mi < 4; mi++) {
            int row = bm + wm + (mi << 4) + fr;
#pragma unroll
            for (int ni = 0; ni < 4; ni++) {
                int col = bn + wn + (ni << 3) + fc;
                float bx = bias[col], by = bias[col + 1];
                *(uint32_t*)&Ch[(size_t)row * N + col] =
                    pack_h2(acc[mi][ni][0] + bx, acc[mi][ni][1] + by);
                *(uint32_t*)&Ch[(size_t)(row + 8) * N + col] =
                    pack_h2(acc[mi][ni][2] + bx, acc[mi][ni][3] + by);
            }
        }
    }
}

// ---------------- proj GEMM: 128x64 tile, K-chunk 64, 3 CTAs/SM ----------------
__global__ __launch_bounds__(256, 3)
void gemm_proj(const unsigned short* __restrict__ Ah,
               const unsigned short* __restrict__ Bh, const unsigned short* __restrict__ Bl,
               const float* __restrict__ bias, float* __restrict__ Cf,
               int M, int N, int K)
{
    extern __shared__ unsigned short sm16[];
    unsigned short* sAh = sm16;                 // [2][TSF]
    unsigned short* sBh = sm16 + 2 * TSF;       // [2][TSB]
    unsigned short* sBl = sm16 + 2 * TSF + 2 * TSB;
    const uint32_t uAh = smem_u32(sAh), uBh = smem_u32(sBh), uBl = smem_u32(sBl);

    const int tid  = threadIdx.x;
    const int lane = tid & 31, wid = tid >> 5;
    const int wm = (wid >> 2) << 6;
    const int wn = (wid & 3) << 4;
    const int bm = blockIdx.y << 7, bn = blockIdx.x << 6;

    float acc[4][2][4];
#pragma unroll
    for (int i = 0; i < 4; i++)
#pragma unroll
        for (int j = 0; j < 2; j++)
#pragma unroll
            for (int k = 0; k < 4; k++) acc[i][j][k] = 0.f;

    const int nchunk = K >> 6;   // 32

#define PREFETCH_P(t) do { \
        int k0_ = (t) << 6; \
        uint32_t sa_ = (uint32_t)((t) & 1) * (TSF * 2); \
        uint32_t sb_ = (uint32_t)((t) & 1) * (TSB * 2); \
        _Pragma("unroll") \
        for (int it_ = 0; it_ < 4; it_++) { \
            int i_ = tid + it_ * 256; \
            int row_ = i_ >> 3, sg_ = i_ & 7; \
            uint32_t so_ = sa_ + (uint32_t)(row_ * 72 + sg_ * 8) * 2; \
            CP_ASYNC16(uAh + so_, Ah + (size_t)(bm + row_) * K + k0_ + sg_ * 8); \
        } \
        _Pragma("unroll") \
        for (int it_ = 0; it_ < 2; it_++) { \
            int i_ = tid + it_ * 256; \
            int row_ = i_ >> 3, sg_ = i_ & 7; \
            uint32_t so_ = sb_ + (uint32_t)(row_ * 72 + sg_ * 8) * 2; \
            size_t bo_ = (size_t)(bn + row_) * K + k0_ + sg_ * 8; \
            CP_ASYNC16(uBh + so_, Bh + bo_); \
            CP_ASYNC16(uBl + so_, Bl + bo_); \
        } \
    } while (0)

    PREFETCH_P(0);
    CP_COMMIT();

    const int l8 = lane & 7, g = lane >> 3;
    uint32_t aoff[4], boff;
#pragma unroll
    for (int mi = 0; mi < 4; mi++)
        aoff[mi] = (uint32_t)((wm + (mi << 4) + ((g & 1) << 3) + l8) * 72 + ((g >> 1) << 3)) * 2;
    boff = (uint32_t)((wn + ((g >> 1) << 3) + l8) * 72 + ((g & 1) << 3)) * 2;

    const int fr = lane >> 2;
    const int fc = (lane & 3) << 1;

    for (int t = 0; t < nchunk; t++) {
        if (t + 1 < nchunk) { PREFETCH_P(t + 1); CP_COMMIT(); CP_WAIT1(); }
        else                { CP_WAIT0(); }
        __syncthreads();
        const uint32_t sa = (uint32_t)(t & 1) * (TSF * 2);
        const uint32_t sb = (uint32_t)(t & 1) * (TSB * 2);
#pragma unroll
        for (int kt = 0; kt < 4; kt++) {
            const uint32_t ko = (uint32_t)(kt << 5);
            uint32_t bh0, bh1, bh2, bh3, bl0, bl1, bl2, bl3;
            LDSM4(bh0, bh1, bh2, bh3, uBh + sb + ko + boff);
            LDSM4(bl0, bl1, bl2, bl3, uBl + sb + ko + boff);
#pragma unroll
            for (int mi = 0; mi < 4; mi++) {
                uint32_t a0, a1, a2, a3;
                LDSM4(a0, a1, a2, a3, uAh + sa + ko + aoff[mi]);
                MMA_F16(acc[mi][0], a0, a1, a2, a3, bh0, bh1);
                MMA_F16(acc[mi][0], a0, a1, a2, a3, bl0, bl1);
                MMA_F16(acc[mi][1], a0, a1, a2, a3, bh2, bh3);
                MMA_F16(acc[mi][1], a0, a1, a2, a3, bl2, bl3);
            }
        }
        __syncthreads();
    }

#pragma unroll
    for (int mi = 0; mi < 4; mi++) {
        int row = bm + wm + (mi << 4) + fr;
#pragma unroll
        for (int ni = 0; ni < 2; ni++) {
            int col = bn + wn + (ni << 3) + fc;
            float bx = bias[col], by = bias[col + 1];
            float2 v0 = { acc[mi][ni][0] + bx, acc[mi][ni][1] + by };
            float2 v1 = { acc[mi][ni][2] + bx, acc[mi][ni][3] + by };
            *(float2*)(Cf + (size_t)row * N + col)       = v0;
            *(float2*)(Cf + (size_t)(row + 8) * N + col) = v1;
        }
    }
}

// ================= fused MMA flash attention (self + cross) =================
#define AST 72
#define QB  (64 * AST)
#define KVB (QB * 2)
#define QSTRIDE 4096

__global__ __launch_bounds__(128)
void attn_fused(const unsigned short* __restrict__ qkvh,
                const unsigned short* __restrict__ qkvl,
                const unsigned short* __restrict__ kvh,
                const float* __restrict__ mask,
                unsigned short* __restrict__ cath)
{
    extern __shared__ char smraw[];
    unsigned short* sQh = (unsigned short*)smraw;
    unsigned short* sQl = sQh + QB;
    unsigned short* sK  = sQl + QB;
    unsigned short* sV  = sK  + 2 * QB;
    float* sMsf = (float*)(sV + 2 * QB);
    const uint32_t uQh = smem_u32(sQh), uQl = smem_u32(sQl);
    const uint32_t uK = smem_u32(sK), uV = smem_u32(sV);
    const uint32_t uMs = smem_u32(sMsf);

    const int bx = blockIdx.x;
    const bool is_self = bx < 16;
    const int qt = is_self ? (15 - bx) : (31 - bx);
    const int h = blockIdx.y, b = blockIdx.z;
    const int tid = threadIdx.x, lane = tid & 31, wid = tid >> 5;
    const int q0 = wid << 4;
    const int r = lane >> 2, cq = (lane & 3) << 1;
    const int l8 = lane & 7, g = lane >> 3;

    const int lenx = g_lens[b], leny = g_lens[2 + b];

    uint32_t qfo = (uint32_t)((q0 + ((g & 1) << 3) + l8) * AST + ((g >> 1) << 3)) * 2;
    uint32_t kfo[4], vfo[4];
#pragma unroll
    for (int p = 0; p < 4; p++) {
        kfo[p] = (uint32_t)(((p << 4) + ((g >> 1) << 3) + l8) * AST + ((g & 1) << 3)) * 2;
        vfo[p] = (uint32_t)((((g & 1) << 3) + l8) * AST + (((p << 1) + (g >> 1)) << 3)) * 2;
    }

    float o[8][4];
#pragma unroll
    for (int i = 0; i < 8; i++)
#pragma unroll
        for (int j = 0; j < 4; j++) o[i][j] = 0.f;
    float mrow0 = -1e30f, mrow1 = -1e30f, lrow0 = 0.f, lrow1 = 0.f;

    if (is_self) {
        const size_t gb = (size_t)b * SXX * QSTRIDE;
        for (int i = tid; i < 512; i += 128) {
            int rr = i >> 3, seg = i & 7;
            size_t src = gb + (size_t)(qt * 64 + rr) * QSTRIDE + h * 64 + seg * 8;
            *(uint4*)&sQh[rr * AST + seg * 8] = *(const uint4*)&qkvh[src];
            *(uint4*)&sQl[rr * AST + seg * 8] = *(const uint4*)&qkvl[src];
        }

        const float* maskb = mask + b * SXX;
        int nt1 = qt + 1, nt2 = (lenx + 63) >> 6;
        const int ntile = nt1 < nt2 ? nt1 : nt2;

#define APREF_SELF(t) do { \
        uint32_t kd_ = uK + (uint32_t)((t) & 1) * KVB; \
        uint32_t vd_ = uV + (uint32_t)((t) & 1) * KVB; \
        _Pragma("unroll") \
        for (int it_ = 0; it_ < 4; it_++) { \
            int i_ = tid + it_ * 128; \
            int rr_ = i_ >> 3, sg_ = i_ & 7; \
            size_t kr_ = gb + (size_t)((t) * 64 + rr_) * QSTRIDE + 1024 + h * 64 + sg_ * 8; \
            uint32_t so_ = (uint32_t)(rr_ * AST + sg_ * 8) * 2; \
            CP_ASYNC16(kd_ + so_, qkvh + kr_); \
            CP_ASYNC16(vd_ + so_, qkvh + kr_ + 1024); \
        } \
        if (tid < 16) CP_ASYNC16(uMs + ((t) & 1) * 256 + tid * 16, maskb + (t) * 64 + tid * 4); \
    } while (0)

        APREF_SELF(0);
        CP_COMMIT();

        for (int t = 0; t < ntile; t++) {
            if (t + 1 < ntile) { APREF_SELF(t + 1); CP_COMMIT(); CP_WAIT1(); }
            else               { CP_WAIT0(); }
            __syncthreads();
            const uint32_t kb = (uint32_t)(t & 1) * KVB;
            const int mb = (t & 1) * 64;

            float sc[8][4];
#pragma unroll
            for (int i = 0; i < 8; i++)
#pragma unroll
                for (int j = 0; j < 4; j++) sc[i][j] = 0.f;

#pragma unroll
            for (int kt = 0; kt < 4; kt++) {
                const uint32_t ko = (uint32_t)(kt << 5);
                uint32_t ah0, ah1, ah2, ah3, al0, al1, al2, al3;
                LDSM4(ah0, ah1, ah2, ah3, uQh + qfo + ko);
                LDSM4(al0, al1, al2, al3, uQl + qfo + ko);
#pragma unroll
                for (int p = 0; p < 4; p++) {
                    uint32_t k0r, k1r, k2r, k3r;
                    LDSM4(k0r, k1r, k2r, k3r, uK + kb + kfo[p] + ko);
                    MMA_F16(sc[2*p],   ah0, ah1, ah2, ah3, k0r, k1r);
                    MMA_F16(sc[2*p],   al0, al1, al2, al3, k0r, k1r);
                    MMA_F16(sc[2*p+1], ah0, ah1, ah2, ah3, k2r, k3r);
                    MMA_F16(sc[2*p+1], al0, al1, al2, al3, k2r, k3r);
                }
            }

            const int grow = qt * 64 + q0 + r;
#pragma unroll
            for (int nt = 0; nt < 8; nt++) {
                int c0 = t * 64 + nt * 8 + cq;
                float m0 = sMsf[mb + nt * 8 + cq], m1 = sMsf[mb + nt * 8 + cq + 1];
                float v;
                v = sc[nt][0] * 0.125f; sc[nt][0] = ((c0     <= grow    ) ? v : -10000.f) + m0;
                v = sc[nt][1] * 0.125f; sc[nt][1] = ((c0 + 1 <= grow    ) ? v : -10000.f) + m1;
                v = sc[nt][2] * 0.125f; sc[nt][2] = ((c0     <= grow + 8) ? v : -10000.f) + m0;
                v = sc[nt][3] * 0.125f; sc[nt][3] = ((c0 + 1 <= grow + 8) ? v : -10000.f) + m1;
            }

            float mx0 = -1e30f, mx1 = -1e30f;
#pragma unroll
            for (int nt = 0; nt < 8; nt++) {
                mx0 = fmaxf(mx0, fmaxf(sc[nt][0], sc[nt][1]));
                mx1 = fmaxf(mx1, fmaxf(sc[nt][2], sc[nt][3]));
            }
            mx0 = fmaxf(mx0, __shfl_xor_sync(0xffffffffu, mx0, 1));
            mx0 = fmaxf(mx0, __shfl_xor_sync(0xffffffffu, mx0, 2));
            mx1 = fmaxf(mx1, __shfl_xor_sync(0xffffffffu, mx1, 1));
            mx1 = fmaxf(mx1, __shfl_xor_sync(0xffffffffu, mx1, 2));
            float mn0 = fmaxf(mrow0, mx0), mn1 = fmaxf(mrow1, mx1);
            float al0f = __expf(mrow0 - mn0), al1f = __expf(mrow1 - mn1);
            float s0 = 0.f, s1 = 0.f;
#pragma unroll
            for (int nt = 0; nt < 8; nt++) {
                sc[nt][0] = __expf(sc[nt][0] - mn0); s0 += sc[nt][0];
                sc[nt][1] = __expf(sc[nt][1] - mn0); s0 += sc[nt][1];
                sc[nt][2] = __expf(sc[nt][2] - mn1); s1 += sc[nt][2];
                sc[nt][3] = __expf(sc[nt][3] - mn1); s1 += sc[nt][3];
            }
            s0 += __shfl_xor_sync(0xffffffffu, s0, 1);
            s0 += __shfl_xor_sync(0xffffffffu, s0, 2);
            s1 += __shfl_xor_sync(0xffffffffu, s1, 1);
            s1 += __shfl_xor_sync(0xffffffffu, s1, 2);
            lrow0 = lrow0 * al0f + s0; mrow0 = mn0;
            lrow1 = lrow1 * al1f + s1; mrow1 = mn1;
#pragma unroll
            for (int nt = 0; nt < 8; nt++) {
                o[nt][0] *= al0f; o[nt][1] *= al0f;
                o[nt][2] *= al1f; o[nt][3] *= al1f;
            }

#pragma unroll
            for (int kc = 0; kc < 4; kc++) {
                uint32_t ph[4], pl[4];
                split_pack_h(sc[2*kc][0],   sc[2*kc][1],   ph[0], pl[0]);
                split_pack_h(sc[2*kc][2],   sc[2*kc][3],   ph[1], pl[1]);
                split_pack_h(sc[2*kc+1][0], sc[2*kc+1][1], ph[2], pl[2]);
                split_pack_h(sc[2*kc+1][2], sc[2*kc+1][3], ph[3], pl[3]);
                const uint32_t vrow = kb + (uint32_t)(kc * 16 * AST) * 2;
#pragma unroll
                for (int p = 0; p < 4; p++) {
                    uint32_t v0r, v1r, v2r, v3r;
                    LDSM4T(v0r, v1r, v2r, v3r, uV + vrow + vfo[p]);
                    MMA_F16(o[2*p],   ph[0], ph[1], ph[2], ph[3], v0r, v1r);
                    MMA_F16(o[2*p],   pl[0], pl[1], pl[2], pl[3], v0r, v1r);
                    MMA_F16(o[2*p+1], ph[0], ph[1], ph[2], ph[3], v2r, v3r);
                    MMA_F16(o[2*p+1], pl[0], pl[1], pl[2], pl[3], v2r, v3r);
                }
            }
            __syncthreads();
        }

        float i0 = 1.f / lrow0, i1 = 1.f / lrow1;
        size_t ob = (size_t)b * SXX * 2048 + (size_t)(qt * 64 + q0 + r) * 2048 + h * 64;
#pragma unroll
        for (int dn = 0; dn < 8; dn++) {
            *(uint32_t*)&cath[ob + dn * 8 + cq] = pack_h2(o[dn][0] * i0, o[dn][1] * i0);
            *(uint32_t*)&cath[ob + (size_t)8 * 2048 + dn * 8 + cq] = pack_h2(o[dn][2] * i1, o[dn][3] * i1);
        }
    } else {
        const int off = FULLN - lenx;
        size_t obase = (size_t)b * SXX * 2048 + (size_t)(qt * 64) * 2048 + 1024 + h * 64;
        if (qt * 64 >= lenx) {
            const uint4 z = {0, 0, 0, 0};
            for (int i = tid; i < 512; i += 128) {
                int rr = i >> 3, seg = i & 7;
                *(uint4*)&cath[obase + (size_t)rr * 2048 + seg * 8] = z;
            }
            return;
        }

        const size_t qgb = (size_t)b * SXX * QSTRIDE;
        for (int i = tid; i < 512; i += 128) {
            int rr = i >> 3, seg = i & 7;
            size_t src = qgb + (size_t)(qt * 64 + rr) * QSTRIDE + 3072 + h * 64 + seg * 8;
            *(uint4*)&sQh[rr * AST + seg * 8] = *(const uint4*)&qkvh[src];
            *(uint4*)&sQl[rr * AST + seg * 8] = *(const uint4*)&qkvl[src];
        }

        int qlast = qt * 64 + 63;
        if (qlast >= lenx) qlast = lenx - 1;
        int jmax = off + qlast + 1;
        if (jmax > leny) jmax = leny;
        const int ntile = (jmax + 63) >> 6;
        const size_t kgb = (size_t)b * SYY * 2048;

#define APREF_CROSS(t) do { \
        uint32_t kd_ = uK + (uint32_t)((t) & 1) * KVB; \
        uint32_t vd_ = uV + (uint32_t)((t) & 1) * KVB; \
        _Pragma("unroll") \
        for (int it_ = 0; it_ < 4; it_++) { \
            int i_ = tid + it_ * 128; \
            int rr_ = i_ >> 3, sg_ = i_ & 7; \
            size_t kr_ = kgb + (size_t)((t) * 64 + rr_) * 2048 + h * 64 + sg_ * 8; \
            uint32_t so_ = (uint32_t)(rr_ * AST + sg_ * 8) * 2; \
            CP_ASYNC16(kd_ + so_, kvh + kr_); \
            CP_ASYNC16(vd_ + so_, kvh + kr_ + 1024); \
        } \
    } while (0)

        APREF_CROSS(0);
        CP_COMMIT();

        for (int t = 0; t < ntile; t++) {
            if (t + 1 < ntile) { APREF_CROSS(t + 1); CP_COMMIT(); CP_WAIT1(); }
            else               { CP_WAIT0(); }
            __syncthreads();
            const uint32_t kb = (uint32_t)(t & 1) * KVB;

            float sc[8][4];
#pragma unroll
            for (int i = 0; i < 8; i++)
#pragma unroll
                for (int j = 0; j < 4; j++) sc[i][j] = 0.f;

#pragma unroll
            for (int kt = 0; kt < 4; kt++) {
                const uint32_t ko = (uint32_t)(kt << 5);
                uint32_t ah0, ah1, ah2, ah3, al0, al1, al2, al3;
                LDSM4(ah0, ah1, ah2, ah3, uQh + qfo + ko);
                LDSM4(al0, al1, al2, al3, uQl + qfo + ko);
#pragma unroll
                for (int p = 0; p < 4; p++) {
                    uint32_t k0r, k1r, k2r, k3r;
                    LDSM4(k0r, k1r, k2r, k3r, uK + kb + kfo[p] + ko);
                    MMA_F16(sc[2*p],   ah0, ah1, ah2, ah3, k0r, k1r);
                    MMA_F16(sc[2*p],   al0, al1, al2, al3, k0r, k1r);
                    MMA_F16(sc[2*p+1], ah0, ah1, ah2, ah3, k2r, k3r);
                    MMA_F16(sc[2*p+1], al0, al1, al2, al3, k2r, k3r);
                }
            }

            const int grow = off + qt * 64 + q0 + r;
#pragma unroll
            for (int nt = 0; nt < 8; nt++) {
                int c0 = t * 64 + nt * 8 + cq;
                sc[nt][0] = (c0     <= grow     && c0     < leny) ? sc[nt][0] * 0.125f : -1e30f;
                sc[nt][1] = (c0 + 1 <= grow     && c0 + 1 < leny) ? sc[nt][1] * 0.125f : -1e30f;
                sc[nt][2] = (c0     <= grow + 8 && c0     < leny) ? sc[nt][2] * 0.125f : -1e30f;
                sc[nt][3] = (c0 + 1 <= grow + 8 && c0 + 1 < leny) ? sc[nt][3] * 0.125f : -1e30f;
            }

            float mx0 = -1e30f, mx1 = -1e30f;
#pragma unroll
            for (int nt = 0; nt < 8; nt++) {
                mx0 = fmaxf(mx0, fmaxf(sc[nt][0], sc[nt][1]));
                mx1 = fmaxf(mx1, fmaxf(sc[nt][2], sc[nt][3]));
            }
            mx0 = fmaxf(mx0, __shfl_xor_sync(0xffffffffu, mx0, 1));
            mx0 = fmaxf(mx0, __shfl_xor_sync(0xffffffffu, mx0, 2));
            mx1 = fmaxf(mx1, __shfl_xor_sync(0xffffffffu, mx1, 1));
            mx1 = fmaxf(mx1, __shfl_xor_sync(0xffffffffu, mx1, 2));
            float mn0 = fmaxf(mrow0, mx0), mn1 = fmaxf(mrow1, mx1);
            float al0f = __expf(mrow0 - mn0), al1f = __expf(mrow1 - mn1);
            float s0 = 0.f, s1 = 0.f;
#pragma unroll
            for (int nt = 0; nt < 8; nt++) {
                sc[nt][0] = __expf(sc[nt][0] - mn0); s0 += sc[nt][0];
                sc[nt][1] = __expf(sc[nt][1] - mn0); s0 += sc[nt][1];
                sc[nt][2] = __expf(sc[nt][2] - mn1); s1 += sc[nt][2];
                sc[nt][3] = __expf(sc[nt][3] - mn1); s1 += sc[nt][3];
            }
            s0 += __shfl_xor_sync(0xffffffffu, s0, 1);
            s0 += __shfl_xor_sync(0xffffffffu, s0, 2);
            s1 += __shfl_xor_sync(0xffffffffu, s1, 1);
            s1 += __shfl_xor_sync(0xffffffffu, s1, 2);
            lrow0 = lrow0 * al0f + s0; mrow0 = mn0;
            lrow1 = lrow1 * al1f + s1; mrow1 = mn1;
#pragma unroll
            for (int nt = 0; nt < 8; nt++) {
                o[nt][0] *= al0f; o[nt][1] *= al0f;
                o[nt][2] *= al1f; o[nt][3] *= al1f;
            }

#pragma unroll
            for (int kc = 0; kc < 4; kc++) {
                uint32_t ph[4], pl[4];
                split_pack_h(sc[2*kc][0],   sc[2*kc][1],   ph[0], pl[0]);
                split_pack_h(sc[2*kc][2],   sc[2*kc][3],   ph[1], pl[1]);
                split_pack_h(sc[2*kc+1][0], sc[2*kc+1][1], ph[2], pl[2]);
                split_pack_h(sc[2*kc+1][2], sc[2*kc+1][3], ph[3], pl[3]);
                const uint32_t vrow = kb + (uint32_t)(kc * 16 * AST) * 2;
#pragma unroll
                for (int p = 0; p < 4; p++) {
                    uint32_t v0r, v1r, v2r, v3r;
                    LDSM4T(v0r, v1r, v2r, v3r, uV + vrow + vfo[p]);
                    MMA_F16(o[2*p],   ph[0], ph[1], ph[2], ph[3], v0r, v1r);
                    MMA_F16(o[2*p],   pl[0], pl[1], pl[2], pl[3], v0r, v1r);
                    MMA_F16(o[2*p+1], ph[0], ph[1], ph[2], ph[3], v2r, v3r);
                    MMA_F16(o[2*p+1], pl[0], pl[1], pl[2], pl[3], v2r, v3r);
                }
            }
            __syncthreads();
        }

        float i0 = 1.f / lrow0, i1 = 1.f / lrow1;
        int row0 = qt * 64 + q0 + r, row1 = row0 + 8;
        bool v0 = row0 < lenx, v1 = row1 < lenx;
        size_t ob = (size_t)b * SXX * 2048 + (size_t)row0 * 2048 + 1024 + h * 64;
#pragma unroll
        for (int dn = 0; dn < 8; dn++) {
            *(uint32_t*)&cath[ob + dn * 8 + cq] =
                v0 ? pack_h2(o[dn][0] * i0, o[dn][1] * i0) : 0u;
            *(uint32_t*)&cath[ob + (size_t)8 * 2048 + dn * 8 + cq] =
                v1 ? pack_h2(o[dn][2] * i1, o[dn][3] * i1) : 0u;
        }
    }
}

// ---------------- launch ----------------
extern "C" void kernel_launch(void* const* d_in, const int* in_sizes, int n_in,
                              void* d_out, int out_size)
{
    const float* x      = (const float*)d_in[0];
    const float* y      = (const float*)d_in[1];
    const float* maskx  = (const float*)d_in[2];
    const float* W_attn = (const float*)d_in[3];
    const float* b_attn = (const float*)d_in[4];
    const float* W_2a   = (const float*)d_in[5];
    const float* b_2a   = (const float*)d_in[6];
    const float* W_2b   = (const float*)d_in[7];
    const float* b_2b   = (const float*)d_in[8];
    const float* W_proj = (const float*)d_in[9];
    const float* b_proj = (const float*)d_in[10];
    const int*   xtb    = (const int*)d_in[11];
    const int*   ytb    = (const int*)d_in[15];

    unsigned short *xh, *xl, *yh, *yl;
    unsigned short *qkvh, *qkvl, *kv2h, *cath;
    unsigned short *wc, *wb, *wph, *wpl;
    float* bias4k;
    cudaGetSymbolAddress((void**)&xh, g_xh);     cudaGetSymbolAddress((void**)&xl, g_xl);
    cudaGetSymbolAddress((void**)&yh, g_yh);     cudaGetSymbolAddress((void**)&yl, g_yl);
    cudaGetSymbolAddress((void**)&qkvh, g_qkvh); cudaGetSymbolAddress((void**)&qkvl, g_qkvl);
    cudaGetSymbolAddress((void**)&kv2h, g_kv2h);
    cudaGetSymbolAddress((void**)&cath, g_cath);
    cudaGetSymbolAddress((void**)&wc, g_wc_h);
    cudaGetSymbolAddress((void**)&wb, g_w2b_h);
    cudaGetSymbolAddress((void**)&wph, g_wpj_h); cudaGetSymbolAddress((void**)&wpl, g_wpj_l);
    cudaGetSymbolAddress((void**)&bias4k, g_bias4k);

    const int SMEM_GF = 6 * TSF * 2;                    // 110592 B
    const int SMEM_GP = (2 * TSF + 4 * TSB) * 2;        // 73728 B
    const int SMEM_ATTN = 6 * QB * 2 + 2 * 64 * 4;      // 55808 B
    cudaFuncSetAttribute((const void*)gemm_front, cudaFuncAttributeMaxDynamicSharedMemorySize, SMEM_GF);
    cudaFuncSetAttribute((const void*)gemm_proj,  cudaFuncAttributeMaxDynamicSharedMemorySize, SMEM_GP);
    cudaFuncSetAttribute((const void*)attn_fused, cudaFuncAttributeMaxDynamicSharedMemorySize, SMEM_ATTN);

    prep_small<<<17, 256>>>(xtb, in_sizes[11], ytb, in_sizes[15], b_attn, b_2a, bias4k);
    split_xy<<<4096, 256>>>(x, y, xh, xl, yh, yl);
    transpose_all<<<8192, 256>>>(W_attn, W_2a, W_2b, W_proj, wc, wb, wph, wpl);

    gemm_front<<<768, 256, SMEM_GF>>>(xh, xl, yh, yl, wc, wb, bias4k, b_2b, qkvh, qkvl, kv2h);

    attn_fused<<<dim3(32, 16, 2), 128, SMEM_ATTN>>>(qkvh, qkvl, kv2h, maskx, cath);

    gemm_proj<<<dim3(16, 16), 256, SMEM_GP>>>(cath, wph, wpl, b_proj, (float*)d_out, 2048, 1024, 2048);
}

// round 13
// speedup vs baseline: 1.8553x; 1.1445x over previous
#include <cuda_runtime.h>
#include <cuda_fp16.h>
#include <cstdint>

#define NB    2
#define SXX   1024
#define SYY   1024
#define DIM   1024
#define NH    16
#define HDIM  64
#define FULLN 1536

// ---------------- scratch (device globals) ----------------
__device__ int   g_lens[4];
__device__ float g_bias4k[4096];

__device__ unsigned short g_xh [2048 * 1024], g_xl [2048 * 1024];
__device__ unsigned short g_yh [2048 * 1024], g_yl [2048 * 1024];
// fused QKV|Q2 (hi only): cols 0-1023 Q, 1024-2047 K, 2048-3071 V, 3072-4095 Q2
__device__ unsigned short g_qkvh[2048 * 4096];
__device__ unsigned short g_kv2h[2048 * 2048];
__device__ unsigned short g_cath[2048 * 2048];
__device__ unsigned short g_wc_h [4096 * 1024];     // W_attn|W_2a [N,K]
__device__ unsigned short g_w2b_h[2048 * 1024];
__device__ unsigned short g_wpj_h[1024 * 2048];

// ---------------- helpers ----------------
__device__ __forceinline__ uint32_t smem_u32(const void* p) {
    uint32_t a;
    asm("{ .reg .u64 t; cvta.to.shared.u64 t, %1; cvt.u32.u64 %0, t; }" : "=r"(a) : "l"(p));
    return a;
}
#define CP_ASYNC16(dst, src) \
    asm volatile("cp.async.ca.shared.global [%0], [%1], 16;" :: "r"(dst), "l"(src) : "memory")
#define CP_COMMIT() asm volatile("cp.async.commit_group;" ::: "memory")
#define CP_WAIT1()  asm volatile("cp.async.wait_group 1;" ::: "memory")
#define CP_WAIT0()  asm volatile("cp.async.wait_group 0;" ::: "memory")

#define MMA_F16(c, a0, a1, a2, a3, b0, b1) \
    asm volatile("mma.sync.aligned.m16n8k16.row.col.f32.f16.f16.f32 " \
        "{%0,%1,%2,%3}, {%4,%5,%6,%7}, {%8,%9}, {%0,%1,%2,%3};" \
        : "+f"((c)[0]), "+f"((c)[1]), "+f"((c)[2]), "+f"((c)[3]) \
        : "r"(a0), "r"(a1), "r"(a2), "r"(a3), "r"(b0), "r"(b1))

#define LDSM4(r0, r1, r2, r3, a) \
    asm volatile("ldmatrix.sync.aligned.m8n8.x4.shared.b16 {%0,%1,%2,%3}, [%4];" \
        : "=r"(r0), "=r"(r1), "=r"(r2), "=r"(r3) : "r"(a))
#define LDSM4T(r0, r1, r2, r3, a) \
    asm volatile("ldmatrix.sync.aligned.m8n8.x4.trans.shared.b16 {%0,%1,%2,%3}, [%4];" \
        : "=r"(r0), "=r"(r1), "=r"(r2), "=r"(r3) : "r"(a))

__device__ __forceinline__ void split_pack_h(float a, float b, uint32_t& h, uint32_t& l) {
    __half ha = __float2half_rn(a), hb = __float2half_rn(b);
    __half la = __float2half_rn(a - __half2float(ha));
    __half lb = __float2half_rn(b - __half2float(hb));
    h = (uint32_t)*(unsigned short*)&ha | ((uint32_t)*(unsigned short*)&hb << 16);
    l = (uint32_t)*(unsigned short*)&la | ((uint32_t)*(unsigned short*)&lb << 16);
}
__device__ __forceinline__ uint32_t pack_h2(float a, float b) {
    __half2 v = __floats2half2_rn(a, b);
    return *(uint32_t*)&v;
}

// ---------------- ALL prep in one launch ----------------
// blocks [0,4096): x|y hi/lo split; [4096,12288): weight transposes;
// 12288..12303: bias concat; 12304: lens
__global__ __launch_bounds__(256)
void prep_all(const float* __restrict__ x, const float* __restrict__ y,
              unsigned short* __restrict__ xh, unsigned short* __restrict__ xl,
              unsigned short* __restrict__ yh, unsigned short* __restrict__ yl,
              const float* __restrict__ Wa, const float* __restrict__ W2a,
              const float* __restrict__ W2b, const float* __restrict__ Wp,
              unsigned short* __restrict__ wc, unsigned short* __restrict__ wb,
              unsigned short* __restrict__ wph,
              const int* __restrict__ xb, int nx, const int* __restrict__ yb, int ny,
              const float* __restrict__ ba, const float* __restrict__ b2a,
              float* __restrict__ bias4k)
{
    const int bid = blockIdx.x;
    if (bid < 4096) {
        const int N4 = 2048 * 1024 / 4;
        int i = bid * 256 + threadIdx.x;
        const float* in; unsigned short *oh, *ol;
        int j;
        if (i < N4) { in = x; oh = xh; ol = xl; j = i; }
        else        { in = y; oh = yh; ol = yl; j = i - N4; }
        float4 v = ((const float4*)in)[j];
        uint32_t h0, l0, h1, l1;
        split_pack_h(v.x, v.y, h0, l0);
        split_pack_h(v.z, v.w, h1, l1);
        ((uint2*)oh)[j] = make_uint2(h0, h1);
        ((uint2*)ol)[j] = make_uint2(l0, l1);
    } else if (bid < 12288) {
        int f = bid - 4096;
        const float* in; unsigned short* oh;
        int K, N, bx, by;
        if (f < 3072)      { in = Wa;  oh = wc;  K = 1024; N = 3072; bx = f % 96; by = f / 96; }
        else if (f < 4096) { in = W2a; oh = wc + (size_t)3072 * 1024; K = 1024; N = 1024; f -= 3072; bx = f % 32; by = f / 32; }
        else if (f < 6144) { in = W2b; oh = wb;  K = 1024; N = 2048; f -= 4096; bx = f % 64; by = f / 64; }
        else               { in = Wp;  oh = wph; K = 2048; N = 1024; f -= 6144; bx = f % 32; by = f / 32; }

        __shared__ float tile[32][33];
        int n0 = bx << 5, k0 = by << 5;
        int tx = threadIdx.x & 31, ty = threadIdx.x >> 5;
        for (int i = ty; i < 32; i += 8)
            tile[i][tx] = in[(size_t)(k0 + i) * N + n0 + tx];
        __syncthreads();
        for (int i = ty; i < 32; i += 8) {
            float v = tile[tx][i];
            __half h = __float2half_rn(v);
            oh[(size_t)(n0 + i) * K + k0 + tx] = *(unsigned short*)&h;
        }
    } else if (bid < 12304) {
        int i = (bid - 12288) * 256 + threadIdx.x;
        bias4k[i] = (i < 3072) ? ba[i] : b2a[i - 3072];
    } else {
        __shared__ int cnt[4];
        int t = threadIdx.x;
        if (t < 4) cnt[t] = 0;
        __syncthreads();
        for (int i = t; i < nx; i += blockDim.x) atomicAdd(&cnt[xb[i]], 1);
        for (int i = t; i < ny; i += blockDim.x) atomicAdd(&cnt[2 + yb[i]], 1);
        __syncthreads();
        if (t < 4) g_lens[t] = cnt[t];
    }
}

// ---------------- front GEMMs: 64x128 tile, K-chunk 64, 3 CTAs/SM ----------------
#define TSF (128 * 72)
#define TSB (64 * 72)

template<bool USEAL>
__device__ __forceinline__ void front_loop(
    const unsigned short* __restrict__ Ah, const unsigned short* __restrict__ Al,
    const unsigned short* __restrict__ Bh,
    int bm, int bn, int tid,
    uint32_t uA, uint32_t uAl, uint32_t uB,
    const uint32_t* aoff, const uint32_t* boff,
    float acc[2][4][4])
{
    const int K = 1024;
    const int nchunk = K >> 6;   // 16

#define PREFETCH_FL(t) do { \
        uint32_t sa_ = (uint32_t)((t) & 1) * (TSB * 2); \
        uint32_t sb_ = (uint32_t)((t) & 1) * (TSF * 2); \
        int k0_  = (t) << 6; \
        _Pragma("unroll") \
        for (int it_ = 0; it_ < 2; it_++) { \
            int i_ = tid + it_ * 256; \
            int row_ = i_ >> 3, sg_ = i_ & 7; \
            uint32_t so_ = sa_ + (uint32_t)(row_ * 72 + sg_ * 8) * 2; \
            size_t ao_ = (size_t)(bm + row_) * K + k0_ + sg_ * 8; \
            CP_ASYNC16(uA + so_, Ah + ao_); \
            if (USEAL) CP_ASYNC16(uAl + so_, Al + ao_); \
        } \
        _Pragma("unroll") \
        for (int it_ = 0; it_ < 4; it_++) { \
            int i_ = tid + it_ * 256; \
            int row_ = i_ >> 3, sg_ = i_ & 7; \
            uint32_t so_ = sb_ + (uint32_t)(row_ * 72 + sg_ * 8) * 2; \
            CP_ASYNC16(uB + so_, Bh + (size_t)(bn + row_) * K + k0_ + sg_ * 8); \
        } \
    } while (0)

    PREFETCH_FL(0);
    CP_COMMIT();

    for (int t = 0; t < nchunk; t++) {
        if (t + 1 < nchunk) { PREFETCH_FL(t + 1); CP_COMMIT(); CP_WAIT1(); }
        else                { CP_WAIT0(); }
        __syncthreads();
        const uint32_t sa = (uint32_t)(t & 1) * (TSB * 2);
        const uint32_t sb = (uint32_t)(t & 1) * (TSF * 2);
#pragma unroll
        for (int kt = 0; kt < 4; kt++) {
            const uint32_t ko = (uint32_t)(kt << 5);
            uint32_t bh[2][4];
#pragma unroll
            for (int p = 0; p < 2; p++)
                LDSM4(bh[p][0], bh[p][1], bh[p][2], bh[p][3], uB + sb + ko + boff[p]);
#pragma unroll
            for (int mi = 0; mi < 2; mi++) {
                uint32_t a0, a1, a2, a3;
                LDSM4(a0, a1, a2, a3, uA + sa + ko + aoff[mi]);
#pragma unroll
                for (int p = 0; p < 2; p++) {
                    MMA_F16(acc[mi][2*p],   a0, a1, a2, a3, bh[p][0], bh[p][1]);
                    MMA_F16(acc[mi][2*p+1], a0, a1, a2, a3, bh[p][2], bh[p][3]);
                }
                if (USEAL) {
                    uint32_t l0, l1, l2, l3;
                    LDSM4(l0, l1, l2, l3, uAl + sa + ko + aoff[mi]);
#pragma unroll
                    for (int p = 0; p < 2; p++) {
                        MMA_F16(acc[mi][2*p],   l0, l1, l2, l3, bh[p][0], bh[p][1]);
                        MMA_F16(acc[mi][2*p+1], l0, l1, l2, l3, bh[p][2], bh[p][3]);
                    }
                }
            }
        }
        __syncthreads();
    }
#undef PREFETCH_FL
}

__global__ __launch_bounds__(256, 3)
void gemm_front(const unsigned short* __restrict__ xh, const unsigned short* __restrict__ xl,
                const unsigned short* __restrict__ yh, const unsigned short* __restrict__ yl,
                const unsigned short* __restrict__ wc, const unsigned short* __restrict__ wb,
                const float* __restrict__ bias4k, const float* __restrict__ b2b,
                unsigned short* __restrict__ qkvh, unsigned short* __restrict__ kv2h)
{
    extern __shared__ unsigned short sm16[];
    unsigned short* sA  = sm16;             // [2][TSB]
    unsigned short* sAl = sm16 + 2 * TSB;   // [2][TSB]
    unsigned short* sB  = sm16 + 4 * TSB;   // [2][TSF]
    const uint32_t uA = smem_u32(sA), uAl = smem_u32(sAl), uB = smem_u32(sB);

    const int bid = blockIdx.x;
    const unsigned short *Ah, *Al, *Bh;
    const float* bias;
    unsigned short* Ch;
    int bm, bn, N;
    bool useAl;
    if (bid < 1024) {
        bm = (bid >> 5) << 6; bn = (bid & 31) << 7; N = 4096;
        Ah = xh; Al = xl; Bh = wc; bias = bias4k; Ch = qkvh;
        useAl = (bn >= 2048) && (bn < 3072);      // only V
    } else {
        int i = bid - 1024;
        bm = (i >> 4) << 6; bn = (i & 15) << 7; N = 2048;
        Ah = yh; Al = yl; Bh = wb; bias = b2b; Ch = kv2h;
        useAl = (bn >= 1024);                     // only V2
    }

    const int tid  = threadIdx.x;
    const int lane = tid & 31, wid = tid >> 5;
    const int wm = (wid >> 2) << 5;     // 0 / 32
    const int wn = (wid & 3) << 5;      // 0/32/64/96

    float acc[2][4][4];
#pragma unroll
    for (int i = 0; i < 2; i++)
#pragma unroll
        for (int j = 0; j < 4; j++)
#pragma unroll
            for (int k = 0; k < 4; k++) acc[i][j][k] = 0.f;

    const int l8 = lane & 7, g = lane >> 3;
    uint32_t aoff[2], boff[2];
#pragma unroll
    for (int mi = 0; mi < 2; mi++)
        aoff[mi] = (uint32_t)((wm + (mi << 4) + ((g & 1) << 3) + l8) * 72 + ((g >> 1) << 3)) * 2;
#pragma unroll
    for (int p = 0; p < 2; p++)
        boff[p] = (uint32_t)((wn + (p << 4) + ((g >> 1) << 3) + l8) * 72 + ((g & 1) << 3)) * 2;

    if (useAl) front_loop<true >(Ah, Al, Bh, bm, bn, tid, uA, uAl, uB, aoff, boff, acc);
    else       front_loop<false>(Ah, Al, Bh, bm, bn, tid, uA, uAl, uB, aoff, boff, acc);

    const int fr = lane >> 2;
    const int fc = (lane & 3) << 1;
#pragma unroll
    for (int mi = 0; mi < 2; mi++) {
        int row = bm + wm + (mi << 4) + fr;
#pragma unroll
        for (int ni = 0; ni < 4; ni++) {
            int col = bn + wn + (ni << 3) + fc;
            float bx = bias[col], by = bias[col + 1];
            *(uint32_t*)&Ch[(size_t)row * N + col] =
                pack_h2(acc[mi][ni][0] + bx, acc[mi][ni][1] + by);
            *(uint32_t*)&Ch[(size_t)(row + 8) * N + col] =
                pack_h2(acc[mi][ni][2] + bx, acc[mi][ni][3] + by);
        }
    }
}

// ---------------- proj GEMM: 128x64 tile, single product, 3 CTAs/SM ----------------
__global__ __launch_bounds__(256, 3)
void gemm_proj(const unsigned short* __restrict__ Ah,
               const unsigned short* __restrict__ Bh,
               const float* __restrict__ bias, float* __restrict__ Cf,
               int M, int N, int K)
{
    extern __shared__ unsigned short sm16[];
    unsigned short* sAh = sm16;                 // [2][TSF]
    unsigned short* sBh = sm16 + 2 * TSF;       // [2][TSB]
    const uint32_t uAh = smem_u32(sAh), uBh = smem_u32(sBh);

    const int tid  = threadIdx.x;
    const int lane = tid & 31, wid = tid >> 5;
    const int wm = (wid >> 2) << 6;
    const int wn = (wid & 3) << 4;
    const int bm = blockIdx.y << 7, bn = blockIdx.x << 6;

    float acc[4][2][4];
#pragma unroll
    for (int i = 0; i < 4; i++)
#pragma unroll
        for (int j = 0; j < 2; j++)
#pragma unroll
            for (int k = 0; k < 4; k++) acc[i][j][k] = 0.f;

    const int nchunk = K >> 6;   // 32

#define PREFETCH_P(t) do { \
        int k0_ = (t) << 6; \
        uint32_t sa_ = (uint32_t)((t) & 1) * (TSF * 2); \
        uint32_t sb_ = (uint32_t)((t) & 1) * (TSB * 2); \
        _Pragma("unroll") \
        for (int it_ = 0; it_ < 4; it_++) { \
            int i_ = tid + it_ * 256; \
            int row_ = i_ >> 3, sg_ = i_ & 7; \
            uint32_t so_ = sa_ + (uint32_t)(row_ * 72 + sg_ * 8) * 2; \
            CP_ASYNC16(uAh + so_, Ah + (size_t)(bm + row_) * K + k0_ + sg_ * 8); \
        } \
        _Pragma("unroll") \
        for (int it_ = 0; it_ < 2; it_++) { \
            int i_ = tid + it_ * 256; \
            int row_ = i_ >> 3, sg_ = i_ & 7; \
            uint32_t so_ = sb_ + (uint32_t)(row_ * 72 + sg_ * 8) * 2; \
            CP_ASYNC16(uBh + so_, Bh + (size_t)(bn + row_) * K + k0_ + sg_ * 8); \
        } \
    } while (0)

    PREFETCH_P(0);
    CP_COMMIT();

    const int l8 = lane & 7, g = lane >> 3;
    uint32_t aoff[4], boff;
#pragma unroll
    for (int mi = 0; mi < 4; mi++)
        aoff[mi] = (uint32_t)((wm + (mi << 4) + ((g & 1) << 3) + l8) * 72 + ((g >> 1) << 3)) * 2;
    boff = (uint32_t)((wn + ((g >> 1) << 3) + l8) * 72 + ((g & 1) << 3)) * 2;

    const int fr = lane >> 2;
    const int fc = (lane & 3) << 1;

    for (int t = 0; t < nchunk; t++) {
        if (t + 1 < nchunk) { PREFETCH_P(t + 1); CP_COMMIT(); CP_WAIT1(); }
        else                { CP_WAIT0(); }
        __syncthreads();
        const uint32_t sa = (uint32_t)(t & 1) * (TSF * 2);
        const uint32_t sb = (uint32_t)(t & 1) * (TSB * 2);
#pragma unroll
        for (int kt = 0; kt < 4; kt++) {
            const uint32_t ko = (uint32_t)(kt << 5);
            uint32_t bh0, bh1, bh2, bh3;
            LDSM4(bh0, bh1, bh2, bh3, uBh + sb + ko + boff);
#pragma unroll
            for (int mi = 0; mi < 4; mi++) {
                uint32_t a0, a1, a2, a3;
                LDSM4(a0, a1, a2, a3, uAh + sa + ko + aoff[mi]);
                MMA_F16(acc[mi][0], a0, a1, a2, a3, bh0, bh1);
                MMA_F16(acc[mi][1], a0, a1, a2, a3, bh2, bh3);
            }
        }
        __syncthreads();
    }

#pragma unroll
    for (int mi = 0; mi < 4; mi++) {
        int row = bm + wm + (mi << 4) + fr;
#pragma unroll
        for (int ni = 0; ni < 2; ni++) {
            int col = bn + wn + (ni << 3) + fc;
            float bx = bias[col], by = bias[col + 1];
            float2 v0 = { acc[mi][ni][0] + bx, acc[mi][ni][1] + by };
            float2 v1 = { acc[mi][ni][2] + bx, acc[mi][ni][3] + by };
            *(float2*)(Cf + (size_t)row * N + col)       = v0;
            *(float2*)(Cf + (size_t)(row + 8) * N + col) = v1;
        }
    }
}

// ================= fused MMA flash attention (self + cross), single-fp16 Q =================
#define AST 72
#define QB  (64 * AST)
#define KVB (QB * 2)
#define QSTRIDE 4096

__global__ __launch_bounds__(128)
void attn_fused(const unsigned short* __restrict__ qkvh,
                const unsigned short* __restrict__ kvh,
                const float* __restrict__ mask,
                unsigned short* __restrict__ cath)
{
    extern __shared__ char smraw[];
    unsigned short* sQ  = (unsigned short*)smraw;
    unsigned short* sK  = sQ + QB;
    unsigned short* sV  = sK + 2 * QB;
    float* sMsf = (float*)(sV + 2 * QB);
    const uint32_t uQ = smem_u32(sQ);
    const uint32_t uK = smem_u32(sK), uV = smem_u32(sV);
    const uint32_t uMs = smem_u32(sMsf);

    const int bx = blockIdx.x;
    const bool is_self = bx < 16;
    const int qt = is_self ? (15 - bx) : (31 - bx);
    const int h = blockIdx.y, b = blockIdx.z;
    const int tid = threadIdx.x, lane = tid & 31, wid = tid >> 5;
    const int q0 = wid << 4;
    const int r = lane >> 2, cq = (lane & 3) << 1;
    const int l8 = lane & 7, g = lane >> 3;

    const int lenx = g_lens[b], leny = g_lens[2 + b];

    uint32_t qfo = (uint32_t)((q0 + ((g & 1) << 3) + l8) * AST + ((g >> 1) << 3)) * 2;
    uint32_t kfo[4], vfo[4];
#pragma unroll
    for (int p = 0; p < 4; p++) {
        kfo[p] = (uint32_t)(((p << 4) + ((g >> 1) << 3) + l8) * AST + ((g & 1) << 3)) * 2;
        vfo[p] = (uint32_t)((((g & 1) << 3) + l8) * AST + (((p << 1) + (g >> 1)) << 3)) * 2;
    }

    float o[8][4];
#pragma unroll
    for (int i = 0; i < 8; i++)
#pragma unroll
        for (int j = 0; j < 4; j++) o[i][j] = 0.f;
    float mrow0 = -1e30f, mrow1 = -1e30f, lrow0 = 0.f, lrow1 = 0.f;

    if (is_self) {
        const size_t gb = (size_t)b * SXX * QSTRIDE;
        for (int i = tid; i < 512; i += 128) {
            int rr = i >> 3, seg = i & 7;
            *(uint4*)&sQ[rr * AST + seg * 8] =
                *(const uint4*)&qkvh[gb + (size_t)(qt * 64 + rr) * QSTRIDE + h * 64 + seg * 8];
        }

        const float* maskb = mask + b * SXX;
        int nt1 = qt + 1, nt2 = (lenx + 63) >> 6;
        const int ntile = nt1 < nt2 ? nt1 : nt2;

#define APREF_SELF(t) do { \
        uint32_t kd_ = uK + (uint32_t)((t) & 1) * KVB; \
        uint32_t vd_ = uV + (uint32_t)((t) & 1) * KVB; \
        _Pragma("unroll") \
        for (int it_ = 0; it_ < 4; it_++) { \
            int i_ = tid + it_ * 128; \
            int rr_ = i_ >> 3, sg_ = i_ & 7; \
            size_t kr_ = gb + (size_t)((t) * 64 + rr_) * QSTRIDE + 1024 + h * 64 + sg_ * 8; \
            uint32_t so_ = (uint32_t)(rr_ * AST + sg_ * 8) * 2; \
            CP_ASYNC16(kd_ + so_, qkvh + kr_); \
            CP_ASYNC16(vd_ + so_, qkvh + kr_ + 1024); \
        } \
        if (tid < 16) CP_ASYNC16(uMs + ((t) & 1) * 256 + tid * 16, maskb + (t) * 64 + tid * 4); \
    } while (0)

        APREF_SELF(0);
        CP_COMMIT();

        for (int t = 0; t < ntile; t++) {
            if (t + 1 < ntile) { APREF_SELF(t + 1); CP_COMMIT(); CP_WAIT1(); }
            else               { CP_WAIT0(); }
            __syncthreads();
            const uint32_t kb = (uint32_t)(t & 1) * KVB;
            const int mb = (t & 1) * 64;

            float sc[8][4];
#pragma unroll
            for (int i = 0; i < 8; i++)
#pragma unroll
                for (int j = 0; j < 4; j++) sc[i][j] = 0.f;

#pragma unroll
            for (int kt = 0; kt < 4; kt++) {
                const uint32_t ko = (uint32_t)(kt << 5);
                uint32_t a0, a1, a2, a3;
                LDSM4(a0, a1, a2, a3, uQ + qfo + ko);
#pragma unroll
                for (int p = 0; p < 4; p++) {
                    uint32_t k0r, k1r, k2r, k3r;
                    LDSM4(k0r, k1r, k2r, k3r, uK + kb + kfo[p] + ko);
                    MMA_F16(sc[2*p],   a0, a1, a2, a3, k0r, k1r);
                    MMA_F16(sc[2*p+1], a0, a1, a2, a3, k2r, k3r);
                }
            }

            const int grow = qt * 64 + q0 + r;
#pragma unroll
            for (int nt = 0; nt < 8; nt++) {
                int c0 = t * 64 + nt * 8 + cq;
                float m0 = sMsf[mb + nt * 8 + cq], m1 = sMsf[mb + nt * 8 + cq + 1];
                float v;
                v = sc[nt][0] * 0.125f; sc[nt][0] = ((c0     <= grow    ) ? v : -10000.f) + m0;
                v = sc[nt][1] * 0.125f; sc[nt][1] = ((c0 + 1 <= grow    ) ? v : -10000.f) + m1;
                v = sc[nt][2] * 0.125f; sc[nt][2] = ((c0     <= grow + 8) ? v : -10000.f) + m0;
                v = sc[nt][3] * 0.125f; sc[nt][3] = ((c0 + 1 <= grow + 8) ? v : -10000.f) + m1;
            }

            float mx0 = -1e30f, mx1 = -1e30f;
#pragma unroll
            for (int nt = 0; nt < 8; nt++) {
                mx0 = fmaxf(mx0, fmaxf(sc[nt][0], sc[nt][1]));
                mx1 = fmaxf(mx1, fmaxf(sc[nt][2], sc[nt][3]));
            }
            mx0 = fmaxf(mx0, __shfl_xor_sync(0xffffffffu, mx0, 1));
            mx0 = fmaxf(mx0, __shfl_xor_sync(0xffffffffu, mx0, 2));
            mx1 = fmaxf(mx1, __shfl_xor_sync(0xffffffffu, mx1, 1));
            mx1 = fmaxf(mx1, __shfl_xor_sync(0xffffffffu, mx1, 2));
            float mn0 = fmaxf(mrow0, mx0), mn1 = fmaxf(mrow1, mx1);
            float al0f = __expf(mrow0 - mn0), al1f = __expf(mrow1 - mn1);
            float s0 = 0.f, s1 = 0.f;
#pragma unroll
            for (int nt = 0; nt < 8; nt++) {
                sc[nt][0] = __expf(sc[nt][0] - mn0); s0 += sc[nt][0];
                sc[nt][1] = __expf(sc[nt][1] - mn0); s0 += sc[nt][1];
                sc[nt][2] = __expf(sc[nt][2] - mn1); s1 += sc[nt][2];
                sc[nt][3] = __expf(sc[nt][3] - mn1); s1 += sc[nt][3];
            }
            s0 += __shfl_xor_sync(0xffffffffu, s0, 1);
            s0 += __shfl_xor_sync(0xffffffffu, s0, 2);
            s1 += __shfl_xor_sync(0xffffffffu, s1, 1);
            s1 += __shfl_xor_sync(0xffffffffu, s1, 2);
            lrow0 = lrow0 * al0f + s0; mrow0 = mn0;
            lrow1 = lrow1 * al1f + s1; mrow1 = mn1;
#pragma unroll
            for (int nt = 0; nt < 8; nt++) {
                o[nt][0] *= al0f; o[nt][1] *= al0f;
                o[nt][2] *= al1f; o[nt][3] *= al1f;
            }

#pragma unroll
            for (int kc = 0; kc < 4; kc++) {
                uint32_t ph[4], pl[4];
                split_pack_h(sc[2*kc][0],   sc[2*kc][1],   ph[0], pl[0]);
                split_pack_h(sc[2*kc][2],   sc[2*kc][3],   ph[1], pl[1]);
                split_pack_h(sc[2*kc+1][0], sc[2*kc+1][1], ph[2], pl[2]);
                split_pack_h(sc[2*kc+1][2], sc[2*kc+1][3], ph[3], pl[3]);
                const uint32_t vrow = kb + (uint32_t)(kc * 16 * AST) * 2;
#pragma unroll
                for (int p = 0; p < 4; p++) {
                    uint32_t v0r, v1r, v2r, v3r;
                    LDSM4T(v0r, v1r, v2r, v3r, uV + vrow + vfo[p]);
                    MMA_F16(o[2*p],   ph[0], ph[1], ph[2], ph[3], v0r, v1r);
                    MMA_F16(o[2*p],   pl[0], pl[1], pl[2], pl[3], v0r, v1r);
                    MMA_F16(o[2*p+1], ph[0], ph[1], ph[2], ph[3], v2r, v3r);
                    MMA_F16(o[2*p+1], pl[0], pl[1], pl[2], pl[3], v2r, v3r);
                }
            }
            __syncthreads();
        }

        float i0 = 1.f / lrow0, i1 = 1.f / lrow1;
        size_t ob = (size_t)b * SXX * 2048 + (size_t)(qt * 64 + q0 + r) * 2048 + h * 64;
#pragma unroll
        for (int dn = 0; dn < 8; dn++) {
            *(uint32_t*)&cath[ob + dn * 8 + cq] = pack_h2(o[dn][0] * i0, o[dn][1] * i0);
            *(uint32_t*)&cath[ob + (size_t)8 * 2048 + dn * 8 + cq] = pack_h2(o[dn][2] * i1, o[dn][3] * i1);
        }
    } else {
        const int off = FULLN - lenx;
        size_t obase = (size_t)b * SXX * 2048 + (size_t)(qt * 64) * 2048 + 1024 + h * 64;
        if (qt * 64 >= lenx) {
            const uint4 z = {0, 0, 0, 0};
            for (int i = tid; i < 512; i += 128) {
                int rr = i >> 3, seg = i & 7;
                *(uint4*)&cath[obase + (size_t)rr * 2048 + seg * 8] = z;
            }
            return;
        }

        const size_t qgb = (size_t)b * SXX * QSTRIDE;
        for (int i = tid; i < 512; i += 128) {
            int rr = i >> 3, seg = i & 7;
            *(uint4*)&sQ[rr * AST + seg * 8] =
                *(const uint4*)&qkvh[qgb + (size_t)(qt * 64 + rr) * QSTRIDE + 3072 + h * 64 + seg * 8];
        }

        int qlast = qt * 64 + 63;
        if (qlast >= lenx) qlast = lenx - 1;
        int jmax = off + qlast + 1;
        if (jmax > leny) jmax = leny;
        const int ntile = (jmax + 63) >> 6;
        const size_t kgb = (size_t)b * SYY * 2048;

#define APREF_CROSS(t) do { \
        uint32_t kd_ = uK + (uint32_t)((t) & 1) * KVB; \
        uint32_t vd_ = uV + (uint32_t)((t) & 1) * KVB; \
        _Pragma("unroll") \
        for (int it_ = 0; it_ < 4; it_++) { \
            int i_ = tid + it_ * 128; \
            int rr_ = i_ >> 3, sg_ = i_ & 7; \
            size_t kr_ = kgb + (size_t)((t) * 64 + rr_) * 2048 + h * 64 + sg_ * 8; \
            uint32_t so_ = (uint32_t)(rr_ * AST + sg_ * 8) * 2; \
            CP_ASYNC16(kd_ + so_, kvh + kr_); \
            CP_ASYNC16(vd_ + so_, kvh + kr_ + 1024); \
        } \
    } while (0)

        APREF_CROSS(0);
        CP_COMMIT();

        for (int t = 0; t < ntile; t++) {
            if (t + 1 < ntile) { APREF_CROSS(t + 1); CP_COMMIT(); CP_WAIT1(); }
            else               { CP_WAIT0(); }
            __syncthreads();
            const uint32_t kb = (uint32_t)(t & 1) * KVB;

            float sc[8][4];
#pragma unroll
            for (int i = 0; i < 8; i++)
#pragma unroll
                for (int j = 0; j < 4; j++) sc[i][j] = 0.f;

#pragma unroll
            for (int kt = 0; kt < 4; kt++) {
                const uint32_t ko = (uint32_t)(kt << 5);
                uint32_t a0, a1, a2, a3;
                LDSM4(a0, a1, a2, a3, uQ + qfo + ko);
#pragma unroll
                for (int p = 0; p < 4; p++) {
                    uint32_t k0r, k1r, k2r, k3r;
                    LDSM4(k0r, k1r, k2r, k3r, uK + kb + kfo[p] + ko);
                    MMA_F16(sc[2*p],   a0, a1, a2, a3, k0r, k1r);
                    MMA_F16(sc[2*p+1], a0, a1, a2, a3, k2r, k3r);
                }
            }

            const int grow = off + qt * 64 + q0 + r;
#pragma unroll
            for (int nt = 0; nt < 8; nt++) {
                int c0 = t * 64 + nt * 8 + cq;
                sc[nt][0] = (c0     <= grow     && c0     < leny) ? sc[nt][0] * 0.125f : -1e30f;
                sc[nt][1] = (c0 + 1 <= grow     && c0 + 1 < leny) ? sc[nt][1] * 0.125f : -1e30f;
                sc[nt][2] = (c0     <= grow + 8 && c0     < leny) ? sc[nt][2] * 0.125f : -1e30f;
                sc[nt][3] = (c0 + 1 <= grow + 8 && c0 + 1 < leny) ? sc[nt][3] * 0.125f : -1e30f;
            }

            float mx0 = -1e30f, mx1 = -1e30f;
#pragma unroll
            for (int nt = 0; nt < 8; nt++) {
                mx0 = fmaxf(mx0, fmaxf(sc[nt][0], sc[nt][1]));
                mx1 = fmaxf(mx1, fmaxf(sc[nt][2], sc[nt][3]));
            }
            mx0 = fmaxf(mx0, __shfl_xor_sync(0xffffffffu, mx0, 1));
            mx0 = fmaxf(mx0, __shfl_xor_sync(0xffffffffu, mx0, 2));
            mx1 = fmaxf(mx1, __shfl_xor_sync(0xffffffffu, mx1, 1));
            mx1 = fmaxf(mx1, __shfl_xor_sync(0xffffffffu, mx1, 2));
            float mn0 = fmaxf(mrow0, mx0), mn1 = fmaxf(mrow1, mx1);
            float al0f = __expf(mrow0 - mn0), al1f = __expf(mrow1 - mn1);
            float s0 = 0.f, s1 = 0.f;
#pragma unroll
            for (int nt = 0; nt < 8; nt++) {
                sc[nt][0] = __expf(sc[nt][0] - mn0); s0 += sc[nt][0];
                sc[nt][1] = __expf(sc[nt][1] - mn0); s0 += sc[nt][1];
                sc[nt][2] = __expf(sc[nt][2] - mn1); s1 += sc[nt][2];
                sc[nt][3] = __expf(sc[nt][3] - mn1); s1 += sc[nt][3];
            }
            s0 += __shfl_xor_sync(0xffffffffu, s0, 1);
            s0 += __shfl_xor_sync(0xffffffffu, s0, 2);
            s1 += __shfl_xor_sync(0xffffffffu, s1, 1);
            s1 += __shfl_xor_sync(0xffffffffu, s1, 2);
            lrow0 = lrow0 * al0f + s0; mrow0 = mn0;
            lrow1 = lrow1 * al1f + s1; mrow1 = mn1;
#pragma unroll
            for (int nt = 0; nt < 8; nt++) {
                o[nt][0] *= al0f; o[nt][1] *= al0f;
                o[nt][2] *= al1f; o[nt][3] *= al1f;
            }

#pragma unroll
            for (int kc = 0; kc < 4; kc++) {
                uint32_t ph[4], pl[4];
                split_pack_h(sc[2*kc][0],   sc[2*kc][1],   ph[0], pl[0]);
                split_pack_h(sc[2*kc][2],   sc[2*kc][3],   ph[1], pl[1]);
                split_pack_h(sc[2*kc+1][0], sc[2*kc+1][1], ph[2], pl[2]);
                split_pack_h(sc[2*kc+1][2], sc[2*kc+1][3], ph[3], pl[3]);
                const uint32_t vrow = kb + (uint32_t)(kc * 16 * AST) * 2;
#pragma unroll
                for (int p = 0; p < 4; p++) {
                    uint32_t v0r, v1r, v2r, v3r;
                    LDSM4T(v0r, v1r, v2r, v3r, uV + vrow + vfo[p]);
                    MMA_F16(o[2*p],   ph[0], ph[1], ph[2], ph[3], v0r, v1r);
                    MMA_F16(o[2*p],   pl[0], pl[1], pl[2], pl[3], v0r, v1r);
                    MMA_F16(o[2*p+1], ph[0], ph[1], ph[2], ph[3], v2r, v3r);
                    MMA_F16(o[2*p+1], pl[0], pl[1], pl[2], pl[3], v2r, v3r);
                }
            }
            __syncthreads();
        }

        float i0 = 1.f / lrow0, i1 = 1.f / lrow1;
        int row0 = qt * 64 + q0 + r, row1 = row0 + 8;
        bool v0 = row0 < lenx, v1 = row1 < lenx;
        size_t ob = (size_t)b * SXX * 2048 + (size_t)row0 * 2048 + 1024 + h * 64;
#pragma unroll
        for (int dn = 0; dn < 8; dn++) {
            *(uint32_t*)&cath[ob + dn * 8 + cq] =
                v0 ? pack_h2(o[dn][0] * i0, o[dn][1] * i0) : 0u;
            *(uint32_t*)&cath[ob + (size_t)8 * 2048 + dn * 8 + cq] =
                v1 ? pack_h2(o[dn][2] * i1, o[dn][3] * i1) : 0u;
        }
    }
}

// ---------------- launch ----------------
extern "C" void kernel_launch(void* const* d_in, const int* in_sizes, int n_in,
                              void* d_out, int out_size)
{
    const float* x      = (const float*)d_in[0];
    const float* y      = (const float*)d_in[1];
    const float* maskx  = (const float*)d_in[2];
    const float* W_attn = (const float*)d_in[3];
    const float* b_attn = (const float*)d_in[4];
    const float* W_2a   = (const float*)d_in[5];
    const float* b_2a   = (const float*)d_in[6];
    const float* W_2b   = (const float*)d_in[7];
    const float* b_2b   = (const float*)d_in[8];
    const float* W_proj = (const float*)d_in[9];
    const float* b_proj = (const float*)d_in[10];
    const int*   xtb    = (const int*)d_in[11];
    const int*   ytb    = (const int*)d_in[15];

    unsigned short *xh, *xl, *yh, *yl;
    unsigned short *qkvh, *kv2h, *cath;
    unsigned short *wc, *wb, *wph;
    float* bias4k;
    cudaGetSymbolAddress((void**)&xh, g_xh);     cudaGetSymbolAddress((void**)&xl, g_xl);
    cudaGetSymbolAddress((void**)&yh, g_yh);     cudaGetSymbolAddress((void**)&yl, g_yl);
    cudaGetSymbolAddress((void**)&qkvh, g_qkvh);
    cudaGetSymbolAddress((void**)&kv2h, g_kv2h);
    cudaGetSymbolAddress((void**)&cath, g_cath);
    cudaGetSymbolAddress((void**)&wc, g_wc_h);
    cudaGetSymbolAddress((void**)&wb, g_w2b_h);
    cudaGetSymbolAddress((void**)&wph, g_wpj_h);
    cudaGetSymbolAddress((void**)&bias4k, g_bias4k);

    const int SMEM_GF = (4 * TSB + 2 * TSF) * 2;        // 73728 B
    const int SMEM_GP = (2 * TSF + 2 * TSB) * 2;        // 55296 B
    const int SMEM_ATTN = 5 * QB * 2 + 2 * 64 * 4;      // 46592 B
    cudaFuncSetAttribute((const void*)gemm_front, cudaFuncAttributeMaxDynamicSharedMemorySize, SMEM_GF);
    cudaFuncSetAttribute((const void*)gemm_proj,  cudaFuncAttributeMaxDynamicSharedMemorySize, SMEM_GP);
    cudaFuncSetAttribute((const void*)attn_fused, cudaFuncAttributeMaxDynamicSharedMemorySize, SMEM_ATTN);

    prep_all<<<12305, 256>>>(x, y, xh, xl, yh, yl,
                             W_attn, W_2a, W_2b, W_proj, wc, wb, wph,
                             xtb, in_sizes[11], ytb, in_sizes[15],
                             b_attn, b_2a, bias4k);

    gemm_front<<<1536, 256, SMEM_GF>>>(xh, xl, yh, yl, wc, wb, bias4k, b_2b, qkvh, kv2h);

    attn_fused<<<dim3(32, 16, 2), 128, SMEM_ATTN>>>(qkvh, kv2h, maskx, cath);

    gemm_proj<<<dim3(16, 16), 256, SMEM_GP>>>(cath, wph, b_proj, (float*)d_out, 2048, 1024, 2048);
}

// round 14
// speedup vs baseline: 1.9400x; 1.0457x over previous
#include <cuda_runtime.h>
#include <cuda_fp16.h>
#include <cstdint>

#define NB    2
#define SXX   1024
#define SYY   1024
#define DIM   1024
#define NH    16
#define HDIM  64
#define FULLN 1536

// ---------------- scratch (device globals) ----------------
__device__ int   g_lens[4];
__device__ float g_bias4k[4096];

__device__ unsigned short g_xh [2048 * 1024], g_xl [2048 * 1024];
__device__ unsigned short g_yh [2048 * 1024], g_yl [2048 * 1024];
// fused QKV|Q2 (hi only): cols 0-1023 Q, 1024-2047 K, 2048-3071 V, 3072-4095 Q2
__device__ unsigned short g_qkvh[2048 * 4096];
__device__ unsigned short g_kv2h[2048 * 2048];
__device__ unsigned short g_cath[2048 * 2048];
__device__ unsigned short g_wc_h [4096 * 1024];     // W_attn|W_2a [N,K]
__device__ unsigned short g_w2b_h[2048 * 1024];
__device__ unsigned short g_wpj_h[1024 * 2048];

// ---------------- helpers ----------------
__device__ __forceinline__ uint32_t smem_u32(const void* p) {
    uint32_t a;
    asm("{ .reg .u64 t; cvta.to.shared.u64 t, %1; cvt.u32.u64 %0, t; }" : "=r"(a) : "l"(p));
    return a;
}
#define CP_ASYNC16(dst, src) \
    asm volatile("cp.async.ca.shared.global [%0], [%1], 16;" :: "r"(dst), "l"(src) : "memory")
#define CP_COMMIT() asm volatile("cp.async.commit_group;" ::: "memory")
#define CP_WAIT1()  asm volatile("cp.async.wait_group 1;" ::: "memory")
#define CP_WAIT0()  asm volatile("cp.async.wait_group 0;" ::: "memory")

#define MMA_F16(c, a0, a1, a2, a3, b0, b1) \
    asm volatile("mma.sync.aligned.m16n8k16.row.col.f32.f16.f16.f32 " \
        "{%0,%1,%2,%3}, {%4,%5,%6,%7}, {%8,%9}, {%0,%1,%2,%3};" \
        : "+f"((c)[0]), "+f"((c)[1]), "+f"((c)[2]), "+f"((c)[3]) \
        : "r"(a0), "r"(a1), "r"(a2), "r"(a3), "r"(b0), "r"(b1))

#define LDSM4(r0, r1, r2, r3, a) \
    asm volatile("ldmatrix.sync.aligned.m8n8.x4.shared.b16 {%0,%1,%2,%3}, [%4];" \
        : "=r"(r0), "=r"(r1), "=r"(r2), "=r"(r3) : "r"(a))
#define LDSM4T(r0, r1, r2, r3, a) \
    asm volatile("ldmatrix.sync.aligned.m8n8.x4.trans.shared.b16 {%0,%1,%2,%3}, [%4];" \
        : "=r"(r0), "=r"(r1), "=r"(r2), "=r"(r3) : "r"(a))

__device__ __forceinline__ void split_pack_h(float a, float b, uint32_t& h, uint32_t& l) {
    __half ha = __float2half_rn(a), hb = __float2half_rn(b);
    __half la = __float2half_rn(a - __half2float(ha));
    __half lb = __float2half_rn(b - __half2float(hb));
    h = (uint32_t)*(unsigned short*)&ha | ((uint32_t)*(unsigned short*)&hb << 16);
    l = (uint32_t)*(unsigned short*)&la | ((uint32_t)*(unsigned short*)&lb << 16);
}
__device__ __forceinline__ uint32_t pack_h2(float a, float b) {
    __half2 v = __floats2half2_rn(a, b);
    return *(uint32_t*)&v;
}

// ---------------- ALL prep in one launch ----------------
__global__ __launch_bounds__(256)
void prep_all(const float* __restrict__ x, const float* __restrict__ y,
              unsigned short* __restrict__ xh, unsigned short* __restrict__ xl,
              unsigned short* __restrict__ yh, unsigned short* __restrict__ yl,
              const float* __restrict__ Wa, const float* __restrict__ W2a,
              const float* __restrict__ W2b, const float* __restrict__ Wp,
              unsigned short* __restrict__ wc, unsigned short* __restrict__ wb,
              unsigned short* __restrict__ wph,
              const int* __restrict__ xb, int nx, const int* __restrict__ yb, int ny,
              const float* __restrict__ ba, const float* __restrict__ b2a,
              float* __restrict__ bias4k)
{
    const int bid = blockIdx.x;
    if (bid < 4096) {
        const int N4 = 2048 * 1024 / 4;
        int i = bid * 256 + threadIdx.x;
        const float* in; unsigned short *oh, *ol;
        int j;
        if (i < N4) { in = x; oh = xh; ol = xl; j = i; }
        else        { in = y; oh = yh; ol = yl; j = i - N4; }
        float4 v = ((const float4*)in)[j];
        uint32_t h0, l0, h1, l1;
        split_pack_h(v.x, v.y, h0, l0);
        split_pack_h(v.z, v.w, h1, l1);
        ((uint2*)oh)[j] = make_uint2(h0, h1);
        ((uint2*)ol)[j] = make_uint2(l0, l1);
    } else if (bid < 12288) {
        int f = bid - 4096;
        const float* in; unsigned short* oh;
        int K, N, bx, by;
        if (f < 3072)      { in = Wa;  oh = wc;  K = 1024; N = 3072; bx = f % 96; by = f / 96; }
        else if (f < 4096) { in = W2a; oh = wc + (size_t)3072 * 1024; K = 1024; N = 1024; f -= 3072; bx = f % 32; by = f / 32; }
        else if (f < 6144) { in = W2b; oh = wb;  K = 1024; N = 2048; f -= 4096; bx = f % 64; by = f / 64; }
        else               { in = Wp;  oh = wph; K = 2048; N = 1024; f -= 6144; bx = f % 32; by = f / 32; }

        __shared__ float tile[32][33];
        int n0 = bx << 5, k0 = by << 5;
        int tx = threadIdx.x & 31, ty = threadIdx.x >> 5;
        for (int i = ty; i < 32; i += 8)
            tile[i][tx] = in[(size_t)(k0 + i) * N + n0 + tx];
        __syncthreads();
        for (int i = ty; i < 32; i += 8) {
            float v = tile[tx][i];
            __half h = __float2half_rn(v);
            oh[(size_t)(n0 + i) * K + k0 + tx] = *(unsigned short*)&h;
        }
    } else if (bid < 12304) {
        int i = (bid - 12288) * 256 + threadIdx.x;
        bias4k[i] = (i < 3072) ? ba[i] : b2a[i - 3072];
    } else {
        __shared__ int cnt[4];
        int t = threadIdx.x;
        if (t < 4) cnt[t] = 0;
        __syncthreads();
        for (int i = t; i < nx; i += blockDim.x) atomicAdd(&cnt[xb[i]], 1);
        for (int i = t; i < ny; i += blockDim.x) atomicAdd(&cnt[2 + yb[i]], 1);
        __syncthreads();
        if (t < 4) g_lens[t] = cnt[t];
    }
}

// ---------------- front GEMMs: 64x128 tile, K-chunk 64, 3 CTAs/SM ----------------
#define TSF (128 * 72)
#define TSB (64 * 72)

template<bool USEAL>
__device__ __forceinline__ void front_loop(
    const unsigned short* __restrict__ Ah, const unsigned short* __restrict__ Al,
    const unsigned short* __restrict__ Bh,
    int bm, int bn, int tid,
    uint32_t uA, uint32_t uAl, uint32_t uB,
    const uint32_t* aoff, const uint32_t* boff,
    float acc[2][4][4])
{
    const int K = 1024;
    const int nchunk = K >> 6;

#define PREFETCH_FL(t) do { \
        uint32_t sa_ = (uint32_t)((t) & 1) * (TSB * 2); \
        uint32_t sb_ = (uint32_t)((t) & 1) * (TSF * 2); \
        int k0_  = (t) << 6; \
        _Pragma("unroll") \
        for (int it_ = 0; it_ < 2; it_++) { \
            int i_ = tid + it_ * 256; \
            int row_ = i_ >> 3, sg_ = i_ & 7; \
            uint32_t so_ = sa_ + (uint32_t)(row_ * 72 + sg_ * 8) * 2; \
            size_t ao_ = (size_t)(bm + row_) * K + k0_ + sg_ * 8; \
            CP_ASYNC16(uA + so_, Ah + ao_); \
            if (USEAL) CP_ASYNC16(uAl + so_, Al + ao_); \
        } \
        _Pragma("unroll") \
        for (int it_ = 0; it_ < 4; it_++) { \
            int i_ = tid + it_ * 256; \
            int row_ = i_ >> 3, sg_ = i_ & 7; \
            uint32_t so_ = sb_ + (uint32_t)(row_ * 72 + sg_ * 8) * 2; \
            CP_ASYNC16(uB + so_, Bh + (size_t)(bn + row_) * K + k0_ + sg_ * 8); \
        } \
    } while (0)

    PREFETCH_FL(0);
    CP_COMMIT();

    for (int t = 0; t < nchunk; t++) {
        if (t + 1 < nchunk) { PREFETCH_FL(t + 1); CP_COMMIT(); CP_WAIT1(); }
        else                { CP_WAIT0(); }
        __syncthreads();
        const uint32_t sa = (uint32_t)(t & 1) * (TSB * 2);
        const uint32_t sb = (uint32_t)(t & 1) * (TSF * 2);
#pragma unroll
        for (int kt = 0; kt < 4; kt++) {
            const uint32_t ko = (uint32_t)(kt << 5);
            uint32_t bh[2][4];
#pragma unroll
            for (int p = 0; p < 2; p++)
                LDSM4(bh[p][0], bh[p][1], bh[p][2], bh[p][3], uB + sb + ko + boff[p]);
#pragma unroll
            for (int mi = 0; mi < 2; mi++) {
                uint32_t a0, a1, a2, a3;
                LDSM4(a0, a1, a2, a3, uA + sa + ko + aoff[mi]);
#pragma unroll
                for (int p = 0; p < 2; p++) {
                    MMA_F16(acc[mi][2*p],   a0, a1, a2, a3, bh[p][0], bh[p][1]);
                    MMA_F16(acc[mi][2*p+1], a0, a1, a2, a3, bh[p][2], bh[p][3]);
                }
                if (USEAL) {
                    uint32_t l0, l1, l2, l3;
                    LDSM4(l0, l1, l2, l3, uAl + sa + ko + aoff[mi]);
#pragma unroll
                    for (int p = 0; p < 2; p++) {
                        MMA_F16(acc[mi][2*p],   l0, l1, l2, l3, bh[p][0], bh[p][1]);
                        MMA_F16(acc[mi][2*p+1], l0, l1, l2, l3, bh[p][2], bh[p][3]);
                    }
                }
            }
        }
        __syncthreads();
    }
#undef PREFETCH_FL
}

__global__ __launch_bounds__(256, 3)
void gemm_front(const unsigned short* __restrict__ xh, const unsigned short* __restrict__ xl,
                const unsigned short* __restrict__ yh, const unsigned short* __restrict__ yl,
                const unsigned short* __restrict__ wc, const unsigned short* __restrict__ wb,
                const float* __restrict__ bias4k, const float* __restrict__ b2b,
                unsigned short* __restrict__ qkvh, unsigned short* __restrict__ kv2h)
{
    extern __shared__ unsigned short sm16[];
    unsigned short* sA  = sm16;
    unsigned short* sAl = sm16 + 2 * TSB;
    unsigned short* sB  = sm16 + 4 * TSB;
    const uint32_t uA = smem_u32(sA), uAl = smem_u32(sAl), uB = smem_u32(sB);

    const int bid = blockIdx.x;
    const unsigned short *Ah, *Al, *Bh;
    const float* bias;
    unsigned short* Ch;
    int bm, bn, N;
    bool useAl;
    if (bid < 1024) {
        bm = (bid >> 5) << 6; bn = (bid & 31) << 7; N = 4096;
        Ah = xh; Al = xl; Bh = wc; bias = bias4k; Ch = qkvh;
        useAl = (bn >= 2048) && (bn < 3072);
    } else {
        int i = bid - 1024;
        bm = (i >> 4) << 6; bn = (i & 15) << 7; N = 2048;
        Ah = yh; Al = yl; Bh = wb; bias = b2b; Ch = kv2h;
        useAl = (bn >= 1024);
    }

    const int tid  = threadIdx.x;
    const int lane = tid & 31, wid = tid >> 5;
    const int wm = (wid >> 2) << 5;
    const int wn = (wid & 3) << 5;

    float acc[2][4][4];
#pragma unroll
    for (int i = 0; i < 2; i++)
#pragma unroll
        for (int j = 0; j < 4; j++)
#pragma unroll
            for (int k = 0; k < 4; k++) acc[i][j][k] = 0.f;

    const int l8 = lane & 7, g = lane >> 3;
    uint32_t aoff[2], boff[2];
#pragma unroll
    for (int mi = 0; mi < 2; mi++)
        aoff[mi] = (uint32_t)((wm + (mi << 4) + ((g & 1) << 3) + l8) * 72 + ((g >> 1) << 3)) * 2;
#pragma unroll
    for (int p = 0; p < 2; p++)
        boff[p] = (uint32_t)((wn + (p << 4) + ((g >> 1) << 3) + l8) * 72 + ((g & 1) << 3)) * 2;

    if (useAl) front_loop<true >(Ah, Al, Bh, bm, bn, tid, uA, uAl, uB, aoff, boff, acc);
    else       front_loop<false>(Ah, Al, Bh, bm, bn, tid, uA, uAl, uB, aoff, boff, acc);

    const int fr = lane >> 2;
    const int fc = (lane & 3) << 1;
#pragma unroll
    for (int mi = 0; mi < 2; mi++) {
        int row = bm + wm + (mi << 4) + fr;
#pragma unroll
        for (int ni = 0; ni < 4; ni++) {
            int col = bn + wn + (ni << 3) + fc;
            float bx = bias[col], by = bias[col + 1];
            *(uint32_t*)&Ch[(size_t)row * N + col] =
                pack_h2(acc[mi][ni][0] + bx, acc[mi][ni][1] + by);
            *(uint32_t*)&Ch[(size_t)(row + 8) * N + col] =
                pack_h2(acc[mi][ni][2] + bx, acc[mi][ni][3] + by);
        }
    }
}

// ---------------- proj GEMM: 64x64 tile, single product, single wave ----------------
__global__ __launch_bounds__(256, 4)
void gemm_proj(const unsigned short* __restrict__ Ah,
               const unsigned short* __restrict__ Bh,
               const float* __restrict__ bias, float* __restrict__ Cf,
               int M, int N, int K)
{
    extern __shared__ unsigned short sm16[];
    unsigned short* sAh = sm16;                 // [2][TSB]
    unsigned short* sBh = sm16 + 2 * TSB;       // [2][TSB]
    const uint32_t uAh = smem_u32(sAh), uBh = smem_u32(sBh);

    const int tid  = threadIdx.x;
    const int lane = tid & 31, wid = tid >> 5;
    const int wm = (wid >> 2) << 5;     // 0 / 32
    const int wn = (wid & 3) << 4;      // 0/16/32/48
    const int bm = blockIdx.y << 6, bn = blockIdx.x << 6;

    float acc[2][2][4];
#pragma unroll
    for (int i = 0; i < 2; i++)
#pragma unroll
        for (int j = 0; j < 2; j++)
#pragma unroll
            for (int k = 0; k < 4; k++) acc[i][j][k] = 0.f;

    const int nchunk = K >> 6;   // 32

#define PREFETCH_P(t) do { \
        int k0_ = (t) << 6; \
        uint32_t st_ = (uint32_t)((t) & 1) * (TSB * 2); \
        _Pragma("unroll") \
        for (int it_ = 0; it_ < 2; it_++) { \
            int i_ = tid + it_ * 256; \
            int row_ = i_ >> 3, sg_ = i_ & 7; \
            uint32_t so_ = st_ + (uint32_t)(row_ * 72 + sg_ * 8) * 2; \
            CP_ASYNC16(uAh + so_, Ah + (size_t)(bm + row_) * K + k0_ + sg_ * 8); \
            CP_ASYNC16(uBh + so_, Bh + (size_t)(bn + row_) * K + k0_ + sg_ * 8); \
        } \
    } while (0)

    PREFETCH_P(0);
    CP_COMMIT();

    const int l8 = lane & 7, g = lane >> 3;
    uint32_t aoff[2], boff;
#pragma unroll
    for (int mi = 0; mi < 2; mi++)
        aoff[mi] = (uint32_t)((wm + (mi << 4) + ((g & 1) << 3) + l8) * 72 + ((g >> 1) << 3)) * 2;
    boff = (uint32_t)((wn + ((g >> 1) << 3) + l8) * 72 + ((g & 1) << 3)) * 2;

    const int fr = lane >> 2;
    const int fc = (lane & 3) << 1;

    for (int t = 0; t < nchunk; t++) {
        if (t + 1 < nchunk) { PREFETCH_P(t + 1); CP_COMMIT(); CP_WAIT1(); }
        else                { CP_WAIT0(); }
        __syncthreads();
        const uint32_t st = (uint32_t)(t & 1) * (TSB * 2);
#pragma unroll
        for (int kt = 0; kt < 4; kt++) {
            const uint32_t ko = (uint32_t)(kt << 5);
            uint32_t bh0, bh1, bh2, bh3;
            LDSM4(bh0, bh1, bh2, bh3, uBh + st + ko + boff);
#pragma unroll
            for (int mi = 0; mi < 2; mi++) {
                uint32_t a0, a1, a2, a3;
                LDSM4(a0, a1, a2, a3, uAh + st + ko + aoff[mi]);
                MMA_F16(acc[mi][0], a0, a1, a2, a3, bh0, bh1);
                MMA_F16(acc[mi][1], a0, a1, a2, a3, bh2, bh3);
            }
        }
        __syncthreads();
    }

#pragma unroll
    for (int mi = 0; mi < 2; mi++) {
        int row = bm + wm + (mi << 4) + fr;
#pragma unroll
        for (int ni = 0; ni < 2; ni++) {
            int col = bn + wn + (ni << 3) + fc;
            float bx = bias[col], by = bias[col + 1];
            float2 v0 = { acc[mi][ni][0] + bx, acc[mi][ni][1] + by };
            float2 v1 = { acc[mi][ni][2] + bx, acc[mi][ni][3] + by };
            *(float2*)(Cf + (size_t)row * N + col)       = v0;
            *(float2*)(Cf + (size_t)(row + 8) * N + col) = v1;
        }
    }
}

// ================= fused MMA flash attention (single-fp16 Q and P) =================
#define AST 72
#define QB  (64 * AST)
#define KVB (QB * 2)
#define QSTRIDE 4096

__global__ __launch_bounds__(128)
void attn_fused(const unsigned short* __restrict__ qkvh,
                const unsigned short* __restrict__ kvh,
                const float* __restrict__ mask,
                unsigned short* __restrict__ cath)
{
    extern __shared__ char smraw[];
    unsigned short* sQ  = (unsigned short*)smraw;
    unsigned short* sK  = sQ + QB;
    unsigned short* sV  = sK + 2 * QB;
    float* sMsf = (float*)(sV + 2 * QB);
    const uint32_t uQ = smem_u32(sQ);
    const uint32_t uK = smem_u32(sK), uV = smem_u32(sV);
    const uint32_t uMs = smem_u32(sMsf);

    const int bx = blockIdx.x;
    const bool is_self = bx < 16;
    const int qt = is_self ? (15 - bx) : (31 - bx);
    const int h = blockIdx.y, b = blockIdx.z;
    const int tid = threadIdx.x, lane = tid & 31, wid = tid >> 5;
    const int q0 = wid << 4;
    const int r = lane >> 2, cq = (lane & 3) << 1;
    const int l8 = lane & 7, g = lane >> 3;

    const int lenx = g_lens[b], leny = g_lens[2 + b];

    uint32_t qfo = (uint32_t)((q0 + ((g & 1) << 3) + l8) * AST + ((g >> 1) << 3)) * 2;
    uint32_t kfo[4], vfo[4];
#pragma unroll
    for (int p = 0; p < 4; p++) {
        kfo[p] = (uint32_t)(((p << 4) + ((g >> 1) << 3) + l8) * AST + ((g & 1) << 3)) * 2;
        vfo[p] = (uint32_t)((((g & 1) << 3) + l8) * AST + (((p << 1) + (g >> 1)) << 3)) * 2;
    }

    float o[8][4];
#pragma unroll
    for (int i = 0; i < 8; i++)
#pragma unroll
        for (int j = 0; j < 4; j++) o[i][j] = 0.f;
    float mrow0 = -1e30f, mrow1 = -1e30f, lrow0 = 0.f, lrow1 = 0.f;

    if (is_self) {
        const size_t gb = (size_t)b * SXX * QSTRIDE;
        for (int i = tid; i < 512; i += 128) {
            int rr = i >> 3, seg = i & 7;
            *(uint4*)&sQ[rr * AST + seg * 8] =
                *(const uint4*)&qkvh[gb + (size_t)(qt * 64 + rr) * QSTRIDE + h * 64 + seg * 8];
        }

        const float* maskb = mask + b * SXX;
        int nt1 = qt + 1, nt2 = (lenx + 63) >> 6;
        const int ntile = nt1 < nt2 ? nt1 : nt2;

#define APREF_SELF(t) do { \
        uint32_t kd_ = uK + (uint32_t)((t) & 1) * KVB; \
        uint32_t vd_ = uV + (uint32_t)((t) & 1) * KVB; \
        _Pragma("unroll") \
        for (int it_ = 0; it_ < 4; it_++) { \
            int i_ = tid + it_ * 128; \
            int rr_ = i_ >> 3, sg_ = i_ & 7; \
            size_t kr_ = gb + (size_t)((t) * 64 + rr_) * QSTRIDE + 1024 + h * 64 + sg_ * 8; \
            uint32_t so_ = (uint32_t)(rr_ * AST + sg_ * 8) * 2; \
            CP_ASYNC16(kd_ + so_, qkvh + kr_); \
            CP_ASYNC16(vd_ + so_, qkvh + kr_ + 1024); \
        } \
        if (tid < 16) CP_ASYNC16(uMs + ((t) & 1) * 256 + tid * 16, maskb + (t) * 64 + tid * 4); \
    } while (0)

        APREF_SELF(0);
        CP_COMMIT();

        for (int t = 0; t < ntile; t++) {
            if (t + 1 < ntile) { APREF_SELF(t + 1); CP_COMMIT(); CP_WAIT1(); }
            else               { CP_WAIT0(); }
            __syncthreads();
            const uint32_t kb = (uint32_t)(t & 1) * KVB;
            const int mb = (t & 1) * 64;

            float sc[8][4];
#pragma unroll
            for (int i = 0; i < 8; i++)
#pragma unroll
                for (int j = 0; j < 4; j++) sc[i][j] = 0.f;

#pragma unroll
            for (int kt = 0; kt < 4; kt++) {
                const uint32_t ko = (uint32_t)(kt << 5);
                uint32_t a0, a1, a2, a3;
                LDSM4(a0, a1, a2, a3, uQ + qfo + ko);
#pragma unroll
                for (int p = 0; p < 4; p++) {
                    uint32_t k0r, k1r, k2r, k3r;
                    LDSM4(k0r, k1r, k2r, k3r, uK + kb + kfo[p] + ko);
                    MMA_F16(sc[2*p],   a0, a1, a2, a3, k0r, k1r);
                    MMA_F16(sc[2*p+1], a0, a1, a2, a3, k2r, k3r);
                }
            }

            const int grow = qt * 64 + q0 + r;
#pragma unroll
            for (int nt = 0; nt < 8; nt++) {
                int c0 = t * 64 + nt * 8 + cq;
                float m0 = sMsf[mb + nt * 8 + cq], m1 = sMsf[mb + nt * 8 + cq + 1];
                float v;
                v = sc[nt][0] * 0.125f; sc[nt][0] = ((c0     <= grow    ) ? v : -10000.f) + m0;
                v = sc[nt][1] * 0.125f; sc[nt][1] = ((c0 + 1 <= grow    ) ? v : -10000.f) + m1;
                v = sc[nt][2] * 0.125f; sc[nt][2] = ((c0     <= grow + 8) ? v : -10000.f) + m0;
                v = sc[nt][3] * 0.125f; sc[nt][3] = ((c0 + 1 <= grow + 8) ? v : -10000.f) + m1;
            }

            float mx0 = -1e30f, mx1 = -1e30f;
#pragma unroll
            for (int nt = 0; nt < 8; nt++) {
                mx0 = fmaxf(mx0, fmaxf(sc[nt][0], sc[nt][1]));
                mx1 = fmaxf(mx1, fmaxf(sc[nt][2], sc[nt][3]));
            }
            mx0 = fmaxf(mx0, __shfl_xor_sync(0xffffffffu, mx0, 1));
            mx0 = fmaxf(mx0, __shfl_xor_sync(0xffffffffu, mx0, 2));
            mx1 = fmaxf(mx1, __shfl_xor_sync(0xffffffffu, mx1, 1));
            mx1 = fmaxf(mx1, __shfl_xor_sync(0xffffffffu, mx1, 2));
            float mn0 = fmaxf(mrow0, mx0), mn1 = fmaxf(mrow1, mx1);
            float al0f = __expf(mrow0 - mn0), al1f = __expf(mrow1 - mn1);
            float s0 = 0.f, s1 = 0.f;
#pragma unroll
            for (int nt = 0; nt < 8; nt++) {
                sc[nt][0] = __expf(sc[nt][0] - mn0); s0 += sc[nt][0];
                sc[nt][1] = __expf(sc[nt][1] - mn0); s0 += sc[nt][1];
                sc[nt][2] = __expf(sc[nt][2] - mn1); s1 += sc[nt][2];
                sc[nt][3] = __expf(sc[nt][3] - mn1); s1 += sc[nt][3];
            }
            s0 += __shfl_xor_sync(0xffffffffu, s0, 1);
            s0 += __shfl_xor_sync(0xffffffffu, s0, 2);
            s1 += __shfl_xor_sync(0xffffffffu, s1, 1);
            s1 += __shfl_xor_sync(0xffffffffu, s1, 2);
            lrow0 = lrow0 * al0f + s0; mrow0 = mn0;
            lrow1 = lrow1 * al1f + s1; mrow1 = mn1;
#pragma unroll
            for (int nt = 0; nt < 8; nt++) {
                o[nt][0] *= al0f; o[nt][1] *= al0f;
                o[nt][2] *= al1f; o[nt][3] *= al1f;
            }

#pragma unroll
            for (int kc = 0; kc < 4; kc++) {
                uint32_t ph[4];
                ph[0] = pack_h2(sc[2*kc][0],   sc[2*kc][1]);
                ph[1] = pack_h2(sc[2*kc][2],   sc[2*kc][3]);
                ph[2] = pack_h2(sc[2*kc+1][0], sc[2*kc+1][1]);
                ph[3] = pack_h2(sc[2*kc+1][2], sc[2*kc+1][3]);
                const uint32_t vrow = kb + (uint32_t)(kc * 16 * AST) * 2;
#pragma unroll
                for (int p = 0; p < 4; p++) {
                    uint32_t v0r, v1r, v2r, v3r;
                    LDSM4T(v0r, v1r, v2r, v3r, uV + vrow + vfo[p]);
                    MMA_F16(o[2*p],   ph[0], ph[1], ph[2], ph[3], v0r, v1r);
                    MMA_F16(o[2*p+1], ph[0], ph[1], ph[2], ph[3], v2r, v3r);
                }
            }
            __syncthreads();
        }

        float i0 = 1.f / lrow0, i1 = 1.f / lrow1;
        size_t ob = (size_t)b * SXX * 2048 + (size_t)(qt * 64 + q0 + r) * 2048 + h * 64;
#pragma unroll
        for (int dn = 0; dn < 8; dn++) {
            *(uint32_t*)&cath[ob + dn * 8 + cq] = pack_h2(o[dn][0] * i0, o[dn][1] * i0);
            *(uint32_t*)&cath[ob + (size_t)8 * 2048 + dn * 8 + cq] = pack_h2(o[dn][2] * i1, o[dn][3] * i1);
        }
    } else {
        const int off = FULLN - lenx;
        size_t obase = (size_t)b * SXX * 2048 + (size_t)(qt * 64) * 2048 + 1024 + h * 64;
        if (qt * 64 >= lenx) {
            const uint4 z = {0, 0, 0, 0};
            for (int i = tid; i < 512; i += 128) {
                int rr = i >> 3, seg = i & 7;
                *(uint4*)&cath[obase + (size_t)rr * 2048 + seg * 8] = z;
            }
            return;
        }

        const size_t qgb = (size_t)b * SXX * QSTRIDE;
        for (int i = tid; i < 512; i += 128) {
            int rr = i >> 3, seg = i & 7;
            *(uint4*)&sQ[rr * AST + seg * 8] =
                *(const uint4*)&qkvh[qgb + (size_t)(qt * 64 + rr) * QSTRIDE + 3072 + h * 64 + seg * 8];
        }

        int qlast = qt * 64 + 63;
        if (qlast >= lenx) qlast = lenx - 1;
        int jmax = off + qlast + 1;
        if (jmax > leny) jmax = leny;
        const int ntile = (jmax + 63) >> 6;
        const size_t kgb = (size_t)b * SYY * 2048;

#define APREF_CROSS(t) do { \
        uint32_t kd_ = uK + (uint32_t)((t) & 1) * KVB; \
        uint32_t vd_ = uV + (uint32_t)((t) & 1) * KVB; \
        _Pragma("unroll") \
        for (int it_ = 0; it_ < 4; it_++) { \
            int i_ = tid + it_ * 128; \
            int rr_ = i_ >> 3, sg_ = i_ & 7; \
            size_t kr_ = kgb + (size_t)((t) * 64 + rr_) * 2048 + h * 64 + sg_ * 8; \
            uint32_t so_ = (uint32_t)(rr_ * AST + sg_ * 8) * 2; \
            CP_ASYNC16(kd_ + so_, kvh + kr_); \
            CP_ASYNC16(vd_ + so_, kvh + kr_ + 1024); \
        } \
    } while (0)

        APREF_CROSS(0);
        CP_COMMIT();

        for (int t = 0; t < ntile; t++) {
            if (t + 1 < ntile) { APREF_CROSS(t + 1); CP_COMMIT(); CP_WAIT1(); }
            else               { CP_WAIT0(); }
            __syncthreads();
            const uint32_t kb = (uint32_t)(t & 1) * KVB;

            float sc[8][4];
#pragma unroll
            for (int i = 0; i < 8; i++)
#pragma unroll
                for (int j = 0; j < 4; j++) sc[i][j] = 0.f;

#pragma unroll
            for (int kt = 0; kt < 4; kt++) {
                const uint32_t ko = (uint32_t)(kt << 5);
                uint32_t a0, a1, a2, a3;
                LDSM4(a0, a1, a2, a3, uQ + qfo + ko);
#pragma unroll
                for (int p = 0; p < 4; p++) {
                    uint32_t k0r, k1r, k2r, k3r;
                    LDSM4(k0r, k1r, k2r, k3r, uK + kb + kfo[p] + ko);
                    MMA_F16(sc[2*p],   a0, a1, a2, a3, k0r, k1r);
                    MMA_F16(sc[2*p+1], a0, a1, a2, a3, k2r, k3r);
                }
            }

            const int grow = off + qt * 64 + q0 + r;
#pragma unroll
            for (int nt = 0; nt < 8; nt++) {
                int c0 = t * 64 + nt * 8 + cq;
                sc[nt][0] = (c0     <= grow     && c0     < leny) ? sc[nt][0] * 0.125f : -1e30f;
                sc[nt][1] = (c0 + 1 <= grow     && c0 + 1 < leny) ? sc[nt][1] * 0.125f : -1e30f;
                sc[nt][2] = (c0     <= grow + 8 && c0     < leny) ? sc[nt][2] * 0.125f : -1e30f;
                sc[nt][3] = (c0 + 1 <= grow + 8 && c0 + 1 < leny) ? sc[nt][3] * 0.125f : -1e30f;
            }

            float mx0 = -1e30f, mx1 = -1e30f;
#pragma unroll
            for (int nt = 0; nt < 8; nt++) {
                mx0 = fmaxf(mx0, fmaxf(sc[nt][0], sc[nt][1]));
                mx1 = fmaxf(mx1, fmaxf(sc[nt][2], sc[nt][3]));
            }
            mx0 = fmaxf(mx0, __shfl_xor_sync(0xffffffffu, mx0, 1));
            mx0 = fmaxf(mx0, __shfl_xor_sync(0xffffffffu, mx0, 2));
            mx1 = fmaxf(mx1, __shfl_xor_sync(0xffffffffu, mx1, 1));
            mx1 = fmaxf(mx1, __shfl_xor_sync(0xffffffffu, mx1, 2));
            float mn0 = fmaxf(mrow0, mx0), mn1 = fmaxf(mrow1, mx1);
            float al0f = __expf(mrow0 - mn0), al1f = __expf(mrow1 - mn1);
            float s0 = 0.f, s1 = 0.f;
#pragma unroll
            for (int nt = 0; nt < 8; nt++) {
                sc[nt][0] = __expf(sc[nt][0] - mn0); s0 += sc[nt][0];
                sc[nt][1] = __expf(sc[nt][1] - mn0); s0 += sc[nt][1];
                sc[nt][2] = __expf(sc[nt][2] - mn1); s1 += sc[nt][2];
                sc[nt][3] = __expf(sc[nt][3] - mn1); s1 += sc[nt][3];
            }
            s0 += __shfl_xor_sync(0xffffffffu, s0, 1);
            s0 += __shfl_xor_sync(0xffffffffu, s0, 2);
            s1 += __shfl_xor_sync(0xffffffffu, s1, 1);
            s1 += __shfl_xor_sync(0xffffffffu, s1, 2);
            lrow0 = lrow0 * al0f + s0; mrow0 = mn0;
            lrow1 = lrow1 * al1f + s1; mrow1 = mn1;
#pragma unroll
            for (int nt = 0; nt < 8; nt++) {
                o[nt][0] *= al0f; o[nt][1] *= al0f;
                o[nt][2] *= al1f; o[nt][3] *= al1f;
            }

#pragma unroll
            for (int kc = 0; kc < 4; kc++) {
                uint32_t ph[4];
                ph[0] = pack_h2(sc[2*kc][0],   sc[2*kc][1]);
                ph[1] = pack_h2(sc[2*kc][2],   sc[2*kc][3]);
                ph[2] = pack_h2(sc[2*kc+1][0], sc[2*kc+1][1]);
                ph[3] = pack_h2(sc[2*kc+1][2], sc[2*kc+1][3]);
                const uint32_t vrow = kb + (uint32_t)(kc * 16 * AST) * 2;
#pragma unroll
                for (int p = 0; p < 4; p++) {
                    uint32_t v0r, v1r, v2r, v3r;
                    LDSM4T(v0r, v1r, v2r, v3r, uV + vrow + vfo[p]);
                    MMA_F16(o[2*p],   ph[0], ph[1], ph[2], ph[3], v0r, v1r);
                    MMA_F16(o[2*p+1], ph[0], ph[1], ph[2], ph[3], v2r, v3r);
                }
            }
            __syncthreads();
        }

        float i0 = 1.f / lrow0, i1 = 1.f / lrow1;
        int row0 = qt * 64 + q0 + r, row1 = row0 + 8;
        bool v0 = row0 < lenx, v1 = row1 < lenx;
        size_t ob = (size_t)b * SXX * 2048 + (size_t)row0 * 2048 + 1024 + h * 64;
#pragma unroll
        for (int dn = 0; dn < 8; dn++) {
            *(uint32_t*)&cath[ob + dn * 8 + cq] =
                v0 ? pack_h2(o[dn][0] * i0, o[dn][1] * i0) : 0u;
            *(uint32_t*)&cath[ob + (size_t)8 * 2048 + dn * 8 + cq] =
                v1 ? pack_h2(o[dn][2] * i1, o[dn][3] * i1) : 0u;
        }
    }
}

// ---------------- launch ----------------
extern "C" void kernel_launch(void* const* d_in, const int* in_sizes, int n_in,
                              void* d_out, int out_size)
{
    const float* x      = (const float*)d_in[0];
    const float* y      = (const float*)d_in[1];
    const float* maskx  = (const float*)d_in[2];
    const float* W_attn = (const float*)d_in[3];
    const float* b_attn = (const float*)d_in[4];
    const float* W_2a   = (const float*)d_in[5];
    const float* b_2a   = (const float*)d_in[6];
    const float* W_2b   = (const float*)d_in[7];
    const float* b_2b   = (const float*)d_in[8];
    const float* W_proj = (const float*)d_in[9];
    const float* b_proj = (const float*)d_in[10];
    const int*   xtb    = (const int*)d_in[11];
    const int*   ytb    = (const int*)d_in[15];

    unsigned short *xh, *xl, *yh, *yl;
    unsigned short *qkvh, *kv2h, *cath;
    unsigned short *wc, *wb, *wph;
    float* bias4k;
    cudaGetSymbolAddress((void**)&xh, g_xh);     cudaGetSymbolAddress((void**)&xl, g_xl);
    cudaGetSymbolAddress((void**)&yh, g_yh);     cudaGetSymbolAddress((void**)&yl, g_yl);
    cudaGetSymbolAddress((void**)&qkvh, g_qkvh);
    cudaGetSymbolAddress((void**)&kv2h, g_kv2h);
    cudaGetSymbolAddress((void**)&cath, g_cath);
    cudaGetSymbolAddress((void**)&wc, g_wc_h);
    cudaGetSymbolAddress((void**)&wb, g_w2b_h);
    cudaGetSymbolAddress((void**)&wph, g_wpj_h);
    cudaGetSymbolAddress((void**)&bias4k, g_bias4k);

    const int SMEM_GF = (4 * TSB + 2 * TSF) * 2;        // 73728 B
    const int SMEM_GP = 4 * TSB * 2;                    // 36864 B
    const int SMEM_ATTN = 5 * QB * 2 + 2 * 64 * 4;      // 46592 B
    cudaFuncSetAttribute((const void*)gemm_front, cudaFuncAttributeMaxDynamicSharedMemorySize, SMEM_GF);
    cudaFuncSetAttribute((const void*)gemm_proj,  cudaFuncAttributeMaxDynamicSharedMemorySize, SMEM_GP);
    cudaFuncSetAttribute((const void*)attn_fused, cudaFuncAttributeMaxDynamicSharedMemorySize, SMEM_ATTN);

    prep_all<<<12305, 256>>>(x, y, xh, xl, yh, yl,
                             W_attn, W_2a, W_2b, W_proj, wc, wb, wph,
                             xtb, in_sizes[11], ytb, in_sizes[15],
                             b_attn, b_2a, bias4k);

    gemm_front<<<1536, 256, SMEM_GF>>>(xh, xl, yh, yl, wc, wb, bias4k, b_2b, qkvh, kv2h);

    attn_fused<<<dim3(32, 16, 2), 128, SMEM_ATTN>>>(qkvh, kv2h, maskx, cath);

    gemm_proj<<<dim3(16, 32), 256, SMEM_GP>>>(cath, wph, b_proj, (float*)d_out, 2048, 1024, 2048);
}

// round 15
// speedup vs baseline: 1.9784x; 1.0198x over previous
#include <cuda_runtime.h>
#include <cuda_fp16.h>
#include <cstdint>

#define NB    2
#define SXX   1024
#define SYY   1024
#define DIM   1024
#define NH    16
#define HDIM  64
#define FULLN 1536

// ---------------- scratch (device globals) ----------------
__device__ int   g_lens[4];
__device__ float g_bias4k[4096];

__device__ unsigned short g_xh [2048 * 1024], g_xl [2048 * 1024];
__device__ unsigned short g_yh [2048 * 1024], g_yl [2048 * 1024];
// fused QKV|Q2 (hi only): cols 0-1023 Q, 1024-2047 K, 2048-3071 V, 3072-4095 Q2
__device__ unsigned short g_qkvh[2048 * 4096];
__device__ unsigned short g_kv2h[2048 * 2048];
__device__ unsigned short g_cath[2048 * 2048];
__device__ unsigned short g_wc_h [4096 * 1024];     // W_attn|W_2a [N,K]
__device__ unsigned short g_w2b_h[2048 * 1024];
__device__ unsigned short g_wpj_h[1024 * 2048];

// ---------------- helpers ----------------
__device__ __forceinline__ uint32_t smem_u32(const void* p) {
    uint32_t a;
    asm("{ .reg .u64 t; cvta.to.shared.u64 t, %1; cvt.u32.u64 %0, t; }" : "=r"(a) : "l"(p));
    return a;
}
#define CP_ASYNC16(dst, src) \
    asm volatile("cp.async.ca.shared.global [%0], [%1], 16;" :: "r"(dst), "l"(src) : "memory")
#define CP_COMMIT() asm volatile("cp.async.commit_group;" ::: "memory")
#define CP_WAIT1()  asm volatile("cp.async.wait_group 1;" ::: "memory")
#define CP_WAIT0()  asm volatile("cp.async.wait_group 0;" ::: "memory")

#define MMA_F16(c, a0, a1, a2, a3, b0, b1) \
    asm volatile("mma.sync.aligned.m16n8k16.row.col.f32.f16.f16.f32 " \
        "{%0,%1,%2,%3}, {%4,%5,%6,%7}, {%8,%9}, {%0,%1,%2,%3};" \
        : "+f"((c)[0]), "+f"((c)[1]), "+f"((c)[2]), "+f"((c)[3]) \
        : "r"(a0), "r"(a1), "r"(a2), "r"(a3), "r"(b0), "r"(b1))

#define LDSM4(r0, r1, r2, r3, a) \
    asm volatile("ldmatrix.sync.aligned.m8n8.x4.shared.b16 {%0,%1,%2,%3}, [%4];" \
        : "=r"(r0), "=r"(r1), "=r"(r2), "=r"(r3) : "r"(a))
#define LDSM4T(r0, r1, r2, r3, a) \
    asm volatile("ldmatrix.sync.aligned.m8n8.x4.trans.shared.b16 {%0,%1,%2,%3}, [%4];" \
        : "=r"(r0), "=r"(r1), "=r"(r2), "=r"(r3) : "r"(a))

__device__ __forceinline__ void split_pack_h(float a, float b, uint32_t& h, uint32_t& l) {
    __half ha = __float2half_rn(a), hb = __float2half_rn(b);
    __half la = __float2half_rn(a - __half2float(ha));
    __half lb = __float2half_rn(b - __half2float(hb));
    h = (uint32_t)*(unsigned short*)&ha | ((uint32_t)*(unsigned short*)&hb << 16);
    l = (uint32_t)*(unsigned short*)&la | ((uint32_t)*(unsigned short*)&lb << 16);
}
__device__ __forceinline__ uint32_t pack_h2(float a, float b) {
    __half2 v = __floats2half2_rn(a, b);
    return *(uint32_t*)&v;
}

// ---------------- ALL prep in one launch ----------------
__global__ __launch_bounds__(256)
void prep_all(const float* __restrict__ x, const float* __restrict__ y,
              unsigned short* __restrict__ xh, unsigned short* __restrict__ xl,
              unsigned short* __restrict__ yh, unsigned short* __restrict__ yl,
              const float* __restrict__ Wa, const float* __restrict__ W2a,
              const float* __restrict__ W2b, const float* __restrict__ Wp,
              unsigned short* __restrict__ wc, unsigned short* __restrict__ wb,
              unsigned short* __restrict__ wph,
              const int* __restrict__ xb, int nx, const int* __restrict__ yb, int ny,
              const float* __restrict__ ba, const float* __restrict__ b2a,
              float* __restrict__ bias4k)
{
    const int bid = blockIdx.x;
    if (bid < 4096) {
        const int N4 = 2048 * 1024 / 4;
        int i = bid * 256 + threadIdx.x;
        const float* in; unsigned short *oh, *ol;
        int j;
        if (i < N4) { in = x; oh = xh; ol = xl; j = i; }
        else        { in = y; oh = yh; ol = yl; j = i - N4; }
        float4 v = ((const float4*)in)[j];
        uint32_t h0, l0, h1, l1;
        split_pack_h(v.x, v.y, h0, l0);
        split_pack_h(v.z, v.w, h1, l1);
        ((uint2*)oh)[j] = make_uint2(h0, h1);
        ((uint2*)ol)[j] = make_uint2(l0, l1);
    } else if (bid < 12288) {
        int f = bid - 4096;
        const float* in; unsigned short* oh;
        int K, N, bx, by;
        if (f < 3072)      { in = Wa;  oh = wc;  K = 1024; N = 3072; bx = f % 96; by = f / 96; }
        else if (f < 4096) { in = W2a; oh = wc + (size_t)3072 * 1024; K = 1024; N = 1024; f -= 3072; bx = f % 32; by = f / 32; }
        else if (f < 6144) { in = W2b; oh = wb;  K = 1024; N = 2048; f -= 4096; bx = f % 64; by = f / 64; }
        else               { in = Wp;  oh = wph; K = 2048; N = 1024; f -= 6144; bx = f % 32; by = f / 32; }

        __shared__ float tile[32][33];
        int n0 = bx << 5, k0 = by << 5;
        int tx = threadIdx.x & 31, ty = threadIdx.x >> 5;
        for (int i = ty; i < 32; i += 8)
            tile[i][tx] = in[(size_t)(k0 + i) * N + n0 + tx];
        __syncthreads();
        for (int i = ty; i < 32; i += 8) {
            float v = tile[tx][i];
            __half h = __float2half_rn(v);
            oh[(size_t)(n0 + i) * K + k0 + tx] = *(unsigned short*)&h;
        }
    } else if (bid < 12304) {
        int i = (bid - 12288) * 256 + threadIdx.x;
        bias4k[i] = (i < 3072) ? ba[i] : b2a[i - 3072];
    } else {
        __shared__ int cnt[4];
        int t = threadIdx.x;
        if (t < 4) cnt[t] = 0;
        __syncthreads();
        for (int i = t; i < nx; i += blockDim.x) atomicAdd(&cnt[xb[i]], 1);
        for (int i = t; i < ny; i += blockDim.x) atomicAdd(&cnt[2 + yb[i]], 1);
        __syncthreads();
        if (t < 4) g_lens[t] = cnt[t];
    }
}

// ---------------- front GEMMs: 64x128 tile, K-chunk 64, 3 CTAs/SM ----------------
#define TSF (128 * 72)
#define TSB (64 * 72)

template<bool USEAL>
__device__ __forceinline__ void front_loop(
    const unsigned short* __restrict__ Ah, const unsigned short* __restrict__ Al,
    const unsigned short* __restrict__ Bh,
    int bm, int bn, int tid,
    uint32_t uA, uint32_t uAl, uint32_t uB,
    const uint32_t* aoff, const uint32_t* boff,
    float acc[2][4][4])
{
    const int K = 1024;
    const int nchunk = K >> 6;

#define PREFETCH_FL(t) do { \
        uint32_t sa_ = (uint32_t)((t) & 1) * (TSB * 2); \
        uint32_t sb_ = (uint32_t)((t) & 1) * (TSF * 2); \
        int k0_  = (t) << 6; \
        _Pragma("unroll") \
        for (int it_ = 0; it_ < 2; it_++) { \
            int i_ = tid + it_ * 256; \
            int row_ = i_ >> 3, sg_ = i_ & 7; \
            uint32_t so_ = sa_ + (uint32_t)(row_ * 72 + sg_ * 8) * 2; \
            size_t ao_ = (size_t)(bm + row_) * K + k0_ + sg_ * 8; \
            CP_ASYNC16(uA + so_, Ah + ao_); \
            if (USEAL) CP_ASYNC16(uAl + so_, Al + ao_); \
        } \
        _Pragma("unroll") \
        for (int it_ = 0; it_ < 4; it_++) { \
            int i_ = tid + it_ * 256; \
            int row_ = i_ >> 3, sg_ = i_ & 7; \
            uint32_t so_ = sb_ + (uint32_t)(row_ * 72 + sg_ * 8) * 2; \
            CP_ASYNC16(uB + so_, Bh + (size_t)(bn + row_) * K + k0_ + sg_ * 8); \
        } \
    } while (0)

    PREFETCH_FL(0);
    CP_COMMIT();

    for (int t = 0; t < nchunk; t++) {
        if (t + 1 < nchunk) { PREFETCH_FL(t + 1); CP_COMMIT(); CP_WAIT1(); }
        else                { CP_WAIT0(); }
        __syncthreads();
        const uint32_t sa = (uint32_t)(t & 1) * (TSB * 2);
        const uint32_t sb = (uint32_t)(t & 1) * (TSF * 2);
#pragma unroll
        for (int kt = 0; kt < 4; kt++) {
            const uint32_t ko = (uint32_t)(kt << 5);
            uint32_t bh[2][4];
#pragma unroll
            for (int p = 0; p < 2; p++)
                LDSM4(bh[p][0], bh[p][1], bh[p][2], bh[p][3], uB + sb + ko + boff[p]);
#pragma unroll
            for (int mi = 0; mi < 2; mi++) {
                uint32_t a0, a1, a2, a3;
                LDSM4(a0, a1, a2, a3, uA + sa + ko + aoff[mi]);
#pragma unroll
                for (int p = 0; p < 2; p++) {
                    MMA_F16(acc[mi][2*p],   a0, a1, a2, a3, bh[p][0], bh[p][1]);
                    MMA_F16(acc[mi][2*p+1], a0, a1, a2, a3, bh[p][2], bh[p][3]);
                }
                if (USEAL) {
                    uint32_t l0, l1, l2, l3;
                    LDSM4(l0, l1, l2, l3, uAl + sa + ko + aoff[mi]);
#pragma unroll
                    for (int p = 0; p < 2; p++) {
                        MMA_F16(acc[mi][2*p],   l0, l1, l2, l3, bh[p][0], bh[p][1]);
                        MMA_F16(acc[mi][2*p+1], l0, l1, l2, l3, bh[p][2], bh[p][3]);
                    }
                }
            }
        }
        __syncthreads();
    }
#undef PREFETCH_FL
}

__global__ __launch_bounds__(256, 3)
void gemm_front(const unsigned short* __restrict__ xh, const unsigned short* __restrict__ xl,
                const unsigned short* __restrict__ yh, const unsigned short* __restrict__ yl,
                const unsigned short* __restrict__ wc, const unsigned short* __restrict__ wb,
                const float* __restrict__ bias4k, const float* __restrict__ b2b,
                unsigned short* __restrict__ qkvh, unsigned short* __restrict__ kv2h)
{
    extern __shared__ unsigned short sm16[];
    unsigned short* sA  = sm16;
    unsigned short* sAl = sm16 + 2 * TSB;
    unsigned short* sB  = sm16 + 4 * TSB;
    const uint32_t uA = smem_u32(sA), uAl = smem_u32(sAl), uB = smem_u32(sB);

    const int bid = blockIdx.x;
    const unsigned short *Ah, *Al, *Bh;
    const float* bias;
    unsigned short* Ch;
    int bm, bn, N;
    bool useAl;
    if (bid < 1024) {
        bm = (bid >> 5) << 6; bn = (bid & 31) << 7; N = 4096;
        Ah = xh; Al = xl; Bh = wc; bias = bias4k; Ch = qkvh;
        useAl = (bn >= 2048) && (bn < 3072);
    } else {
        int i = bid - 1024;
        bm = (i >> 4) << 6; bn = (i & 15) << 7; N = 2048;
        Ah = yh; Al = yl; Bh = wb; bias = b2b; Ch = kv2h;
        useAl = (bn >= 1024);
    }

    const int tid  = threadIdx.x;
    const int lane = tid & 31, wid = tid >> 5;
    const int wm = (wid >> 2) << 5;
    const int wn = (wid & 3) << 5;

    float acc[2][4][4];
#pragma unroll
    for (int i = 0; i < 2; i++)
#pragma unroll
        for (int j = 0; j < 4; j++)
#pragma unroll
            for (int k = 0; k < 4; k++) acc[i][j][k] = 0.f;

    const int l8 = lane & 7, g = lane >> 3;
    uint32_t aoff[2], boff[2];
#pragma unroll
    for (int mi = 0; mi < 2; mi++)
        aoff[mi] = (uint32_t)((wm + (mi << 4) + ((g & 1) << 3) + l8) * 72 + ((g >> 1) << 3)) * 2;
#pragma unroll
    for (int p = 0; p < 2; p++)
        boff[p] = (uint32_t)((wn + (p << 4) + ((g >> 1) << 3) + l8) * 72 + ((g & 1) << 3)) * 2;

    if (useAl) front_loop<true >(Ah, Al, Bh, bm, bn, tid, uA, uAl, uB, aoff, boff, acc);
    else       front_loop<false>(Ah, Al, Bh, bm, bn, tid, uA, uAl, uB, aoff, boff, acc);

    const int fr = lane >> 2;
    const int fc = (lane & 3) << 1;
#pragma unroll
    for (int mi = 0; mi < 2; mi++) {
        int row = bm + wm + (mi << 4) + fr;
#pragma unroll
        for (int ni = 0; ni < 4; ni++) {
            int col = bn + wn + (ni << 3) + fc;
            float bx = bias[col], by = bias[col + 1];
            *(uint32_t*)&Ch[(size_t)row * N + col] =
                pack_h2(acc[mi][ni][0] + bx, acc[mi][ni][1] + by);
            *(uint32_t*)&Ch[(size_t)(row + 8) * N + col] =
                pack_h2(acc[mi][ni][2] + bx, acc[mi][ni][3] + by);
        }
    }
}

// ---------------- proj GEMM: 128x64 tile, K-chunk 64, single product, 3 CTAs/SM ----------------
__global__ __launch_bounds__(256, 3)
void gemm_proj(const unsigned short* __restrict__ Ah,
               const unsigned short* __restrict__ Bh,
               const float* __restrict__ bias, float* __restrict__ Cf,
               int M, int N, int K)
{
    extern __shared__ unsigned short sm16[];
    unsigned short* sAh = sm16;                 // [2][TSF]
    unsigned short* sBh = sm16 + 2 * TSF;       // [2][TSB]
    const uint32_t uAh = smem_u32(sAh), uBh = smem_u32(sBh);

    const int tid  = threadIdx.x;
    const int lane = tid & 31, wid = tid >> 5;
    const int wm = (wid >> 2) << 6;
    const int wn = (wid & 3) << 4;
    const int bm = blockIdx.y << 7, bn = blockIdx.x << 6;

    float acc[4][2][4];
#pragma unroll
    for (int i = 0; i < 4; i++)
#pragma unroll
        for (int j = 0; j < 2; j++)
#pragma unroll
            for (int k = 0; k < 4; k++) acc[i][j][k] = 0.f;

    const int nchunk = K >> 6;   // 32

#define PREFETCH_P(t) do { \
        int k0_ = (t) << 6; \
        uint32_t sa_ = (uint32_t)((t) & 1) * (TSF * 2); \
        uint32_t sb_ = (uint32_t)((t) & 1) * (TSB * 2); \
        _Pragma("unroll") \
        for (int it_ = 0; it_ < 4; it_++) { \
            int i_ = tid + it_ * 256; \
            int row_ = i_ >> 3, sg_ = i_ & 7; \
            uint32_t so_ = sa_ + (uint32_t)(row_ * 72 + sg_ * 8) * 2; \
            CP_ASYNC16(uAh + so_, Ah + (size_t)(bm + row_) * K + k0_ + sg_ * 8); \
        } \
        _Pragma("unroll") \
        for (int it_ = 0; it_ < 2; it_++) { \
            int i_ = tid + it_ * 256; \
            int row_ = i_ >> 3, sg_ = i_ & 7; \
            uint32_t so_ = sb_ + (uint32_t)(row_ * 72 + sg_ * 8) * 2; \
            CP_ASYNC16(uBh + so_, Bh + (size_t)(bn + row_) * K + k0_ + sg_ * 8); \
        } \
    } while (0)

    PREFETCH_P(0);
    CP_COMMIT();

    const int l8 = lane & 7, g = lane >> 3;
    uint32_t aoff[4], boff;
#pragma unroll
    for (int mi = 0; mi < 4; mi++)
        aoff[mi] = (uint32_t)((wm + (mi << 4) + ((g & 1) << 3) + l8) * 72 + ((g >> 1) << 3)) * 2;
    boff = (uint32_t)((wn + ((g >> 1) << 3) + l8) * 72 + ((g & 1) << 3)) * 2;

    const int fr = lane >> 2;
    const int fc = (lane & 3) << 1;

    for (int t = 0; t < nchunk; t++) {
        if (t + 1 < nchunk) { PREFETCH_P(t + 1); CP_COMMIT(); CP_WAIT1(); }
        else                { CP_WAIT0(); }
        __syncthreads();
        const uint32_t sa = (uint32_t)(t & 1) * (TSF * 2);
        const uint32_t sb = (uint32_t)(t & 1) * (TSB * 2);
#pragma unroll
        for (int kt = 0; kt < 4; kt++) {
            const uint32_t ko = (uint32_t)(kt << 5);
            uint32_t bh0, bh1, bh2, bh3;
            LDSM4(bh0, bh1, bh2, bh3, uBh + sb + ko + boff);
#pragma unroll
            for (int mi = 0; mi < 4; mi++) {
                uint32_t a0, a1, a2, a3;
                LDSM4(a0, a1, a2, a3, uAh + sa + ko + aoff[mi]);
                MMA_F16(acc[mi][0], a0, a1, a2, a3, bh0, bh1);
                MMA_F16(acc[mi][1], a0, a1, a2, a3, bh2, bh3);
            }
        }
        __syncthreads();
    }

#pragma unroll
    for (int mi = 0; mi < 4; mi++) {
        int row = bm + wm + (mi << 4) + fr;
#pragma unroll
        for (int ni = 0; ni < 2; ni++) {
            int col = bn + wn + (ni << 3) + fc;
            float bx = bias[col], by = bias[col + 1];
            float2 v0 = { acc[mi][ni][0] + bx, acc[mi][ni][1] + by };
            float2 v1 = { acc[mi][ni][2] + bx, acc[mi][ni][3] + by };
            *(float2*)(Cf + (size_t)row * N + col)       = v0;
            *(float2*)(Cf + (size_t)(row + 8) * N + col) = v1;
        }
    }
}

// ================= fused MMA flash attention (single-fp16 Q and P) =================
#define AST 72
#define QB  (64 * AST)
#define KVB (QB * 2)
#define QSTRIDE 4096

__global__ __launch_bounds__(128)
void attn_fused(const unsigned short* __restrict__ qkvh,
                const unsigned short* __restrict__ kvh,
                const float* __restrict__ mask,
                unsigned short* __restrict__ cath)
{
    extern __shared__ char smraw[];
    unsigned short* sQ  = (unsigned short*)smraw;
    unsigned short* sK  = sQ + QB;
    unsigned short* sV  = sK + 2 * QB;
    float* sMsf = (float*)(sV + 2 * QB);
    const uint32_t uQ = smem_u32(sQ);
    const uint32_t uK = smem_u32(sK), uV = smem_u32(sV);
    const uint32_t uMs = smem_u32(sMsf);

    const int bx = blockIdx.x;
    const bool is_self = bx < 16;
    const int qt = is_self ? (15 - bx) : (31 - bx);
    const int h = blockIdx.y, b = blockIdx.z;
    const int tid = threadIdx.x, lane = tid & 31, wid = tid >> 5;
    const int q0 = wid << 4;
    const int r = lane >> 2, cq = (lane & 3) << 1;
    const int l8 = lane & 7, g = lane >> 3;

    const int lenx = g_lens[b], leny = g_lens[2 + b];

    uint32_t qfo = (uint32_t)((q0 + ((g & 1) << 3) + l8) * AST + ((g >> 1) << 3)) * 2;
    uint32_t kfo[4], vfo[4];
#pragma unroll
    for (int p = 0; p < 4; p++) {
        kfo[p] = (uint32_t)(((p << 4) + ((g >> 1) << 3) + l8) * AST + ((g & 1) << 3)) * 2;
        vfo[p] = (uint32_t)((((g & 1) << 3) + l8) * AST + (((p << 1) + (g >> 1)) << 3)) * 2;
    }

    float o[8][4];
#pragma unroll
    for (int i = 0; i < 8; i++)
#pragma unroll
        for (int j = 0; j < 4; j++) o[i][j] = 0.f;
    float mrow0 = -1e30f, mrow1 = -1e30f, lrow0 = 0.f, lrow1 = 0.f;

    if (is_self) {
        const size_t gb = (size_t)b * SXX * QSTRIDE;
        for (int i = tid; i < 512; i += 128) {
            int rr = i >> 3, seg = i & 7;
            *(uint4*)&sQ[rr * AST + seg * 8] =
                *(const uint4*)&qkvh[gb + (size_t)(qt * 64 + rr) * QSTRIDE + h * 64 + seg * 8];
        }

        const float* maskb = mask + b * SXX;
        int nt1 = qt + 1, nt2 = (lenx + 63) >> 6;
        const int ntile = nt1 < nt2 ? nt1 : nt2;

#define APREF_SELF(t) do { \
        uint32_t kd_ = uK + (uint32_t)((t) & 1) * KVB; \
        uint32_t vd_ = uV + (uint32_t)((t) & 1) * KVB; \
        _Pragma("unroll") \
        for (int it_ = 0; it_ < 4; it_++) { \
            int i_ = tid + it_ * 128; \
            int rr_ = i_ >> 3, sg_ = i_ & 7; \
            size_t kr_ = gb + (size_t)((t) * 64 + rr_) * QSTRIDE + 1024 + h * 64 + sg_ * 8; \
            uint32_t so_ = (uint32_t)(rr_ * AST + sg_ * 8) * 2; \
            CP_ASYNC16(kd_ + so_, qkvh + kr_); \
            CP_ASYNC16(vd_ + so_, qkvh + kr_ + 1024); \
        } \
        if (tid < 16) CP_ASYNC16(uMs + ((t) & 1) * 256 + tid * 16, maskb + (t) * 64 + tid * 4); \
    } while (0)

        APREF_SELF(0);
        CP_COMMIT();

        for (int t = 0; t < ntile; t++) {
            if (t + 1 < ntile) { APREF_SELF(t + 1); CP_COMMIT(); CP_WAIT1(); }
            else               { CP_WAIT0(); }
            __syncthreads();
            const uint32_t kb = (uint32_t)(t & 1) * KVB;
            const int mb = (t & 1) * 64;

            float sc[8][4];
#pragma unroll
            for (int i = 0; i < 8; i++)
#pragma unroll
                for (int j = 0; j < 4; j++) sc[i][j] = 0.f;

#pragma unroll
            for (int kt = 0; kt < 4; kt++) {
                const uint32_t ko = (uint32_t)(kt << 5);
                uint32_t a0, a1, a2, a3;
                LDSM4(a0, a1, a2, a3, uQ + qfo + ko);
#pragma unroll
                for (int p = 0; p < 4; p++) {
                    uint32_t k0r, k1r, k2r, k3r;
                    LDSM4(k0r, k1r, k2r, k3r, uK + kb + kfo[p] + ko);
                    MMA_F16(sc[2*p],   a0, a1, a2, a3, k0r, k1r);
                    MMA_F16(sc[2*p+1], a0, a1, a2, a3, k2r, k3r);
                }
            }

            const int grow = qt * 64 + q0 + r;
#pragma unroll
            for (int nt = 0; nt < 8; nt++) {
                int c0 = t * 64 + nt * 8 + cq;
                float m0 = sMsf[mb + nt * 8 + cq], m1 = sMsf[mb + nt * 8 + cq + 1];
                float v;
                v = sc[nt][0] * 0.125f; sc[nt][0] = ((c0     <= grow    ) ? v : -10000.f) + m0;
                v = sc[nt][1] * 0.125f; sc[nt][1] = ((c0 + 1 <= grow    ) ? v : -10000.f) + m1;
                v = sc[nt][2] * 0.125f; sc[nt][2] = ((c0     <= grow + 8) ? v : -10000.f) + m0;
                v = sc[nt][3] * 0.125f; sc[nt][3] = ((c0 + 1 <= grow + 8) ? v : -10000.f) + m1;
            }

            float mx0 = -1e30f, mx1 = -1e30f;
#pragma unroll
            for (int nt = 0; nt < 8; nt++) {
                mx0 = fmaxf(mx0, fmaxf(sc[nt][0], sc[nt][1]));
                mx1 = fmaxf(mx1, fmaxf(sc[nt][2], sc[nt][3]));
            }
            mx0 = fmaxf(mx0, __shfl_xor_sync(0xffffffffu, mx0, 1));
            mx0 = fmaxf(mx0, __shfl_xor_sync(0xffffffffu, mx0, 2));
            mx1 = fmaxf(mx1, __shfl_xor_sync(0xffffffffu, mx1, 1));
            mx1 = fmaxf(mx1, __shfl_xor_sync(0xffffffffu, mx1, 2));
            float mn0 = fmaxf(mrow0, mx0), mn1 = fmaxf(mrow1, mx1);
            float al0f = __expf(mrow0 - mn0), al1f = __expf(mrow1 - mn1);
            float s0 = 0.f, s1 = 0.f;
#pragma unroll
            for (int nt = 0; nt < 8; nt++) {
                sc[nt][0] = __expf(sc[nt][0] - mn0); s0 += sc[nt][0];
                sc[nt][1] = __expf(sc[nt][1] - mn0); s0 += sc[nt][1];
                sc[nt][2] = __expf(sc[nt][2] - mn1); s1 += sc[nt][2];
                sc[nt][3] = __expf(sc[nt][3] - mn1); s1 += sc[nt][3];
            }
            s0 += __shfl_xor_sync(0xffffffffu, s0, 1);
            s0 += __shfl_xor_sync(0xffffffffu, s0, 2);
            s1 += __shfl_xor_sync(0xffffffffu, s1, 1);
            s1 += __shfl_xor_sync(0xffffffffu, s1, 2);
            lrow0 = lrow0 * al0f + s0; mrow0 = mn0;
            lrow1 = lrow1 * al1f + s1; mrow1 = mn1;
#pragma unroll
            for (int nt = 0; nt < 8; nt++) {
                o[nt][0] *= al0f; o[nt][1] *= al0f;
                o[nt][2] *= al1f; o[nt][3] *= al1f;
            }

#pragma unroll
            for (int kc = 0; kc < 4; kc++) {
                uint32_t ph[4];
                ph[0] = pack_h2(sc[2*kc][0],   sc[2*kc][1]);
                ph[1] = pack_h2(sc[2*kc][2],   sc[2*kc][3]);
                ph[2] = pack_h2(sc[2*kc+1][0], sc[2*kc+1][1]);
                ph[3] = pack_h2(sc[2*kc+1][2], sc[2*kc+1][3]);
                const uint32_t vrow = kb + (uint32_t)(kc * 16 * AST) * 2;
#pragma unroll
                for (int p = 0; p < 4; p++) {
                    uint32_t v0r, v1r, v2r, v3r;
                    LDSM4T(v0r, v1r, v2r, v3r, uV + vrow + vfo[p]);
                    MMA_F16(o[2*p],   ph[0], ph[1], ph[2], ph[3], v0r, v1r);
                    MMA_F16(o[2*p+1], ph[0], ph[1], ph[2], ph[3], v2r, v3r);
                }
            }
            __syncthreads();
        }

        float i0 = 1.f / lrow0, i1 = 1.f / lrow1;
        size_t ob = (size_t)b * SXX * 2048 + (size_t)(qt * 64 + q0 + r) * 2048 + h * 64;
#pragma unroll
        for (int dn = 0; dn < 8; dn++) {
            *(uint32_t*)&cath[ob + dn * 8 + cq] = pack_h2(o[dn][0] * i0, o[dn][1] * i0);
            *(uint32_t*)&cath[ob + (size_t)8 * 2048 + dn * 8 + cq] = pack_h2(o[dn][2] * i1, o[dn][3] * i1);
        }
    } else {
        const int off = FULLN - lenx;
        size_t obase = (size_t)b * SXX * 2048 + (size_t)(qt * 64) * 2048 + 1024 + h * 64;
        if (qt * 64 >= lenx) {
            const uint4 z = {0, 0, 0, 0};
            for (int i = tid; i < 512; i += 128) {
                int rr = i >> 3, seg = i & 7;
                *(uint4*)&cath[obase + (size_t)rr * 2048 + seg * 8] = z;
            }
            return;
        }

        const size_t qgb = (size_t)b * SXX * QSTRIDE;
        for (int i = tid; i < 512; i += 128) {
            int rr = i >> 3, seg = i & 7;
            *(uint4*)&sQ[rr * AST + seg * 8] =
                *(const uint4*)&qkvh[qgb + (size_t)(qt * 64 + rr) * QSTRIDE + 3072 + h * 64 + seg * 8];
        }

        int qlast = qt * 64 + 63;
        if (qlast >= lenx) qlast = lenx - 1;
        int jmax = off + qlast + 1;
        if (jmax > leny) jmax = leny;
        const int ntile = (jmax + 63) >> 6;
        const size_t kgb = (size_t)b * SYY * 2048;

#define APREF_CROSS(t) do { \
        uint32_t kd_ = uK + (uint32_t)((t) & 1) * KVB; \
        uint32_t vd_ = uV + (uint32_t)((t) & 1) * KVB; \
        _Pragma("unroll") \
        for (int it_ = 0; it_ < 4; it_++) { \
            int i_ = tid + it_ * 128; \
            int rr_ = i_ >> 3, sg_ = i_ & 7; \
            size_t kr_ = kgb + (size_t)((t) * 64 + rr_) * 2048 + h * 64 + sg_ * 8; \
            uint32_t so_ = (uint32_t)(rr_ * AST + sg_ * 8) * 2; \
            CP_ASYNC16(kd_ + so_, kvh + kr_); \
            CP_ASYNC16(vd_ + so_, kvh + kr_ + 1024); \
        } \
    } while (0)

        APREF_CROSS(0);
        CP_COMMIT();

        for (int t = 0; t < ntile; t++) {
            if (t + 1 < ntile) { APREF_CROSS(t + 1); CP_COMMIT(); CP_WAIT1(); }
            else               { CP_WAIT0(); }
            __syncthreads();
            const uint32_t kb = (uint32_t)(t & 1) * KVB;

            float sc[8][4];
#pragma unroll
            for (int i = 0; i < 8; i++)
#pragma unroll
                for (int j = 0; j < 4; j++) sc[i][j] = 0.f;

#pragma unroll
            for (int kt = 0; kt < 4; kt++) {
                const uint32_t ko = (uint32_t)(kt << 5);
                uint32_t a0, a1, a2, a3;
                LDSM4(a0, a1, a2, a3, uQ + qfo + ko);
#pragma unroll
                for (int p = 0; p < 4; p++) {
                    uint32_t k0r, k1r, k2r, k3r;
                    LDSM4(k0r, k1r, k2r, k3r, uK + kb + kfo[p] + ko);
                    MMA_F16(sc[2*p],   a0, a1, a2, a3, k0r, k1r);
                    MMA_F16(sc[2*p+1], a0, a1, a2, a3, k2r, k3r);
                }
            }

            const int grow = off + qt * 64 + q0 + r;
#pragma unroll
            for (int nt = 0; nt < 8; nt++) {
                int c0 = t * 64 + nt * 8 + cq;
                sc[nt][0] = (c0     <= grow     && c0     < leny) ? sc[nt][0] * 0.125f : -1e30f;
                sc[nt][1] = (c0 + 1 <= grow     && c0 + 1 < leny) ? sc[nt][1] * 0.125f : -1e30f;
                sc[nt][2] = (c0     <= grow + 8 && c0     < leny) ? sc[nt][2] * 0.125f : -1e30f;
                sc[nt][3] = (c0 + 1 <= grow + 8 && c0 + 1 < leny) ? sc[nt][3] * 0.125f : -1e30f;
            }

            float mx0 = -1e30f, mx1 = -1e30f;
#pragma unroll
            for (int nt = 0; nt < 8; nt++) {
                mx0 = fmaxf(mx0, fmaxf(sc[nt][0], sc[nt][1]));
                mx1 = fmaxf(mx1, fmaxf(sc[nt][2], sc[nt][3]));
            }
            mx0 = fmaxf(mx0, __shfl_xor_sync(0xffffffffu, mx0, 1));
            mx0 = fmaxf(mx0, __shfl_xor_sync(0xffffffffu, mx0, 2));
            mx1 = fmaxf(mx1, __shfl_xor_sync(0xffffffffu, mx1, 1));
            mx1 = fmaxf(mx1, __shfl_xor_sync(0xffffffffu, mx1, 2));
            float mn0 = fmaxf(mrow0, mx0), mn1 = fmaxf(mrow1, mx1);
            float al0f = __expf(mrow0 - mn0), al1f = __expf(mrow1 - mn1);
            float s0 = 0.f, s1 = 0.f;
#pragma unroll
            for (int nt = 0; nt < 8; nt++) {
                sc[nt][0] = __expf(sc[nt][0] - mn0); s0 += sc[nt][0];
                sc[nt][1] = __expf(sc[nt][1] - mn0); s0 += sc[nt][1];
                sc[nt][2] = __expf(sc[nt][2] - mn1); s1 += sc[nt][2];
                sc[nt][3] = __expf(sc[nt][3] - mn1); s1 += sc[nt][3];
            }
            s0 += __shfl_xor_sync(0xffffffffu, s0, 1);
            s0 += __shfl_xor_sync(0xffffffffu, s0, 2);
            s1 += __shfl_xor_sync(0xffffffffu, s1, 1);
            s1 += __shfl_xor_sync(0xffffffffu, s1, 2);
            lrow0 = lrow0 * al0f + s0; mrow0 = mn0;
            lrow1 = lrow1 * al1f + s1; mrow1 = mn1;
#pragma unroll
            for (int nt = 0; nt < 8; nt++) {
                o[nt][0] *= al0f; o[nt][1] *= al0f;
                o[nt][2] *= al1f; o[nt][3] *= al1f;
            }

#pragma unroll
            for (int kc = 0; kc < 4; kc++) {
                uint32_t ph[4];
                ph[0] = pack_h2(sc[2*kc][0],   sc[2*kc][1]);
                ph[1] = pack_h2(sc[2*kc][2],   sc[2*kc][3]);
                ph[2] = pack_h2(sc[2*kc+1][0], sc[2*kc+1][1]);
                ph[3] = pack_h2(sc[2*kc+1][2], sc[2*kc+1][3]);
                const uint32_t vrow = kb + (uint32_t)(kc * 16 * AST) * 2;
#pragma unroll
                for (int p = 0; p < 4; p++) {
                    uint32_t v0r, v1r, v2r, v3r;
                    LDSM4T(v0r, v1r, v2r, v3r, uV + vrow + vfo[p]);
                    MMA_F16(o[2*p],   ph[0], ph[1], ph[2], ph[3], v0r, v1r);
                    MMA_F16(o[2*p+1], ph[0], ph[1], ph[2], ph[3], v2r, v3r);
                }
            }
            __syncthreads();
        }

        float i0 = 1.f / lrow0, i1 = 1.f / lrow1;
        int row0 = qt * 64 + q0 + r, row1 = row0 + 8;
        bool v0 = row0 < lenx, v1 = row1 < lenx;
        size_t ob = (size_t)b * SXX * 2048 + (size_t)row0 * 2048 + 1024 + h * 64;
#pragma unroll
        for (int dn = 0; dn < 8; dn++) {
            *(uint32_t*)&cath[ob + dn * 8 + cq] =
                v0 ? pack_h2(o[dn][0] * i0, o[dn][1] * i0) : 0u;
            *(uint32_t*)&cath[ob + (size_t)8 * 2048 + dn * 8 + cq] =
                v1 ? pack_h2(o[dn][2] * i1, o[dn][3] * i1) : 0u;
        }
    }
}

// ---------------- launch ----------------
extern "C" void kernel_launch(void* const* d_in, const int* in_sizes, int n_in,
                              void* d_out, int out_size)
{
    const float* x      = (const float*)d_in[0];
    const float* y      = (const float*)d_in[1];
    const float* maskx  = (const float*)d_in[2];
    const float* W_attn = (const float*)d_in[3];
    const float* b_attn = (const float*)d_in[4];
    const float* W_2a   = (const float*)d_in[5];
    const float* b_2a   = (const float*)d_in[6];
    const float* W_2b   = (const float*)d_in[7];
    const float* b_2b   = (const float*)d_in[8];
    const float* W_proj = (const float*)d_in[9];
    const float* b_proj = (const float*)d_in[10];
    const int*   xtb    = (const int*)d_in[11];
    const int*   ytb    = (const int*)d_in[15];

    unsigned short *xh, *xl, *yh, *yl;
    unsigned short *qkvh, *kv2h, *cath;
    unsigned short *wc, *wb, *wph;
    float* bias4k;
    cudaGetSymbolAddress((void**)&xh, g_xh);     cudaGetSymbolAddress((void**)&xl, g_xl);
    cudaGetSymbolAddress((void**)&yh, g_yh);     cudaGetSymbolAddress((void**)&yl, g_yl);
    cudaGetSymbolAddress((void**)&qkvh, g_qkvh);
    cudaGetSymbolAddress((void**)&kv2h, g_kv2h);
    cudaGetSymbolAddress((void**)&cath, g_cath);
    cudaGetSymbolAddress((void**)&wc, g_wc_h);
    cudaGetSymbolAddress((void**)&wb, g_w2b_h);
    cudaGetSymbolAddress((void**)&wph, g_wpj_h);
    cudaGetSymbolAddress((void**)&bias4k, g_bias4k);

    const int SMEM_GF = (4 * TSB + 2 * TSF) * 2;        // 73728 B
    const int SMEM_GP = (2 * TSF + 2 * TSB) * 2;        // 55296 B
    const int SMEM_ATTN = 5 * QB * 2 + 2 * 64 * 4;      // 46592 B
    cudaFuncSetAttribute((const void*)gemm_front, cudaFuncAttributeMaxDynamicSharedMemorySize, SMEM_GF);
    cudaFuncSetAttribute((const void*)gemm_proj,  cudaFuncAttributeMaxDynamicSharedMemorySize, SMEM_GP);
    cudaFuncSetAttribute((const void*)attn_fused, cudaFuncAttributeMaxDynamicSharedMemorySize, SMEM_ATTN);

    prep_all<<<12305, 256>>>(x, y, xh, xl, yh, yl,
                             W_attn, W_2a, W_2b, W_proj, wc, wb, wph,
                             xtb, in_sizes[11], ytb, in_sizes[15],
                             b_attn, b_2a, bias4k);

    gemm_front<<<1536, 256, SMEM_GF>>>(xh, xl, yh, yl, wc, wb, bias4k, b_2b, qkvh, kv2h);

    attn_fused<<<dim3(32, 16, 2), 128, SMEM_ATTN>>>(qkvh, kv2h, maskx, cath);

    gemm_proj<<<dim3(16, 16), 256, SMEM_GP>>>(cath, wph, b_proj, (float*)d_out, 2048, 1024, 2048);
}

// round 16
// speedup vs baseline: 2.0189x; 1.0205x over previous
#include <cuda_runtime.h>
#include <cuda_fp16.h>
#include <cstdint>

#define NB    2
#define SXX   1024
#define SYY   1024
#define DIM   1024
#define NH    16
#define HDIM  64
#define FULLN 1536

// ---------------- scratch (device globals) ----------------
__device__ int   g_lens[4];
__device__ float g_bias4k[4096];

__device__ unsigned short g_xh [2048 * 1024], g_xl [2048 * 1024];
__device__ unsigned short g_yh [2048 * 1024], g_yl [2048 * 1024];
__device__ unsigned short g_qkvh[2048 * 4096];
__device__ unsigned short g_kv2h[2048 * 2048];
__device__ unsigned short g_cath[2048 * 2048];
__device__ unsigned short g_wc_h [4096 * 1024];
__device__ unsigned short g_w2b_h[2048 * 1024];
__device__ unsigned short g_wpj_h[1024 * 2048];
__device__ float g_pp[2 * 2048 * 1024];             // proj split-K partials

// ---------------- helpers ----------------
__device__ __forceinline__ uint32_t smem_u32(const void* p) {
    uint32_t a;
    asm("{ .reg .u64 t; cvta.to.shared.u64 t, %1; cvt.u32.u64 %0, t; }" : "=r"(a) : "l"(p));
    return a;
}
#define CP_ASYNC16(dst, src) \
    asm volatile("cp.async.ca.shared.global [%0], [%1], 16;" :: "r"(dst), "l"(src) : "memory")
#define CP_COMMIT() asm volatile("cp.async.commit_group;" ::: "memory")
#define CP_WAIT0()  asm volatile("cp.async.wait_group 0;" ::: "memory")

#define MMA_F16(c, a0, a1, a2, a3, b0, b1) \
    asm volatile("mma.sync.aligned.m16n8k16.row.col.f32.f16.f16.f32 " \
        "{%0,%1,%2,%3}, {%4,%5,%6,%7}, {%8,%9}, {%0,%1,%2,%3};" \
        : "+f"((c)[0]), "+f"((c)[1]), "+f"((c)[2]), "+f"((c)[3]) \
        : "r"(a0), "r"(a1), "r"(a2), "r"(a3), "r"(b0), "r"(b1))

#define LDSM4(r0, r1, r2, r3, a) \
    asm volatile("ldmatrix.sync.aligned.m8n8.x4.shared.b16 {%0,%1,%2,%3}, [%4];" \
        : "=r"(r0), "=r"(r1), "=r"(r2), "=r"(r3) : "r"(a))
#define LDSM4T(r0, r1, r2, r3, a) \
    asm volatile("ldmatrix.sync.aligned.m8n8.x4.trans.shared.b16 {%0,%1,%2,%3}, [%4];" \
        : "=r"(r0), "=r"(r1), "=r"(r2), "=r"(r3) : "r"(a))

__device__ __forceinline__ void split_pack_h(float a, float b, uint32_t& h, uint32_t& l) {
    __half ha = __float2half_rn(a), hb = __float2half_rn(b);
    __half la = __float2half_rn(a - __half2float(ha));
    __half lb = __float2half_rn(b - __half2float(hb));
    h = (uint32_t)*(unsigned short*)&ha | ((uint32_t)*(unsigned short*)&hb << 16);
    l = (uint32_t)*(unsigned short*)&la | ((uint32_t)*(unsigned short*)&lb << 16);
}
__device__ __forceinline__ uint32_t pack_h2(float a, float b) {
    __half2 v = __floats2half2_rn(a, b);
    return *(uint32_t*)&v;
}

// ---------------- ALL prep in one launch ----------------
__global__ __launch_bounds__(256)
void prep_all(const float* __restrict__ x, const float* __restrict__ y,
              unsigned short* __restrict__ xh, unsigned short* __restrict__ xl,
              unsigned short* __restrict__ yh, unsigned short* __restrict__ yl,
              const float* __restrict__ Wa, const float* __restrict__ W2a,
              const float* __restrict__ W2b, const float* __restrict__ Wp,
              unsigned short* __restrict__ wc, unsigned short* __restrict__ wb,
              unsigned short* __restrict__ wph,
              const int* __restrict__ xb, int nx, const int* __restrict__ yb, int ny,
              const float* __restrict__ ba, const float* __restrict__ b2a,
              float* __restrict__ bias4k)
{
    const int bid = blockIdx.x;
    if (bid < 4096) {
        const int N4 = 2048 * 1024 / 4;
        int i = bid * 256 + threadIdx.x;
        const float* in; unsigned short *oh, *ol;
        int j;
        if (i < N4) { in = x; oh = xh; ol = xl; j = i; }
        else        { in = y; oh = yh; ol = yl; j = i - N4; }
        float4 v = ((const float4*)in)[j];
        uint32_t h0, l0, h1, l1;
        split_pack_h(v.x, v.y, h0, l0);
        split_pack_h(v.z, v.w, h1, l1);
        ((uint2*)oh)[j] = make_uint2(h0, h1);
        ((uint2*)ol)[j] = make_uint2(l0, l1);
    } else if (bid < 12288) {
        int f = bid - 4096;
        const float* in; unsigned short* oh;
        int K, N, bx, by;
        if (f < 3072)      { in = Wa;  oh = wc;  K = 1024; N = 3072; bx = f % 96; by = f / 96; }
        else if (f < 4096) { in = W2a; oh = wc + (size_t)3072 * 1024; K = 1024; N = 1024; f -= 3072; bx = f % 32; by = f / 32; }
        else if (f < 6144) { in = W2b; oh = wb;  K = 1024; N = 2048; f -= 4096; bx = f % 64; by = f / 64; }
        else               { in = Wp;  oh = wph; K = 2048; N = 1024; f -= 6144; bx = f % 32; by = f / 32; }

        __shared__ float tile[32][33];
        int n0 = bx << 5, k0 = by << 5;
        int tx = threadIdx.x & 31, ty = threadIdx.x >> 5;
        for (int i = ty; i < 32; i += 8)
            tile[i][tx] = in[(size_t)(k0 + i) * N + n0 + tx];
        __syncthreads();
        for (int i = ty; i < 32; i += 8) {
            float v = tile[tx][i];
            __half h = __float2half_rn(v);
            oh[(size_t)(n0 + i) * K + k0 + tx] = *(unsigned short*)&h;
        }
    } else if (bid < 12304) {
        int i = (bid - 12288) * 256 + threadIdx.x;
        bias4k[i] = (i < 3072) ? ba[i] : b2a[i - 3072];
    } else {
        __shared__ int cnt[4];
        int t = threadIdx.x;
        if (t < 4) cnt[t] = 0;
        __syncthreads();
        for (int i = t; i < nx; i += blockDim.x) atomicAdd(&cnt[xb[i]], 1);
        for (int i = t; i < ny; i += blockDim.x) atomicAdd(&cnt[2 + yb[i]], 1);
        __syncthreads();
        if (t < 4) g_lens[t] = cnt[t];
    }
}

// ---------------- front GEMMs: 64x128 tile, K-chunk 64, single-sync pipeline ----------------
#define TSF (128 * 72)
#define TSB (64 * 72)

template<bool USEAL>
__device__ __forceinline__ void front_loop(
    const unsigned short* __restrict__ Ah, const unsigned short* __restrict__ Al,
    const unsigned short* __restrict__ Bh,
    int bm, int bn, int tid,
    uint32_t uA, uint32_t uAl, uint32_t uB,
    const uint32_t* aoff, const uint32_t* boff,
    float acc[2][4][4])
{
    const int K = 1024;
    const int nchunk = K >> 6;

#define PREFETCH_FL(t) do { \
        uint32_t sa_ = (uint32_t)((t) & 1) * (TSB * 2); \
        uint32_t sb_ = (uint32_t)((t) & 1) * (TSF * 2); \
        int k0_  = (t) << 6; \
        _Pragma("unroll") \
        for (int it_ = 0; it_ < 2; it_++) { \
            int i_ = tid + it_ * 256; \
            int row_ = i_ >> 3, sg_ = i_ & 7; \
            uint32_t so_ = sa_ + (uint32_t)(row_ * 72 + sg_ * 8) * 2; \
            size_t ao_ = (size_t)(bm + row_) * K + k0_ + sg_ * 8; \
            CP_ASYNC16(uA + so_, Ah + ao_); \
            if (USEAL) CP_ASYNC16(uAl + so_, Al + ao_); \
        } \
        _Pragma("unroll") \
        for (int it_ = 0; it_ < 4; it_++) { \
            int i_ = tid + it_ * 256; \
            int row_ = i_ >> 3, sg_ = i_ & 7; \
            uint32_t so_ = sb_ + (uint32_t)(row_ * 72 + sg_ * 8) * 2; \
            CP_ASYNC16(uB + so_, Bh + (size_t)(bn + row_) * K + k0_ + sg_ * 8); \
        } \
    } while (0)

    PREFETCH_FL(0);
    CP_COMMIT();

    for (int t = 0; t < nchunk; t++) {
        CP_WAIT0();
        __syncthreads();
        if (t + 1 < nchunk) { PREFETCH_FL(t + 1); CP_COMMIT(); }
        const uint32_t sa = (uint32_t)(t & 1) * (TSB * 2);
        const uint32_t sb = (uint32_t)(t & 1) * (TSF * 2);
#pragma unroll
        for (int kt = 0; kt < 4; kt++) {
            const uint32_t ko = (uint32_t)(kt << 5);
            uint32_t bh[2][4];
#pragma unroll
            for (int p = 0; p < 2; p++)
                LDSM4(bh[p][0], bh[p][1], bh[p][2], bh[p][3], uB + sb + ko + boff[p]);
#pragma unroll
            for (int mi = 0; mi < 2; mi++) {
                uint32_t a0, a1, a2, a3;
                LDSM4(a0, a1, a2, a3, uA + sa + ko + aoff[mi]);
#pragma unroll
                for (int p = 0; p < 2; p++) {
                    MMA_F16(acc[mi][2*p],   a0, a1, a2, a3, bh[p][0], bh[p][1]);
                    MMA_F16(acc[mi][2*p+1], a0, a1, a2, a3, bh[p][2], bh[p][3]);
                }
                if (USEAL) {
                    uint32_t l0, l1, l2, l3;
                    LDSM4(l0, l1, l2, l3, uAl + sa + ko + aoff[mi]);
#pragma unroll
                    for (int p = 0; p < 2; p++) {
                        MMA_F16(acc[mi][2*p],   l0, l1, l2, l3, bh[p][0], bh[p][1]);
                        MMA_F16(acc[mi][2*p+1], l0, l1, l2, l3, bh[p][2], bh[p][3]);
                    }
                }
            }
        }
    }
#undef PREFETCH_FL
}

__global__ __launch_bounds__(256, 3)
void gemm_front(const unsigned short* __restrict__ xh, const unsigned short* __restrict__ xl,
                const unsigned short* __restrict__ yh, const unsigned short* __restrict__ yl,
                const unsigned short* __restrict__ wc, const unsigned short* __restrict__ wb,
                const float* __restrict__ bias4k, const float* __restrict__ b2b,
                unsigned short* __restrict__ qkvh, unsigned short* __restrict__ kv2h)
{
    extern __shared__ unsigned short sm16[];
    unsigned short* sA  = sm16;
    unsigned short* sAl = sm16 + 2 * TSB;
    unsigned short* sB  = sm16 + 4 * TSB;
    const uint32_t uA = smem_u32(sA), uAl = smem_u32(sAl), uB = smem_u32(sB);

    // --- long-CTAs-first remap: [0,256)=qkv-V, [256,512)=kv2-V2, then shorts ---
    const int bid = blockIdx.x;
    int obid;
    if (bid < 256) {
        int m = bid >> 3, nb = 16 + (bid & 7);
        obid = m * 32 + nb;
    } else if (bid < 512) {
        int i = bid - 256; int m = i >> 3, nb = 8 + (i & 7);
        obid = 1024 + m * 16 + nb;
    } else if (bid < 1280) {
        int i = bid - 512; int m = i / 24; int nbi = i % 24;
        int nb = nbi < 16 ? nbi : nbi + 8;
        obid = m * 32 + nb;
    } else {
        int i = bid - 1280; int m = i >> 3, nb = i & 7;
        obid = 1024 + m * 16 + nb;
    }

    const unsigned short *Ah, *Al, *Bh;
    const float* bias;
    unsigned short* Ch;
    int bm, bn, N;
    bool useAl;
    if (obid < 1024) {
        bm = (obid >> 5) << 6; bn = (obid & 31) << 7; N = 4096;
        Ah = xh; Al = xl; Bh = wc; bias = bias4k; Ch = qkvh;
        useAl = (bn >= 2048) && (bn < 3072);
    } else {
        int i = obid - 1024;
        bm = (i >> 4) << 6; bn = (i & 15) << 7; N = 2048;
        Ah = yh; Al = yl; Bh = wb; bias = b2b; Ch = kv2h;
        useAl = (bn >= 1024);
    }

    const int tid  = threadIdx.x;
    const int lane = tid & 31, wid = tid >> 5;
    const int wm = (wid >> 2) << 5;
    const int wn = (wid & 3) << 5;

    float acc[2][4][4];
#pragma unroll
    for (int i = 0; i < 2; i++)
#pragma unroll
        for (int j = 0; j < 4; j++)
#pragma unroll
            for (int k = 0; k < 4; k++) acc[i][j][k] = 0.f;

    const int l8 = lane & 7, g = lane >> 3;
    uint32_t aoff[2], boff[2];
#pragma unroll
    for (int mi = 0; mi < 2; mi++)
        aoff[mi] = (uint32_t)((wm + (mi << 4) + ((g & 1) << 3) + l8) * 72 + ((g >> 1) << 3)) * 2;
#pragma unroll
    for (int p = 0; p < 2; p++)
        boff[p] = (uint32_t)((wn + (p << 4) + ((g >> 1) << 3) + l8) * 72 + ((g & 1) << 3)) * 2;

    if (useAl) front_loop<true >(Ah, Al, Bh, bm, bn, tid, uA, uAl, uB, aoff, boff, acc);
    else       front_loop<false>(Ah, Al, Bh, bm, bn, tid, uA, uAl, uB, aoff, boff, acc);

    const int fr = lane >> 2;
    const int fc = (lane & 3) << 1;
#pragma unroll
    for (int mi = 0; mi < 2; mi++) {
        int row = bm + wm + (mi << 4) + fr;
#pragma unroll
        for (int ni = 0; ni < 4; ni++) {
            int col = bn + wn + (ni << 3) + fc;
            float bx = bias[col], by = bias[col + 1];
            *(uint32_t*)&Ch[(size_t)row * N + col] =
                pack_h2(acc[mi][ni][0] + bx, acc[mi][ni][1] + by);
            *(uint32_t*)&Ch[(size_t)(row + 8) * N + col] =
                pack_h2(acc[mi][ni][2] + bx, acc[mi][ni][3] + by);
        }
    }
}

// ---------------- proj GEMM: 128x64 tile, split-K=2, partials out ----------------
__global__ __launch_bounds__(256, 3)
void gemm_proj(const unsigned short* __restrict__ Ah,
               const unsigned short* __restrict__ Bh,
               float* __restrict__ Pf)
{
    extern __shared__ unsigned short sm16[];
    unsigned short* sAh = sm16;                 // [2][TSF]
    unsigned short* sBh = sm16 + 2 * TSF;       // [2][TSB]
    const uint32_t uAh = smem_u32(sAh), uBh = smem_u32(sBh);

    const int tid  = threadIdx.x;
    const int lane = tid & 31, wid = tid >> 5;
    const int wm = (wid >> 2) << 6;
    const int wn = (wid & 3) << 4;
    const int bm = blockIdx.y << 7, bn = blockIdx.x << 6;
    const int kz = blockIdx.z;
    const int kbase = kz << 10;
    const int K = 2048, N = 1024;
    float* P = Pf + (size_t)kz * 2048 * 1024;

    float acc[4][2][4];
#pragma unroll
    for (int i = 0; i < 4; i++)
#pragma unroll
        for (int j = 0; j < 2; j++)
#pragma unroll
            for (int k = 0; k < 4; k++) acc[i][j][k] = 0.f;

    const int nchunk = 16;

#define PREFETCH_P(t) do { \
        int k0_ = kbase + ((t) << 6); \
        uint32_t sa_ = (uint32_t)((t) & 1) * (TSF * 2); \
        uint32_t sb_ = (uint32_t)((t) & 1) * (TSB * 2); \
        _Pragma("unroll") \
        for (int it_ = 0; it_ < 4; it_++) { \
            int i_ = tid + it_ * 256; \
            int row_ = i_ >> 3, sg_ = i_ & 7; \
            uint32_t so_ = sa_ + (uint32_t)(row_ * 72 + sg_ * 8) * 2; \
            CP_ASYNC16(uAh + so_, Ah + (size_t)(bm + row_) * K + k0_ + sg_ * 8); \
        } \
        _Pragma("unroll") \
        for (int it_ = 0; it_ < 2; it_++) { \
            int i_ = tid + it_ * 256; \
            int row_ = i_ >> 3, sg_ = i_ & 7; \
            uint32_t so_ = sb_ + (uint32_t)(row_ * 72 + sg_ * 8) * 2; \
            CP_ASYNC16(uBh + so_, Bh + (size_t)(bn + row_) * K + k0_ + sg_ * 8); \
        } \
    } while (0)

    PREFETCH_P(0);
    CP_COMMIT();

    const int l8 = lane & 7, g = lane >> 3;
    uint32_t aoff[4], boff;
#pragma unroll
    for (int mi = 0; mi < 4; mi++)
        aoff[mi] = (uint32_t)((wm + (mi << 4) + ((g & 1) << 3) + l8) * 72 + ((g >> 1) << 3)) * 2;
    boff = (uint32_t)((wn + ((g >> 1) << 3) + l8) * 72 + ((g & 1) << 3)) * 2;

    const int fr = lane >> 2;
    const int fc = (lane & 3) << 1;

    for (int t = 0; t < nchunk; t++) {
        CP_WAIT0();
        __syncthreads();
        if (t + 1 < nchunk) { PREFETCH_P(t + 1); CP_COMMIT(); }
        const uint32_t sa = (uint32_t)(t & 1) * (TSF * 2);
        const uint32_t sb = (uint32_t)(t & 1) * (TSB * 2);
#pragma unroll
        for (int kt = 0; kt < 4; kt++) {
            const uint32_t ko = (uint32_t)(kt << 5);
            uint32_t bh0, bh1, bh2, bh3;
            LDSM4(bh0, bh1, bh2, bh3, uBh + sb + ko + boff);
#pragma unroll
            for (int mi = 0; mi < 4; mi++) {
                uint32_t a0, a1, a2, a3;
                LDSM4(a0, a1, a2, a3, uAh + sa + ko + aoff[mi]);
                MMA_F16(acc[mi][0], a0, a1, a2, a3, bh0, bh1);
                MMA_F16(acc[mi][1], a0, a1, a2, a3, bh2, bh3);
            }
        }
    }

#pragma unroll
    for (int mi = 0; mi < 4; mi++) {
        int row = bm + wm + (mi << 4) + fr;
#pragma unroll
        for (int ni = 0; ni < 2; ni++) {
            int col = bn + wn + (ni << 3) + fc;
            float2 v0 = { acc[mi][ni][0], acc[mi][ni][1] };
            float2 v1 = { acc[mi][ni][2], acc[mi][ni][3] };
            *(float2*)(P + (size_t)row * N + col)       = v0;
            *(float2*)(P + (size_t)(row + 8) * N + col) = v1;
        }
    }
}

// ---------------- reduce partials + bias -> out ----------------
__global__ __launch_bounds__(256)
void reduce_out(const float* __restrict__ Pf, const float* __restrict__ bias,
                float* __restrict__ out)
{
    int i = blockIdx.x * 256 + threadIdx.x;
    float4 a = ((const float4*)Pf)[i];
    float4 b = ((const float4*)(Pf + (size_t)2048 * 1024))[i];
    int col = (i << 2) & 1023;
    float4 o;
    o.x = a.x + b.x + bias[col + 0];
    o.y = a.y + b.y + bias[col + 1];
    o.z = a.z + b.z + bias[col + 2];
    o.w = a.w + b.w + bias[col + 3];
    ((float4*)out)[i] = o;
}

// ================= fused MMA flash attention (single-fp16 Q and P) =================
#define AST 72
#define QB  (64 * AST)
#define KVB (QB * 2)
#define QSTRIDE 4096

__global__ __launch_bounds__(128)
void attn_fused(const unsigned short* __restrict__ qkvh,
                const unsigned short* __restrict__ kvh,
                const float* __restrict__ mask,
                unsigned short* __restrict__ cath)
{
    extern __shared__ char smraw[];
    unsigned short* sQ  = (unsigned short*)smraw;
    unsigned short* sK  = sQ + QB;
    unsigned short* sV  = sK + 2 * QB;
    float* sMsf = (float*)(sV + 2 * QB);
    const uint32_t uQ = smem_u32(sQ);
    const uint32_t uK = smem_u32(sK), uV = smem_u32(sV);
    const uint32_t uMs = smem_u32(sMsf);

    const int bx = blockIdx.x;
    const bool is_self = bx < 16;
    const int qt = is_self ? (15 - bx) : (31 - bx);
    const int h = blockIdx.y, b = blockIdx.z;
    const int tid = threadIdx.x, lane = tid & 31, wid = tid >> 5;
    const int q0 = wid << 4;
    const int r = lane >> 2, cq = (lane & 3) << 1;
    const int l8 = lane & 7, g = lane >> 3;

    const int lenx = g_lens[b], leny = g_lens[2 + b];

    uint32_t qfo = (uint32_t)((q0 + ((g & 1) << 3) + l8) * AST + ((g >> 1) << 3)) * 2;
    uint32_t kfo[4], vfo[4];
#pragma unroll
    for (int p = 0; p < 4; p++) {
        kfo[p] = (uint32_t)(((p << 4) + ((g >> 1) << 3) + l8) * AST + ((g & 1) << 3)) * 2;
        vfo[p] = (uint32_t)((((g & 1) << 3) + l8) * AST + (((p << 1) + (g >> 1)) << 3)) * 2;
    }

    float o[8][4];
#pragma unroll
    for (int i = 0; i < 8; i++)
#pragma unroll
        for (int j = 0; j < 4; j++) o[i][j] = 0.f;
    float mrow0 = -1e30f, mrow1 = -1e30f, lrow0 = 0.f, lrow1 = 0.f;

    if (is_self) {
        const size_t gb = (size_t)b * SXX * QSTRIDE;
        for (int i = tid; i < 512; i += 128) {
            int rr = i >> 3, seg = i & 7;
            *(uint4*)&sQ[rr * AST + seg * 8] =
                *(const uint4*)&qkvh[gb + (size_t)(qt * 64 + rr) * QSTRIDE + h * 64 + seg * 8];
        }

        const float* maskb = mask + b * SXX;
        int nt1 = qt + 1, nt2 = (lenx + 63) >> 6;
        const int ntile = nt1 < nt2 ? nt1 : nt2;

#define APREF_SELF(t) do { \
        uint32_t kd_ = uK + (uint32_t)((t) & 1) * KVB; \
        uint32_t vd_ = uV + (uint32_t)((t) & 1) * KVB; \
        _Pragma("unroll") \
        for (int it_ = 0; it_ < 4; it_++) { \
            int i_ = tid + it_ * 128; \
            int rr_ = i_ >> 3, sg_ = i_ & 7; \
            size_t kr_ = gb + (size_t)((t) * 64 + rr_) * QSTRIDE + 1024 + h * 64 + sg_ * 8; \
            uint32_t so_ = (uint32_t)(rr_ * AST + sg_ * 8) * 2; \
            CP_ASYNC16(kd_ + so_, qkvh + kr_); \
            CP_ASYNC16(vd_ + so_, qkvh + kr_ + 1024); \
        } \
        if (tid < 16) CP_ASYNC16(uMs + ((t) & 1) * 256 + tid * 16, maskb + (t) * 64 + tid * 4); \
    } while (0)

        APREF_SELF(0);
        CP_COMMIT();

        for (int t = 0; t < ntile; t++) {
            CP_WAIT0();
            __syncthreads();
            if (t + 1 < ntile) { APREF_SELF(t + 1); CP_COMMIT(); }
            const uint32_t kb = (uint32_t)(t & 1) * KVB;
            const int mb = (t & 1) * 64;

            float sc[8][4];
#pragma unroll
            for (int i = 0; i < 8; i++)
#pragma unroll
                for (int j = 0; j < 4; j++) sc[i][j] = 0.f;

#pragma unroll
            for (int kt = 0; kt < 4; kt++) {
                const uint32_t ko = (uint32_t)(kt << 5);
                uint32_t a0, a1, a2, a3;
                LDSM4(a0, a1, a2, a3, uQ + qfo + ko);
#pragma unroll
                for (int p = 0; p < 4; p++) {
                    uint32_t k0r, k1r, k2r, k3r;
                    LDSM4(k0r, k1r, k2r, k3r, uK + kb + kfo[p] + ko);
                    MMA_F16(sc[2*p],   a0, a1, a2, a3, k0r, k1r);
                    MMA_F16(sc[2*p+1], a0, a1, a2, a3, k2r, k3r);
                }
            }

            const int grow = qt * 64 + q0 + r;
#pragma unroll
            for (int nt = 0; nt < 8; nt++) {
                int c0 = t * 64 + nt * 8 + cq;
                float m0 = sMsf[mb + nt * 8 + cq], m1 = sMsf[mb + nt * 8 + cq + 1];
                float v;
                v = sc[nt][0] * 0.125f; sc[nt][0] = ((c0     <= grow    ) ? v : -10000.f) + m0;
                v = sc[nt][1] * 0.125f; sc[nt][1] = ((c0 + 1 <= grow    ) ? v : -10000.f) + m1;
                v = sc[nt][2] * 0.125f; sc[nt][2] = ((c0     <= grow + 8) ? v : -10000.f) + m0;
                v = sc[nt][3] * 0.125f; sc[nt][3] = ((c0 + 1 <= grow + 8) ? v : -10000.f) + m1;
            }

            float mx0 = -1e30f, mx1 = -1e30f;
#pragma unroll
            for (int nt = 0; nt < 8; nt++) {
                mx0 = fmaxf(mx0, fmaxf(sc[nt][0], sc[nt][1]));
                mx1 = fmaxf(mx1, fmaxf(sc[nt][2], sc[nt][3]));
            }
            mx0 = fmaxf(mx0, __shfl_xor_sync(0xffffffffu, mx0, 1));
            mx0 = fmaxf(mx0, __shfl_xor_sync(0xffffffffu, mx0, 2));
            mx1 = fmaxf(mx1, __shfl_xor_sync(0xffffffffu, mx1, 1));
            mx1 = fmaxf(mx1, __shfl_xor_sync(0xffffffffu, mx1, 2));
            float mn0 = fmaxf(mrow0, mx0), mn1 = fmaxf(mrow1, mx1);
            float al0f = __expf(mrow0 - mn0), al1f = __expf(mrow1 - mn1);
            float s0 = 0.f, s1 = 0.f;
#pragma unroll
            for (int nt = 0; nt < 8; nt++) {
                sc[nt][0] = __expf(sc[nt][0] - mn0); s0 += sc[nt][0];
                sc[nt][1] = __expf(sc[nt][1] - mn0); s0 += sc[nt][1];
                sc[nt][2] = __expf(sc[nt][2] - mn1); s1 += sc[nt][2];
                sc[nt][3] = __expf(sc[nt][3] - mn1); s1 += sc[nt][3];
            }
            s0 += __shfl_xor_sync(0xffffffffu, s0, 1);
            s0 += __shfl_xor_sync(0xffffffffu, s0, 2);
            s1 += __shfl_xor_sync(0xffffffffu, s1, 1);
            s1 += __shfl_xor_sync(0xffffffffu, s1, 2);
            lrow0 = lrow0 * al0f + s0; mrow0 = mn0;
            lrow1 = lrow1 * al1f + s1; mrow1 = mn1;
#pragma unroll
            for (int nt = 0; nt < 8; nt++) {
                o[nt][0] *= al0f; o[nt][1] *= al0f;
                o[nt][2] *= al1f; o[nt][3] *= al1f;
            }

#pragma unroll
            for (int kc = 0; kc < 4; kc++) {
                uint32_t ph[4];
                ph[0] = pack_h2(sc[2*kc][0],   sc[2*kc][1]);
                ph[1] = pack_h2(sc[2*kc][2],   sc[2*kc][3]);
                ph[2] = pack_h2(sc[2*kc+1][0], sc[2*kc+1][1]);
                ph[3] = pack_h2(sc[2*kc+1][2], sc[2*kc+1][3]);
                const uint32_t vrow = kb + (uint32_t)(kc * 16 * AST) * 2;
#pragma unroll
                for (int p = 0; p < 4; p++) {
                    uint32_t v0r, v1r, v2r, v3r;
                    LDSM4T(v0r, v1r, v2r, v3r, uV + vrow + vfo[p]);
                    MMA_F16(o[2*p],   ph[0], ph[1], ph[2], ph[3], v0r, v1r);
                    MMA_F16(o[2*p+1], ph[0], ph[1], ph[2], ph[3], v2r, v3r);
                }
            }
        }

        float i0 = 1.f / lrow0, i1 = 1.f / lrow1;
        size_t ob = (size_t)b * SXX * 2048 + (size_t)(qt * 64 + q0 + r) * 2048 + h * 64;
#pragma unroll
        for (int dn = 0; dn < 8; dn++) {
            *(uint32_t*)&cath[ob + dn * 8 + cq] = pack_h2(o[dn][0] * i0, o[dn][1] * i0);
            *(uint32_t*)&cath[ob + (size_t)8 * 2048 + dn * 8 + cq] = pack_h2(o[dn][2] * i1, o[dn][3] * i1);
        }
    } else {
        const int off = FULLN - lenx;
        size_t obase = (size_t)b * SXX * 2048 + (size_t)(qt * 64) * 2048 + 1024 + h * 64;
        if (qt * 64 >= lenx) {
            const uint4 z = {0, 0, 0, 0};
            for (int i = tid; i < 512; i += 128) {
                int rr = i >> 3, seg = i & 7;
                *(uint4*)&cath[obase + (size_t)rr * 2048 + seg * 8] = z;
            }
            return;
        }

        const size_t qgb = (size_t)b * SXX * QSTRIDE;
        for (int i = tid; i < 512; i += 128) {
            int rr = i >> 3, seg = i & 7;
            *(uint4*)&sQ[rr * AST + seg * 8] =
                *(const uint4*)&qkvh[qgb + (size_t)(qt * 64 + rr) * QSTRIDE + 3072 + h * 64 + seg * 8];
        }

        int qlast = qt * 64 + 63;
        if (qlast >= lenx) qlast = lenx - 1;
        int jmax = off + qlast + 1;
        if (jmax > leny) jmax = leny;
        const int ntile = (jmax + 63) >> 6;
        const size_t kgb = (size_t)b * SYY * 2048;

#define APREF_CROSS(t) do { \
        uint32_t kd_ = uK + (uint32_t)((t) & 1) * KVB; \
        uint32_t vd_ = uV + (uint32_t)((t) & 1) * KVB; \
        _Pragma("unroll") \
        for (int it_ = 0; it_ < 4; it_++) { \
            int i_ = tid + it_ * 128; \
            int rr_ = i_ >> 3, sg_ = i_ & 7; \
            size_t kr_ = kgb + (size_t)((t) * 64 + rr_) * 2048 + h * 64 + sg_ * 8; \
            uint32_t so_ = (uint32_t)(rr_ * AST + sg_ * 8) * 2; \
            CP_ASYNC16(kd_ + so_, kvh + kr_); \
            CP_ASYNC16(vd_ + so_, kvh + kr_ + 1024); \
        } \
    } while (0)

        APREF_CROSS(0);
        CP_COMMIT();

        for (int t = 0; t < ntile; t++) {
            CP_WAIT0();
            __syncthreads();
            if (t + 1 < ntile) { APREF_CROSS(t + 1); CP_COMMIT(); }
            const uint32_t kb = (uint32_t)(t & 1) * KVB;

            float sc[8][4];
#pragma unroll
            for (int i = 0; i < 8; i++)
#pragma unroll
                for (int j = 0; j < 4; j++) sc[i][j] = 0.f;

#pragma unroll
            for (int kt = 0; kt < 4; kt++) {
                const uint32_t ko = (uint32_t)(kt << 5);
                uint32_t a0, a1, a2, a3;
                LDSM4(a0, a1, a2, a3, uQ + qfo + ko);
#pragma unroll
                for (int p = 0; p < 4; p++) {
                    uint32_t k0r, k1r, k2r, k3r;
                    LDSM4(k0r, k1r, k2r, k3r, uK + kb + kfo[p] + ko);
                    MMA_F16(sc[2*p],   a0, a1, a2, a3, k0r, k1r);
                    MMA_F16(sc[2*p+1], a0, a1, a2, a3, k2r, k3r);
                }
            }

            const int grow = off + qt * 64 + q0 + r;
#pragma unroll
            for (int nt = 0; nt < 8; nt++) {
                int c0 = t * 64 + nt * 8 + cq;
                sc[nt][0] = (c0     <= grow     && c0     < leny) ? sc[nt][0] * 0.125f : -1e30f;
                sc[nt][1] = (c0 + 1 <= grow     && c0 + 1 < leny) ? sc[nt][1] * 0.125f : -1e30f;
                sc[nt][2] = (c0     <= grow + 8 && c0     < leny) ? sc[nt][2] * 0.125f : -1e30f;
                sc[nt][3] = (c0 + 1 <= grow + 8 && c0 + 1 < leny) ? sc[nt][3] * 0.125f : -1e30f;
            }

            float mx0 = -1e30f, mx1 = -1e30f;
#pragma unroll
            for (int nt = 0; nt < 8; nt++) {
                mx0 = fmaxf(mx0, fmaxf(sc[nt][0], sc[nt][1]));
                mx1 = fmaxf(mx1, fmaxf(sc[nt][2], sc[nt][3]));
            }
            mx0 = fmaxf(mx0, __shfl_xor_sync(0xffffffffu, mx0, 1));
            mx0 = fmaxf(mx0, __shfl_xor_sync(0xffffffffu, mx0, 2));
            mx1 = fmaxf(mx1, __shfl_xor_sync(0xffffffffu, mx1, 1));
            mx1 = fmaxf(mx1, __shfl_xor_sync(0xffffffffu, mx1, 2));
            float mn0 = fmaxf(mrow0, mx0), mn1 = fmaxf(mrow1, mx1);
            float al0f = __expf(mrow0 - mn0), al1f = __expf(mrow1 - mn1);
            float s0 = 0.f, s1 = 0.f;
#pragma unroll
            for (int nt = 0; nt < 8; nt++) {
                sc[nt][0] = __expf(sc[nt][0] - mn0); s0 += sc[nt][0];
                sc[nt][1] = __expf(sc[nt][1] - mn0); s0 += sc[nt][1];
                sc[nt][2] = __expf(sc[nt][2] - mn1); s1 += sc[nt][2];
                sc[nt][3] = __expf(sc[nt][3] - mn1); s1 += sc[nt][3];
            }
            s0 += __shfl_xor_sync(0xffffffffu, s0, 1);
            s0 += __shfl_xor_sync(0xffffffffu, s0, 2);
            s1 += __shfl_xor_sync(0xffffffffu, s1, 1);
            s1 += __shfl_xor_sync(0xffffffffu, s1, 2);
            lrow0 = lrow0 * al0f + s0; mrow0 = mn0;
            lrow1 = lrow1 * al1f + s1; mrow1 = mn1;
#pragma unroll
            for (int nt = 0; nt < 8; nt++) {
                o[nt][0] *= al0f; o[nt][1] *= al0f;
                o[nt][2] *= al1f; o[nt][3] *= al1f;
            }

#pragma unroll
            for (int kc = 0; kc < 4; kc++) {
                uint32_t ph[4];
                ph[0] = pack_h2(sc[2*kc][0],   sc[2*kc][1]);
                ph[1] = pack_h2(sc[2*kc][2],   sc[2*kc][3]);
                ph[2] = pack_h2(sc[2*kc+1][0], sc[2*kc+1][1]);
                ph[3] = pack_h2(sc[2*kc+1][2], sc[2*kc+1][3]);
                const uint32_t vrow = kb + (uint32_t)(kc * 16 * AST) * 2;
#pragma unroll
                for (int p = 0; p < 4; p++) {
                    uint32_t v0r, v1r, v2r, v3r;
                    LDSM4T(v0r, v1r, v2r, v3r, uV + vrow + vfo[p]);
                    MMA_F16(o[2*p],   ph[0], ph[1], ph[2], ph[3], v0r, v1r);
                    MMA_F16(o[2*p+1], ph[0], ph[1], ph[2], ph[3], v2r, v3r);
                }
            }
        }

        float i0 = 1.f / lrow0, i1 = 1.f / lrow1;
        int row0 = qt * 64 + q0 + r, row1 = row0 + 8;
        bool v0 = row0 < lenx, v1 = row1 < lenx;
        size_t ob = (size_t)b * SXX * 2048 + (size_t)row0 * 2048 + 1024 + h * 64;
#pragma unroll
        for (int dn = 0; dn < 8; dn++) {
            *(uint32_t*)&cath[ob + dn * 8 + cq] =
                v0 ? pack_h2(o[dn][0] * i0, o[dn][1] * i0) : 0u;
            *(uint32_t*)&cath[ob + (size_t)8 * 2048 + dn * 8 + cq] =
                v1 ? pack_h2(o[dn][2] * i1, o[dn][3] * i1) : 0u;
        }
    }
}

// ---------------- launch ----------------
extern "C" void kernel_launch(void* const* d_in, const int* in_sizes, int n_in,
                              void* d_out, int out_size)
{
    const float* x      = (const float*)d_in[0];
    const float* y      = (const float*)d_in[1];
    const float* maskx  = (const float*)d_in[2];
    const float* W_attn = (const float*)d_in[3];
    const float* b_attn = (const float*)d_in[4];
    const float* W_2a   = (const float*)d_in[5];
    const float* b_2a   = (const float*)d_in[6];
    const float* W_2b   = (const float*)d_in[7];
    const float* b_2b   = (const float*)d_in[8];
    const float* W_proj = (const float*)d_in[9];
    const float* b_proj = (const float*)d_in[10];
    const int*   xtb    = (const int*)d_in[11];
    const int*   ytb    = (const int*)d_in[15];

    unsigned short *xh, *xl, *yh, *yl;
    unsigned short *qkvh, *kv2h, *cath;
    unsigned short *wc, *wb, *wph;
    float *bias4k, *pp;
    cudaGetSymbolAddress((void**)&xh, g_xh);     cudaGetSymbolAddress((void**)&xl, g_xl);
    cudaGetSymbolAddress((void**)&yh, g_yh);     cudaGetSymbolAddress((void**)&yl, g_yl);
    cudaGetSymbolAddress((void**)&qkvh, g_qkvh);
    cudaGetSymbolAddress((void**)&kv2h, g_kv2h);
    cudaGetSymbolAddress((void**)&cath, g_cath);
    cudaGetSymbolAddress((void**)&wc, g_wc_h);
    cudaGetSymbolAddress((void**)&wb, g_w2b_h);
    cudaGetSymbolAddress((void**)&wph, g_wpj_h);
    cudaGetSymbolAddress((void**)&bias4k, g_bias4k);
    cudaGetSymbolAddress((void**)&pp, g_pp);

    const int SMEM_GF = (4 * TSB + 2 * TSF) * 2;        // 73728 B
    const int SMEM_GP = (2 * TSF + 2 * TSB) * 2;        // 55296 B
    const int SMEM_ATTN = 5 * QB * 2 + 2 * 64 * 4;      // 46592 B
    cudaFuncSetAttribute((const void*)gemm_front, cudaFuncAttributeMaxDynamicSharedMemorySize, SMEM_GF);
    cudaFuncSetAttribute((const void*)gemm_proj,  cudaFuncAttributeMaxDynamicSharedMemorySize, SMEM_GP);
    cudaFuncSetAttribute((const void*)attn_fused, cudaFuncAttributeMaxDynamicSharedMemorySize, SMEM_ATTN);

    prep_all<<<12305, 256>>>(x, y, xh, xl, yh, yl,
                             W_attn, W_2a, W_2b, W_proj, wc, wb, wph,
                             xtb, in_sizes[11], ytb, in_sizes[15],
                             b_attn, b_2a, bias4k);

    gemm_front<<<1536, 256, SMEM_GF>>>(xh, xl, yh, yl, wc, wb, bias4k, b_2b, qkvh, kv2h);

    attn_fused<<<dim3(32, 16, 2), 128, SMEM_ATTN>>>(qkvh, kv2h, maskx, cath);

    gemm_proj<<<dim3(16, 16, 2), 256, SMEM_GP>>>(cath, wph, pp);
    reduce_out<<<2048, 256>>>(pp, b_proj, (float*)d_out);
}

// round 17
// speedup vs baseline: 2.0936x; 1.0370x over previous
#include <cuda_runtime.h>
#include <cuda_fp16.h>
#include <cstdint>

#define NB    2
#define SXX   1024
#define SYY   1024
#define DIM   1024
#define NH    16
#define HDIM  64
#define FULLN 1536

// ---------------- scratch (device globals) ----------------
__device__ int   g_lens[4];
__device__ float g_bias4k[4096];

__device__ unsigned short g_xh [2048 * 1024], g_xl [2048 * 1024];
__device__ unsigned short g_yh [2048 * 1024], g_yl [2048 * 1024];
__device__ unsigned short g_qkvh[2048 * 4096];
__device__ unsigned short g_kv2h[2048 * 2048];
__device__ unsigned short g_cath[2048 * 2048];
__device__ unsigned short g_wc_h [4096 * 1024];
__device__ unsigned short g_w2b_h[2048 * 1024];
__device__ unsigned short g_wpj_h[1024 * 2048];

// ---------------- helpers ----------------
__device__ __forceinline__ uint32_t smem_u32(const void* p) {
    uint32_t a;
    asm("{ .reg .u64 t; cvta.to.shared.u64 t, %1; cvt.u32.u64 %0, t; }" : "=r"(a) : "l"(p));
    return a;
}
#define CP_ASYNC16(dst, src) \
    asm volatile("cp.async.ca.shared.global [%0], [%1], 16;" :: "r"(dst), "l"(src) : "memory")
#define CP_COMMIT() asm volatile("cp.async.commit_group;" ::: "memory")
#define CP_WAIT0()  asm volatile("cp.async.wait_group 0;" ::: "memory")

#define MMA_F16(c, a0, a1, a2, a3, b0, b1) \
    asm volatile("mma.sync.aligned.m16n8k16.row.col.f32.f16.f16.f32 " \
        "{%0,%1,%2,%3}, {%4,%5,%6,%7}, {%8,%9}, {%0,%1,%2,%3};" \
        : "+f"((c)[0]), "+f"((c)[1]), "+f"((c)[2]), "+f"((c)[3]) \
        : "r"(a0), "r"(a1), "r"(a2), "r"(a3), "r"(b0), "r"(b1))

#define LDSM4(r0, r1, r2, r3, a) \
    asm volatile("ldmatrix.sync.aligned.m8n8.x4.shared.b16 {%0,%1,%2,%3}, [%4];" \
        : "=r"(r0), "=r"(r1), "=r"(r2), "=r"(r3) : "r"(a))
#define LDSM4T(r0, r1, r2, r3, a) \
    asm volatile("ldmatrix.sync.aligned.m8n8.x4.trans.shared.b16 {%0,%1,%2,%3}, [%4];" \
        : "=r"(r0), "=r"(r1), "=r"(r2), "=r"(r3) : "r"(a))

__device__ __forceinline__ void split_pack_h(float a, float b, uint32_t& h, uint32_t& l) {
    __half ha = __float2half_rn(a), hb = __float2half_rn(b);
    __half la = __float2half_rn(a - __half2float(ha));
    __half lb = __float2half_rn(b - __half2float(hb));
    h = (uint32_t)*(unsigned short*)&ha | ((uint32_t)*(unsigned short*)&hb << 16);
    l = (uint32_t)*(unsigned short*)&la | ((uint32_t)*(unsigned short*)&lb << 16);
}
__device__ __forceinline__ uint32_t pack_h2(float a, float b) {
    __half2 v = __floats2half2_rn(a, b);
    return *(uint32_t*)&v;
}

// ---------------- ALL prep in one launch ----------------
__global__ __launch_bounds__(256)
void prep_all(const float* __restrict__ x, const float* __restrict__ y,
              unsigned short* __restrict__ xh, unsigned short* __restrict__ xl,
              unsigned short* __restrict__ yh, unsigned short* __restrict__ yl,
              const float* __restrict__ Wa, const float* __restrict__ W2a,
              const float* __restrict__ W2b, const float* __restrict__ Wp,
              unsigned short* __restrict__ wc, unsigned short* __restrict__ wb,
              unsigned short* __restrict__ wph,
              const int* __restrict__ xb, int nx, const int* __restrict__ yb, int ny,
              const float* __restrict__ ba, const float* __restrict__ b2a,
              float* __restrict__ bias4k)
{
    const int bid = blockIdx.x;
    if (bid < 4096) {
        const int N4 = 2048 * 1024 / 4;
        int i = bid * 256 + threadIdx.x;
        const float* in; unsigned short *oh, *ol;
        int j;
        if (i < N4) { in = x; oh = xh; ol = xl; j = i; }
        else        { in = y; oh = yh; ol = yl; j = i - N4; }
        float4 v = ((const float4*)in)[j];
        uint32_t h0, l0, h1, l1;
        split_pack_h(v.x, v.y, h0, l0);
        split_pack_h(v.z, v.w, h1, l1);
        ((uint2*)oh)[j] = make_uint2(h0, h1);
        ((uint2*)ol)[j] = make_uint2(l0, l1);
    } else if (bid < 12288) {
        int f = bid - 4096;
        const float* in; unsigned short* oh;
        int K, N, bx, by;
        if (f < 3072)      { in = Wa;  oh = wc;  K = 1024; N = 3072; bx = f % 96; by = f / 96; }
        else if (f < 4096) { in = W2a; oh = wc + (size_t)3072 * 1024; K = 1024; N = 1024; f -= 3072; bx = f % 32; by = f / 32; }
        else if (f < 6144) { in = W2b; oh = wb;  K = 1024; N = 2048; f -= 4096; bx = f % 64; by = f / 64; }
        else               { in = Wp;  oh = wph; K = 2048; N = 1024; f -= 6144; bx = f % 32; by = f / 32; }

        __shared__ float tile[32][33];
        int n0 = bx << 5, k0 = by << 5;
        int tx = threadIdx.x & 31, ty = threadIdx.x >> 5;
        for (int i = ty; i < 32; i += 8)
            tile[i][tx] = in[(size_t)(k0 + i) * N + n0 + tx];
        __syncthreads();
        for (int i = ty; i < 32; i += 8) {
            float v = tile[tx][i];
            __half h = __float2half_rn(v);
            oh[(size_t)(n0 + i) * K + k0 + tx] = *(unsigned short*)&h;
        }
    } else if (bid < 12304) {
        int i = (bid - 12288) * 256 + threadIdx.x;
        bias4k[i] = (i < 3072) ? ba[i] : b2a[i - 3072];
    } else {
        __shared__ int cnt[4];
        int t = threadIdx.x;
        if (t < 4) cnt[t] = 0;
        __syncthreads();
        for (int i = t; i < nx; i += blockDim.x) atomicAdd(&cnt[xb[i]], 1);
        for (int i = t; i < ny; i += blockDim.x) atomicAdd(&cnt[2 + yb[i]], 1);
        __syncthreads();
        if (t < 4) g_lens[t] = cnt[t];
    }
}

// ---------------- front GEMMs: 64x128 tile, K-chunk 64, single-sync pipeline ----------------
#define TSF (128 * 72)
#define TSB (64 * 72)

template<bool USEAL>
__device__ __forceinline__ void front_loop(
    const unsigned short* __restrict__ Ah, const unsigned short* __restrict__ Al,
    const unsigned short* __restrict__ Bh,
    int bm, int bn, int tid,
    uint32_t uA, uint32_t uAl, uint32_t uB,
    const uint32_t* aoff, const uint32_t* boff,
    float acc[2][4][4])
{
    const int K = 1024;
    const int nchunk = K >> 6;

#define PREFETCH_FL(t) do { \
        uint32_t sa_ = (uint32_t)((t) & 1) * (TSB * 2); \
        uint32_t sb_ = (uint32_t)((t) & 1) * (TSF * 2); \
        int k0_  = (t) << 6; \
        _Pragma("unroll") \
        for (int it_ = 0; it_ < 2; it_++) { \
            int i_ = tid + it_ * 256; \
            int row_ = i_ >> 3, sg_ = i_ & 7; \
            uint32_t so_ = sa_ + (uint32_t)(row_ * 72 + sg_ * 8) * 2; \
            size_t ao_ = (size_t)(bm + row_) * K + k0_ + sg_ * 8; \
            CP_ASYNC16(uA + so_, Ah + ao_); \
            if (USEAL) CP_ASYNC16(uAl + so_, Al + ao_); \
        } \
        _Pragma("unroll") \
        for (int it_ = 0; it_ < 4; it_++) { \
            int i_ = tid + it_ * 256; \
            int row_ = i_ >> 3, sg_ = i_ & 7; \
            uint32_t so_ = sb_ + (uint32_t)(row_ * 72 + sg_ * 8) * 2; \
            CP_ASYNC16(uB + so_, Bh + (size_t)(bn + row_) * K + k0_ + sg_ * 8); \
        } \
    } while (0)

    PREFETCH_FL(0);
    CP_COMMIT();

    for (int t = 0; t < nchunk; t++) {
        CP_WAIT0();
        __syncthreads();
        if (t + 1 < nchunk) { PREFETCH_FL(t + 1); CP_COMMIT(); }
        const uint32_t sa = (uint32_t)(t & 1) * (TSB * 2);
        const uint32_t sb = (uint32_t)(t & 1) * (TSF * 2);
#pragma unroll
        for (int kt = 0; kt < 4; kt++) {
            const uint32_t ko = (uint32_t)(kt << 5);
            uint32_t bh[2][4];
#pragma unroll
            for (int p = 0; p < 2; p++)
                LDSM4(bh[p][0], bh[p][1], bh[p][2], bh[p][3], uB + sb + ko + boff[p]);
#pragma unroll
            for (int mi = 0; mi < 2; mi++) {
                uint32_t a0, a1, a2, a3;
                LDSM4(a0, a1, a2, a3, uA + sa + ko + aoff[mi]);
#pragma unroll
                for (int p = 0; p < 2; p++) {
                    MMA_F16(acc[mi][2*p],   a0, a1, a2, a3, bh[p][0], bh[p][1]);
                    MMA_F16(acc[mi][2*p+1], a0, a1, a2, a3, bh[p][2], bh[p][3]);
                }
                if (USEAL) {
                    uint32_t l0, l1, l2, l3;
                    LDSM4(l0, l1, l2, l3, uAl + sa + ko + aoff[mi]);
#pragma unroll
                    for (int p = 0; p < 2; p++) {
                        MMA_F16(acc[mi][2*p],   l0, l1, l2, l3, bh[p][0], bh[p][1]);
                        MMA_F16(acc[mi][2*p+1], l0, l1, l2, l3, bh[p][2], bh[p][3]);
                    }
                }
            }
        }
    }
#undef PREFETCH_FL
}

__global__ __launch_bounds__(256, 3)
void gemm_front(const unsigned short* __restrict__ xh, const unsigned short* __restrict__ xl,
                const unsigned short* __restrict__ yh, const unsigned short* __restrict__ yl,
                const unsigned short* __restrict__ wc, const unsigned short* __restrict__ wb,
                const float* __restrict__ bias4k, const float* __restrict__ b2b,
                unsigned short* __restrict__ qkvh, unsigned short* __restrict__ kv2h)
{
    extern __shared__ unsigned short sm16[];
    unsigned short* sA  = sm16;
    unsigned short* sAl = sm16 + 2 * TSB;
    unsigned short* sB  = sm16 + 4 * TSB;
    const uint32_t uA = smem_u32(sA), uAl = smem_u32(sAl), uB = smem_u32(sB);

    // long-CTAs-first remap
    const int bid = blockIdx.x;
    int obid;
    if (bid < 256) {
        int m = bid >> 3, nb = 16 + (bid & 7);
        obid = m * 32 + nb;
    } else if (bid < 512) {
        int i = bid - 256; int m = i >> 3, nb = 8 + (i & 7);
        obid = 1024 + m * 16 + nb;
    } else if (bid < 1280) {
        int i = bid - 512; int m = i / 24; int nbi = i % 24;
        int nb = nbi < 16 ? nbi : nbi + 8;
        obid = m * 32 + nb;
    } else {
        int i = bid - 1280; int m = i >> 3, nb = i & 7;
        obid = 1024 + m * 16 + nb;
    }

    const unsigned short *Ah, *Al, *Bh;
    const float* bias;
    unsigned short* Ch;
    int bm, bn, N;
    bool useAl;
    if (obid < 1024) {
        bm = (obid >> 5) << 6; bn = (obid & 31) << 7; N = 4096;
        Ah = xh; Al = xl; Bh = wc; bias = bias4k; Ch = qkvh;
        useAl = (bn >= 2048) && (bn < 3072);
    } else {
        int i = obid - 1024;
        bm = (i >> 4) << 6; bn = (i & 15) << 7; N = 2048;
        Ah = yh; Al = yl; Bh = wb; bias = b2b; Ch = kv2h;
        useAl = (bn >= 1024);
    }

    const int tid  = threadIdx.x;
    const int lane = tid & 31, wid = tid >> 5;
    const int wm = (wid >> 2) << 5;
    const int wn = (wid & 3) << 5;

    float acc[2][4][4];
#pragma unroll
    for (int i = 0; i < 2; i++)
#pragma unroll
        for (int j = 0; j < 4; j++)
#pragma unroll
            for (int k = 0; k < 4; k++) acc[i][j][k] = 0.f;

    const int l8 = lane & 7, g = lane >> 3;
    uint32_t aoff[2], boff[2];
#pragma unroll
    for (int mi = 0; mi < 2; mi++)
        aoff[mi] = (uint32_t)((wm + (mi << 4) + ((g & 1) << 3) + l8) * 72 + ((g >> 1) << 3)) * 2;
#pragma unroll
    for (int p = 0; p < 2; p++)
        boff[p] = (uint32_t)((wn + (p << 4) + ((g >> 1) << 3) + l8) * 72 + ((g & 1) << 3)) * 2;

    if (useAl) front_loop<true >(Ah, Al, Bh, bm, bn, tid, uA, uAl, uB, aoff, boff, acc);
    else       front_loop<false>(Ah, Al, Bh, bm, bn, tid, uA, uAl, uB, aoff, boff, acc);

    const int fr = lane >> 2;
    const int fc = (lane & 3) << 1;
#pragma unroll
    for (int mi = 0; mi < 2; mi++) {
        int row = bm + wm + (mi << 4) + fr;
#pragma unroll
        for (int ni = 0; ni < 4; ni++) {
            int col = bn + wn + (ni << 3) + fc;
            float bx = bias[col], by = bias[col + 1];
            *(uint32_t*)&Ch[(size_t)row * N + col] =
                pack_h2(acc[mi][ni][0] + bx, acc[mi][ni][1] + by);
            *(uint32_t*)&Ch[(size_t)(row + 8) * N + col] =
                pack_h2(acc[mi][ni][2] + bx, acc[mi][ni][3] + by);
        }
    }
}

// ---------------- proj GEMM: 128x64 tile, full K, bias, single-sync pipeline ----------------
__global__ __launch_bounds__(256, 3)
void gemm_proj(const unsigned short* __restrict__ Ah,
               const unsigned short* __restrict__ Bh,
               const float* __restrict__ bias, float* __restrict__ Cf,
               int M, int N, int K)
{
    extern __shared__ unsigned short sm16[];
    unsigned short* sAh = sm16;                 // [2][TSF]
    unsigned short* sBh = sm16 + 2 * TSF;       // [2][TSB]
    const uint32_t uAh = smem_u32(sAh), uBh = smem_u32(sBh);

    const int tid  = threadIdx.x;
    const int lane = tid & 31, wid = tid >> 5;
    const int wm = (wid >> 2) << 6;
    const int wn = (wid & 3) << 4;
    const int bm = blockIdx.y << 7, bn = blockIdx.x << 6;

    float acc[4][2][4];
#pragma unroll
    for (int i = 0; i < 4; i++)
#pragma unroll
        for (int j = 0; j < 2; j++)
#pragma unroll
            for (int k = 0; k < 4; k++) acc[i][j][k] = 0.f;

    const int nchunk = K >> 6;   // 32

#define PREFETCH_P(t) do { \
        int k0_ = (t) << 6; \
        uint32_t sa_ = (uint32_t)((t) & 1) * (TSF * 2); \
        uint32_t sb_ = (uint32_t)((t) & 1) * (TSB * 2); \
        _Pragma("unroll") \
        for (int it_ = 0; it_ < 4; it_++) { \
            int i_ = tid + it_ * 256; \
            int row_ = i_ >> 3, sg_ = i_ & 7; \
            uint32_t so_ = sa_ + (uint32_t)(row_ * 72 + sg_ * 8) * 2; \
            CP_ASYNC16(uAh + so_, Ah + (size_t)(bm + row_) * K + k0_ + sg_ * 8); \
        } \
        _Pragma("unroll") \
        for (int it_ = 0; it_ < 2; it_++) { \
            int i_ = tid + it_ * 256; \
            int row_ = i_ >> 3, sg_ = i_ & 7; \
            uint32_t so_ = sb_ + (uint32_t)(row_ * 72 + sg_ * 8) * 2; \
            CP_ASYNC16(uBh + so_, Bh + (size_t)(bn + row_) * K + k0_ + sg_ * 8); \
        } \
    } while (0)

    PREFETCH_P(0);
    CP_COMMIT();

    const int l8 = lane & 7, g = lane >> 3;
    uint32_t aoff[4], boff;
#pragma unroll
    for (int mi = 0; mi < 4; mi++)
        aoff[mi] = (uint32_t)((wm + (mi << 4) + ((g & 1) << 3) + l8) * 72 + ((g >> 1) << 3)) * 2;
    boff = (uint32_t)((wn + ((g >> 1) << 3) + l8) * 72 + ((g & 1) << 3)) * 2;

    const int fr = lane >> 2;
    const int fc = (lane & 3) << 1;

    for (int t = 0; t < nchunk; t++) {
        CP_WAIT0();
        __syncthreads();
        if (t + 1 < nchunk) { PREFETCH_P(t + 1); CP_COMMIT(); }
        const uint32_t sa = (uint32_t)(t & 1) * (TSF * 2);
        const uint32_t sb = (uint32_t)(t & 1) * (TSB * 2);
#pragma unroll
        for (int kt = 0; kt < 4; kt++) {
            const uint32_t ko = (uint32_t)(kt << 5);
            uint32_t bh0, bh1, bh2, bh3;
            LDSM4(bh0, bh1, bh2, bh3, uBh + sb + ko + boff);
#pragma unroll
            for (int mi = 0; mi < 4; mi++) {
                uint32_t a0, a1, a2, a3;
                LDSM4(a0, a1, a2, a3, uAh + sa + ko + aoff[mi]);
                MMA_F16(acc[mi][0], a0, a1, a2, a3, bh0, bh1);
                MMA_F16(acc[mi][1], a0, a1, a2, a3, bh2, bh3);
            }
        }
    }

#pragma unroll
    for (int mi = 0; mi < 4; mi++) {
        int row = bm + wm + (mi << 4) + fr;
#pragma unroll
        for (int ni = 0; ni < 2; ni++) {
            int col = bn + wn + (ni << 3) + fc;
            float bx = bias[col], by = bias[col + 1];
            float2 v0 = { acc[mi][ni][0] + bx, acc[mi][ni][1] + by };
            float2 v1 = { acc[mi][ni][2] + bx, acc[mi][ni][3] + by };
            *(float2*)(Cf + (size_t)row * N + col)       = v0;
            *(float2*)(Cf + (size_t)(row + 8) * N + col) = v1;
        }
    }
}

// ================= fused MMA flash attention (single-fp16 Q and P) =================
#define AST 72
#define QB  (64 * AST)
#define KVB (QB * 2)
#define QSTRIDE 4096

__global__ __launch_bounds__(128)
void attn_fused(const unsigned short* __restrict__ qkvh,
                const unsigned short* __restrict__ kvh,
                const float* __restrict__ mask,
                unsigned short* __restrict__ cath)
{
    extern __shared__ char smraw[];
    unsigned short* sQ  = (unsigned short*)smraw;
    unsigned short* sK  = sQ + QB;
    unsigned short* sV  = sK + 2 * QB;
    float* sMsf = (float*)(sV + 2 * QB);
    const uint32_t uQ = smem_u32(sQ);
    const uint32_t uK = smem_u32(sK), uV = smem_u32(sV);
    const uint32_t uMs = smem_u32(sMsf);

    const int bx = blockIdx.x;
    const bool is_self = bx < 16;
    const int qt = is_self ? (15 - bx) : (31 - bx);
    const int h = blockIdx.y, b = blockIdx.z;
    const int tid = threadIdx.x, lane = tid & 31, wid = tid >> 5;
    const int q0 = wid << 4;
    const int r = lane >> 2, cq = (lane & 3) << 1;
    const int l8 = lane & 7, g = lane >> 3;

    const int lenx = g_lens[b], leny = g_lens[2 + b];

    uint32_t qfo = (uint32_t)((q0 + ((g & 1) << 3) + l8) * AST + ((g >> 1) << 3)) * 2;
    uint32_t kfo[4], vfo[4];
#pragma unroll
    for (int p = 0; p < 4; p++) {
        kfo[p] = (uint32_t)(((p << 4) + ((g >> 1) << 3) + l8) * AST + ((g & 1) << 3)) * 2;
        vfo[p] = (uint32_t)((((g & 1) << 3) + l8) * AST + (((p << 1) + (g >> 1)) << 3)) * 2;
    }

    float o[8][4];
#pragma unroll
    for (int i = 0; i < 8; i++)
#pragma unroll
        for (int j = 0; j < 4; j++) o[i][j] = 0.f;
    float mrow0 = -1e30f, mrow1 = -1e30f, lrow0 = 0.f, lrow1 = 0.f;

    if (is_self) {
        const size_t gb = (size_t)b * SXX * QSTRIDE;
        for (int i = tid; i < 512; i += 128) {
            int rr = i >> 3, seg = i & 7;
            *(uint4*)&sQ[rr * AST + seg * 8] =
                *(const uint4*)&qkvh[gb + (size_t)(qt * 64 + rr) * QSTRIDE + h * 64 + seg * 8];
        }

        const float* maskb = mask + b * SXX;
        int nt1 = qt + 1, nt2 = (lenx + 63) >> 6;
        const int ntile = nt1 < nt2 ? nt1 : nt2;

#define APREF_SELF(t) do { \
        uint32_t kd_ = uK + (uint32_t)((t) & 1) * KVB; \
        uint32_t vd_ = uV + (uint32_t)((t) & 1) * KVB; \
        _Pragma("unroll") \
        for (int it_ = 0; it_ < 4; it_++) { \
            int i_ = tid + it_ * 128; \
            int rr_ = i_ >> 3, sg_ = i_ & 7; \
            size_t kr_ = gb + (size_t)((t) * 64 + rr_) * QSTRIDE + 1024 + h * 64 + sg_ * 8; \
            uint32_t so_ = (uint32_t)(rr_ * AST + sg_ * 8) * 2; \
            CP_ASYNC16(kd_ + so_, qkvh + kr_); \
            CP_ASYNC16(vd_ + so_, qkvh + kr_ + 1024); \
        } \
        if (tid < 16) CP_ASYNC16(uMs + ((t) & 1) * 256 + tid * 16, maskb + (t) * 64 + tid * 4); \
    } while (0)

        APREF_SELF(0);
        CP_COMMIT();

        for (int t = 0; t < ntile; t++) {
            CP_WAIT0();
            __syncthreads();
            if (t + 1 < ntile) { APREF_SELF(t + 1); CP_COMMIT(); }
            const uint32_t kb = (uint32_t)(t & 1) * KVB;
            const int mb = (t & 1) * 64;

            float sc[8][4];
#pragma unroll
            for (int i = 0; i < 8; i++)
#pragma unroll
                for (int j = 0; j < 4; j++) sc[i][j] = 0.f;

#pragma unroll
            for (int kt = 0; kt < 4; kt++) {
                const uint32_t ko = (uint32_t)(kt << 5);
                uint32_t a0, a1, a2, a3;
                LDSM4(a0, a1, a2, a3, uQ + qfo + ko);
#pragma unroll
                for (int p = 0; p < 4; p++) {
                    uint32_t k0r, k1r, k2r, k3r;
                    LDSM4(k0r, k1r, k2r, k3r, uK + kb + kfo[p] + ko);
                    MMA_F16(sc[2*p],   a0, a1, a2, a3, k0r, k1r);
                    MMA_F16(sc[2*p+1], a0, a1, a2, a3, k2r, k3r);
                }
            }

            const int grow = qt * 64 + q0 + r;
#pragma unroll
            for (int nt = 0; nt < 8; nt++) {
                int c0 = t * 64 + nt * 8 + cq;
                float m0 = sMsf[mb + nt * 8 + cq], m1 = sMsf[mb + nt * 8 + cq + 1];
                float v;
                v = sc[nt][0] * 0.125f; sc[nt][0] = ((c0     <= grow    ) ? v : -10000.f) + m0;
                v = sc[nt][1] * 0.125f; sc[nt][1] = ((c0 + 1 <= grow    ) ? v : -10000.f) + m1;
                v = sc[nt][2] * 0.125f; sc[nt][2] = ((c0     <= grow + 8) ? v : -10000.f) + m0;
                v = sc[nt][3] * 0.125f; sc[nt][3] = ((c0 + 1 <= grow + 8) ? v : -10000.f) + m1;
            }

            float mx0 = -1e30f, mx1 = -1e30f;
#pragma unroll
            for (int nt = 0; nt < 8; nt++) {
                mx0 = fmaxf(mx0, fmaxf(sc[nt][0], sc[nt][1]));
                mx1 = fmaxf(mx1, fmaxf(sc[nt][2], sc[nt][3]));
            }
            mx0 = fmaxf(mx0, __shfl_xor_sync(0xffffffffu, mx0, 1));
            mx0 = fmaxf(mx0, __shfl_xor_sync(0xffffffffu, mx0, 2));
            mx1 = fmaxf(mx1, __shfl_xor_sync(0xffffffffu, mx1, 1));
            mx1 = fmaxf(mx1, __shfl_xor_sync(0xffffffffu, mx1, 2));
            float mn0 = fmaxf(mrow0, mx0), mn1 = fmaxf(mrow1, mx1);
            float al0f = __expf(mrow0 - mn0), al1f = __expf(mrow1 - mn1);
            float s0 = 0.f, s1 = 0.f;
#pragma unroll
            for (int nt = 0; nt < 8; nt++) {
                sc[nt][0] = __expf(sc[nt][0] - mn0); s0 += sc[nt][0];
                sc[nt][1] = __expf(sc[nt][1] - mn0); s0 += sc[nt][1];
                sc[nt][2] = __expf(sc[nt][2] - mn1); s1 += sc[nt][2];
                sc[nt][3] = __expf(sc[nt][3] - mn1); s1 += sc[nt][3];
            }
            s0 += __shfl_xor_sync(0xffffffffu, s0, 1);
            s0 += __shfl_xor_sync(0xffffffffu, s0, 2);
            s1 += __shfl_xor_sync(0xffffffffu, s1, 1);
            s1 += __shfl_xor_sync(0xffffffffu, s1, 2);
            lrow0 = lrow0 * al0f + s0; mrow0 = mn0;
            lrow1 = lrow1 * al1f + s1; mrow1 = mn1;
#pragma unroll
            for (int nt = 0; nt < 8; nt++) {
                o[nt][0] *= al0f; o[nt][1] *= al0f;
                o[nt][2] *= al1f; o[nt][3] *= al1f;
            }

#pragma unroll
            for (int kc = 0; kc < 4; kc++) {
                uint32_t ph[4];
                ph[0] = pack_h2(sc[2*kc][0],   sc[2*kc][1]);
                ph[1] = pack_h2(sc[2*kc][2],   sc[2*kc][3]);
                ph[2] = pack_h2(sc[2*kc+1][0], sc[2*kc+1][1]);
                ph[3] = pack_h2(sc[2*kc+1][2], sc[2*kc+1][3]);
                const uint32_t vrow = kb + (uint32_t)(kc * 16 * AST) * 2;
#pragma unroll
                for (int p = 0; p < 4; p++) {
                    uint32_t v0r, v1r, v2r, v3r;
                    LDSM4T(v0r, v1r, v2r, v3r, uV + vrow + vfo[p]);
                    MMA_F16(o[2*p],   ph[0], ph[1], ph[2], ph[3], v0r, v1r);
                    MMA_F16(o[2*p+1], ph[0], ph[1], ph[2], ph[3], v2r, v3r);
                }
            }
        }

        float i0 = 1.f / lrow0, i1 = 1.f / lrow1;
        size_t ob = (size_t)b * SXX * 2048 + (size_t)(qt * 64 + q0 + r) * 2048 + h * 64;
#pragma unroll
        for (int dn = 0; dn < 8; dn++) {
            *(uint32_t*)&cath[ob + dn * 8 + cq] = pack_h2(o[dn][0] * i0, o[dn][1] * i0);
            *(uint32_t*)&cath[ob + (size_t)8 * 2048 + dn * 8 + cq] = pack_h2(o[dn][2] * i1, o[dn][3] * i1);
        }
    } else {
        const int off = FULLN - lenx;
        size_t obase = (size_t)b * SXX * 2048 + (size_t)(qt * 64) * 2048 + 1024 + h * 64;
        if (qt * 64 >= lenx) {
            const uint4 z = {0, 0, 0, 0};
            for (int i = tid; i < 512; i += 128) {
                int rr = i >> 3, seg = i & 7;
                *(uint4*)&cath[obase + (size_t)rr * 2048 + seg * 8] = z;
            }
            return;
        }

        const size_t qgb = (size_t)b * SXX * QSTRIDE;
        for (int i = tid; i < 512; i += 128) {
            int rr = i >> 3, seg = i & 7;
            *(uint4*)&sQ[rr * AST + seg * 8] =
                *(const uint4*)&qkvh[qgb + (size_t)(qt * 64 + rr) * QSTRIDE + 3072 + h * 64 + seg * 8];
        }

        int qlast = qt * 64 + 63;
        if (qlast >= lenx) qlast = lenx - 1;
        int jmax = off + qlast + 1;
        if (jmax > leny) jmax = leny;
        const int ntile = (jmax + 63) >> 6;
        const size_t kgb = (size_t)b * SYY * 2048;

#define APREF_CROSS(t) do { \
        uint32_t kd_ = uK + (uint32_t)((t) & 1) * KVB; \
        uint32_t vd_ = uV + (uint32_t)((t) & 1) * KVB; \
        _Pragma("unroll") \
        for (int it_ = 0; it_ < 4; it_++) { \
            int i_ = tid + it_ * 128; \
            int rr_ = i_ >> 3, sg_ = i_ & 7; \
            size_t kr_ = kgb + (size_t)((t) * 64 + rr_) * 2048 + h * 64 + sg_ * 8; \
            uint32_t so_ = (uint32_t)(rr_ * AST + sg_ * 8) * 2; \
            CP_ASYNC16(kd_ + so_, kvh + kr_); \
            CP_ASYNC16(vd_ + so_, kvh + kr_ + 1024); \
        } \
    } while (0)

        APREF_CROSS(0);
        CP_COMMIT();

        for (int t = 0; t < ntile; t++) {
            CP_WAIT0();
            __syncthreads();
            if (t + 1 < ntile) { APREF_CROSS(t + 1); CP_COMMIT(); }
            const uint32_t kb = (uint32_t)(t & 1) * KVB;

            float sc[8][4];
#pragma unroll
            for (int i = 0; i < 8; i++)
#pragma unroll
                for (int j = 0; j < 4; j++) sc[i][j] = 0.f;

#pragma unroll
            for (int kt = 0; kt < 4; kt++) {
                const uint32_t ko = (uint32_t)(kt << 5);
                uint32_t a0, a1, a2, a3;
                LDSM4(a0, a1, a2, a3, uQ + qfo + ko);
#pragma unroll
                for (int p = 0; p < 4; p++) {
                    uint32_t k0r, k1r, k2r, k3r;
                    LDSM4(k0r, k1r, k2r, k3r, uK + kb + kfo[p] + ko);
                    MMA_F16(sc[2*p],   a0, a1, a2, a3, k0r, k1r);
                    MMA_F16(sc[2*p+1], a0, a1, a2, a3, k2r, k3r);
                }
            }

            const int grow = off + qt * 64 + q0 + r;
#pragma unroll
            for (int nt = 0; nt < 8; nt++) {
                int c0 = t * 64 + nt * 8 + cq;
                sc[nt][0] = (c0     <= grow     && c0     < leny) ? sc[nt][0] * 0.125f : -1e30f;
                sc[nt][1] = (c0 + 1 <= grow     && c0 + 1 < leny) ? sc[nt][1] * 0.125f : -1e30f;
                sc[nt][2] = (c0     <= grow + 8 && c0     < leny) ? sc[nt][2] * 0.125f : -1e30f;
                sc[nt][3] = (c0 + 1 <= grow + 8 && c0 + 1 < leny) ? sc[nt][3] * 0.125f : -1e30f;
            }

            float mx0 = -1e30f, mx1 = -1e30f;
#pragma unroll
            for (int nt = 0; nt < 8; nt++) {
                mx0 = fmaxf(mx0, fmaxf(sc[nt][0], sc[nt][1]));
                mx1 = fmaxf(mx1, fmaxf(sc[nt][2], sc[nt][3]));
            }
            mx0 = fmaxf(mx0, __shfl_xor_sync(0xffffffffu, mx0, 1));
            mx0 = fmaxf(mx0, __shfl_xor_sync(0xffffffffu, mx0, 2));
            mx1 = fmaxf(mx1, __shfl_xor_sync(0xffffffffu, mx1, 1));
            mx1 = fmaxf(mx1, __shfl_xor_sync(0xffffffffu, mx1, 2));
            float mn0 = fmaxf(mrow0, mx0), mn1 = fmaxf(mrow1, mx1);
            float al0f = __expf(mrow0 - mn0), al1f = __expf(mrow1 - mn1);
            float s0 = 0.f, s1 = 0.f;
#pragma unroll
            for (int nt = 0; nt < 8; nt++) {
                sc[nt][0] = __expf(sc[nt][0] - mn0); s0 += sc[nt][0];
                sc[nt][1] = __expf(sc[nt][1] - mn0); s0 += sc[nt][1];
                sc[nt][2] = __expf(sc[nt][2] - mn1); s1 += sc[nt][2];
                sc[nt][3] = __expf(sc[nt][3] - mn1); s1 += sc[nt][3];
            }
            s0 += __shfl_xor_sync(0xffffffffu, s0, 1);
            s0 += __shfl_xor_sync(0xffffffffu, s0, 2);
            s1 += __shfl_xor_sync(0xffffffffu, s1, 1);
            s1 += __shfl_xor_sync(0xffffffffu, s1, 2);
            lrow0 = lrow0 * al0f + s0; mrow0 = mn0;
            lrow1 = lrow1 * al1f + s1; mrow1 = mn1;
#pragma unroll
            for (int nt = 0; nt < 8; nt++) {
                o[nt][0] *= al0f; o[nt][1] *= al0f;
                o[nt][2] *= al1f; o[nt][3] *= al1f;
            }

#pragma unroll
            for (int kc = 0; kc < 4; kc++) {
                uint32_t ph[4];
                ph[0] = pack_h2(sc[2*kc][0],   sc[2*kc][1]);
                ph[1] = pack_h2(sc[2*kc][2],   sc[2*kc][3]);
                ph[2] = pack_h2(sc[2*kc+1][0], sc[2*kc+1][1]);
                ph[3] = pack_h2(sc[2*kc+1][2], sc[2*kc+1][3]);
                const uint32_t vrow = kb + (uint32_t)(kc * 16 * AST) * 2;
#pragma unroll
                for (int p = 0; p < 4; p++) {
                    uint32_t v0r, v1r, v2r, v3r;
                    LDSM4T(v0r, v1r, v2r, v3r, uV + vrow + vfo[p]);
                    MMA_F16(o[2*p],   ph[0], ph[1], ph[2], ph[3], v0r, v1r);
                    MMA_F16(o[2*p+1], ph[0], ph[1], ph[2], ph[3], v2r, v3r);
                }
            }
        }

        float i0 = 1.f / lrow0, i1 = 1.f / lrow1;
        int row0 = qt * 64 + q0 + r, row1 = row0 + 8;
        bool v0 = row0 < lenx, v1 = row1 < lenx;
        size_t ob = (size_t)b * SXX * 2048 + (size_t)row0 * 2048 + 1024 + h * 64;
#pragma unroll
        for (int dn = 0; dn < 8; dn++) {
            *(uint32_t*)&cath[ob + dn * 8 + cq] =
                v0 ? pack_h2(o[dn][0] * i0, o[dn][1] * i0) : 0u;
            *(uint32_t*)&cath[ob + (size_t)8 * 2048 + dn * 8 + cq] =
                v1 ? pack_h2(o[dn][2] * i1, o[dn][3] * i1) : 0u;
        }
    }
}

// ---------------- launch ----------------
extern "C" void kernel_launch(void* const* d_in, const int* in_sizes, int n_in,
                              void* d_out, int out_size)
{
    const float* x      = (const float*)d_in[0];
    const float* y      = (const float*)d_in[1];
    const float* maskx  = (const float*)d_in[2];
    const float* W_attn = (const float*)d_in[3];
    const float* b_attn = (const float*)d_in[4];
    const float* W_2a   = (const float*)d_in[5];
    const float* b_2a   = (const float*)d_in[6];
    const float* W_2b   = (const float*)d_in[7];
    const float* b_2b   = (const float*)d_in[8];
    const float* W_proj = (const float*)d_in[9];
    const float* b_proj = (const float*)d_in[10];
    const int*   xtb    = (const int*)d_in[11];
    const int*   ytb    = (const int*)d_in[15];

    unsigned short *xh, *xl, *yh, *yl;
    unsigned short *qkvh, *kv2h, *cath;
    unsigned short *wc, *wb, *wph;
    float* bias4k;
    cudaGetSymbolAddress((void**)&xh, g_xh);     cudaGetSymbolAddress((void**)&xl, g_xl);
    cudaGetSymbolAddress((void**)&yh, g_yh);     cudaGetSymbolAddress((void**)&yl, g_yl);
    cudaGetSymbolAddress((void**)&qkvh, g_qkvh);
    cudaGetSymbolAddress((void**)&kv2h, g_kv2h);
    cudaGetSymbolAddress((void**)&cath, g_cath);
    cudaGetSymbolAddress((void**)&wc, g_wc_h);
    cudaGetSymbolAddress((void**)&wb, g_w2b_h);
    cudaGetSymbolAddress((void**)&wph, g_wpj_h);
    cudaGetSymbolAddress((void**)&bias4k, g_bias4k);

    const int SMEM_GF = (4 * TSB + 2 * TSF) * 2;        // 73728 B
    const int SMEM_GP = (2 * TSF + 2 * TSB) * 2;        // 55296 B
    const int SMEM_ATTN = 5 * QB * 2 + 2 * 64 * 4;      // 46592 B
    cudaFuncSetAttribute((const void*)gemm_front, cudaFuncAttributeMaxDynamicSharedMemorySize, SMEM_GF);
    cudaFuncSetAttribute((const void*)gemm_proj,  cudaFuncAttributeMaxDynamicSharedMemorySize, SMEM_GP);
    cudaFuncSetAttribute((const void*)attn_fused, cudaFuncAttributeMaxDynamicSharedMemorySize, SMEM_ATTN);

    prep_all<<<12305, 256>>>(x, y, xh, xl, yh, yl,
                             W_attn, W_2a, W_2b, W_proj, wc, wb, wph,
                             xtb, in_sizes[11], ytb, in_sizes[15],
                             b_attn, b_2a, bias4k);

    gemm_front<<<1536, 256, SMEM_GF>>>(xh, xl, yh, yl, wc, wb, bias4k, b_2b, qkvh, kv2h);

    attn_fused<<<dim3(32, 16, 2), 128, SMEM_ATTN>>>(qkvh, kv2h, maskx, cath);

    gemm_proj<<<dim3(16, 16), 256, SMEM_GP>>>(cath, wph, b_proj, (float*)d_out, 2048, 1024, 2048);
}